// round 1
// baseline (speedup 1.0000x reference)
#include <cuda_runtime.h>
#include <math.h>

// Problem constants: B=4, C=512, H=W=64 -> HW=4096
constexpr int NB  = 4;
constexpr int NC  = 512;
constexpr int NHW = 4096;
#define EPSV 1e-5f

// ---------------- scratch (static device arrays; no allocation allowed) ---------
__device__ float g_normC[(size_t)NB * NC * NHW];            // 32 MB
__device__ float g_normS[(size_t)NB * NC * NHW];            // 32 MB
__device__ float g_Fbuf [(size_t)NB * NC * NHW];            // 32 MB
__device__ float g_Gbuf [(size_t)NB * NC * NHW];            // 32 MB
__device__ float g_Hbuf [(size_t)NB * NC * NHW];            // 32 MB
__device__ float g_Obuf [(size_t)NB * NC * NHW];            // 32 MB
__device__ float g_energy[(size_t)NB * NHW * NHW];          // 256 MB

// ---------------- block reductions ----------------------------------------------
__device__ __forceinline__ float2 block_reduce_sum2(float s, float s2) {
    __shared__ float2 sh[8];
    int lane = threadIdx.x & 31, w = threadIdx.x >> 5;
    #pragma unroll
    for (int o = 16; o > 0; o >>= 1) {
        s  += __shfl_down_sync(0xffffffffu, s, o);
        s2 += __shfl_down_sync(0xffffffffu, s2, o);
    }
    if (lane == 0) sh[w] = make_float2(s, s2);
    __syncthreads();
    if (w == 0) {
        float2 v = (lane < 8) ? sh[lane] : make_float2(0.f, 0.f);
        #pragma unroll
        for (int o = 4; o > 0; o >>= 1) {
            v.x += __shfl_down_sync(0xffffffffu, v.x, o);
            v.y += __shfl_down_sync(0xffffffffu, v.y, o);
        }
        if (lane == 0) sh[0] = v;
    }
    __syncthreads();
    return sh[0];
}

__device__ __forceinline__ float block_reduce_max(float v) {
    __shared__ float sh[8];
    int lane = threadIdx.x & 31, w = threadIdx.x >> 5;
    #pragma unroll
    for (int o = 16; o > 0; o >>= 1)
        v = fmaxf(v, __shfl_down_sync(0xffffffffu, v, o));
    if (lane == 0) sh[w] = v;
    __syncthreads();
    if (w == 0) {
        float t = (lane < 8) ? sh[lane] : -3.4e38f;
        #pragma unroll
        for (int o = 4; o > 0; o >>= 1)
            t = fmaxf(t, __shfl_down_sync(0xffffffffu, t, o));
        if (lane == 0) sh[0] = t;
    }
    __syncthreads();
    return sh[0];
}

__device__ __forceinline__ float block_reduce_sum(float v) {
    __shared__ float sh[8];
    int lane = threadIdx.x & 31, w = threadIdx.x >> 5;
    #pragma unroll
    for (int o = 16; o > 0; o >>= 1)
        v += __shfl_down_sync(0xffffffffu, v, o);
    if (lane == 0) sh[w] = v;
    __syncthreads();
    if (w == 0) {
        float t = (lane < 8) ? sh[lane] : 0.f;
        #pragma unroll
        for (int o = 4; o > 0; o >>= 1)
            t += __shfl_down_sync(0xffffffffu, t, o);
        if (lane == 0) sh[0] = t;
    }
    __syncthreads();
    return sh[0];
}

// ---------------- mean/variance normalization over spatial dims ------------------
// one block per (b,c) row of 4096 elems; 256 threads * 16 floats each
__global__ __launch_bounds__(256) void norm_kernel(const float* __restrict__ x,
                                                   float* __restrict__ y) {
    size_t base = (size_t)blockIdx.x * NHW;
    const float4* xp = (const float4*)(x + base);
    float4*       yp = (float4*)(y + base);
    float4 v[4];
    float s = 0.f, s2 = 0.f;
    #pragma unroll
    for (int i = 0; i < 4; i++) {
        v[i] = xp[threadIdx.x + i * 256];
        s  += v[i].x + v[i].y + v[i].z + v[i].w;
        s2 += v[i].x * v[i].x + v[i].y * v[i].y + v[i].z * v[i].z + v[i].w * v[i].w;
    }
    float2 r = block_reduce_sum2(s, s2);
    float mean = r.x * (1.f / NHW);
    float var  = r.y * (1.f / NHW) - mean * mean;
    float sc   = rsqrtf(var + EPSV);
    #pragma unroll
    for (int i = 0; i < 4; i++) {
        float4 o;
        o.x = (v[i].x - mean) * sc;
        o.y = (v[i].y - mean) * sc;
        o.z = (v[i].z - mean) * sc;
        o.w = (v[i].w - mean) * sc;
        yp[threadIdx.x + i * 256] = o;
    }
}

// ---------------- row softmax (in place), row length 4096 ------------------------
__global__ __launch_bounds__(256) void softmax_kernel(float* __restrict__ e) {
    size_t row = (size_t)blockIdx.y * NHW + blockIdx.x;
    float4* p = (float4*)(e + row * (size_t)NHW);
    float4 v[4];
    float mx = -3.4e38f;
    #pragma unroll
    for (int i = 0; i < 4; i++) {
        v[i] = p[threadIdx.x + i * 256];
        mx = fmaxf(mx, fmaxf(fmaxf(v[i].x, v[i].y), fmaxf(v[i].z, v[i].w)));
    }
    mx = block_reduce_max(mx);
    float s = 0.f;
    #pragma unroll
    for (int i = 0; i < 4; i++) {
        v[i].x = __expf(v[i].x - mx); s += v[i].x;
        v[i].y = __expf(v[i].y - mx); s += v[i].y;
        v[i].z = __expf(v[i].z - mx); s += v[i].z;
        v[i].w = __expf(v[i].w - mx); s += v[i].w;
    }
    s = block_reduce_sum(s);
    float inv = 1.0f / s;
    #pragma unroll
    for (int i = 0; i < 4; i++) {
        v[i].x *= inv; v[i].y *= inv; v[i].z *= inv; v[i].w *= inv;
        p[threadIdx.x + i * 256] = v[i];
    }
}

// ---------------- generic batched SGEMM ------------------------------------------
// C[b] = op(A[b]) * op(B[b]) (+ bias[m]) (+ resid[b])
// Logical A: [M,K].  TA=0: stored row-major [M,K]. TA=1: stored [K,M] (A[m,k] at k*M+m)
// Logical B: [K,N].  TB=0: stored row-major [K,N]. TB=1: stored [N,K] (B[k,n] at n*K+k)
// C stored row-major [M,N]. EPI: 0 none, 1 +bias[m], 2 +bias[m]+resid
// Tiles: 128x128x16, 256 threads, 8x8 per thread. All dims divisible by tiles.
template <int TA, int TB, int EPI>
__global__ __launch_bounds__(256) void gemm128(
    const float* __restrict__ A, const float* __restrict__ B,
    float* __restrict__ C, int M, int N, int K,
    long sA, long sB, long sC,
    const float* __restrict__ bias,
    const float* __restrict__ resid, long sR)
{
    constexpr int BM = 128, BN = 128, BK = 16;
    __shared__ __align__(16) float As[BK][BM + 4];
    __shared__ __align__(16) float Bs[BK][BN + 4];

    const int tid = threadIdx.x;
    const int tx = tid & 15;        // 0..15 -> 8 columns each
    const int ty = tid >> 4;        // 0..15 -> 8 rows each
    const int m0 = blockIdx.y * BM;
    const int n0 = blockIdx.x * BN;
    const int b  = blockIdx.z;

    const float* Ab = A + (size_t)b * sA;
    const float* Bb = B + (size_t)b * sB;

    float acc[8][8];
    #pragma unroll
    for (int i = 0; i < 8; i++)
        #pragma unroll
        for (int j = 0; j < 8; j++) acc[i][j] = 0.f;

    for (int k0 = 0; k0 < K; k0 += BK) {
        // load A tile -> As[k][m]
        #pragma unroll
        for (int it = 0; it < (BM * BK) / 256; it++) {
            int i = tid + it * 256;
            if (TA) { int m = i & (BM - 1), k = i >> 7;
                      As[k][m] = Ab[(size_t)(k0 + k) * M + (m0 + m)]; }
            else    { int k = i & (BK - 1), m = i >> 4;
                      As[k][m] = Ab[(size_t)(m0 + m) * K + (k0 + k)]; }
        }
        // load B tile -> Bs[k][n]
        #pragma unroll
        for (int it = 0; it < (BN * BK) / 256; it++) {
            int i = tid + it * 256;
            if (TB) { int k = i & (BK - 1), n = i >> 4;
                      Bs[k][n] = Bb[(size_t)(n0 + n) * K + (k0 + k)]; }
            else    { int n = i & (BN - 1), k = i >> 7;
                      Bs[k][n] = Bb[(size_t)(k0 + k) * N + (n0 + n)]; }
        }
        __syncthreads();

        #pragma unroll
        for (int kk = 0; kk < BK; kk++) {
            float af[8], bf[8];
            *reinterpret_cast<float4*>(&af[0]) = *reinterpret_cast<const float4*>(&As[kk][ty * 8]);
            *reinterpret_cast<float4*>(&af[4]) = *reinterpret_cast<const float4*>(&As[kk][ty * 8 + 4]);
            *reinterpret_cast<float4*>(&bf[0]) = *reinterpret_cast<const float4*>(&Bs[kk][tx * 8]);
            *reinterpret_cast<float4*>(&bf[4]) = *reinterpret_cast<const float4*>(&Bs[kk][tx * 8 + 4]);
            #pragma unroll
            for (int i = 0; i < 8; i++)
                #pragma unroll
                for (int j = 0; j < 8; j++)
                    acc[i][j] = fmaf(af[i], bf[j], acc[i][j]);
        }
        __syncthreads();
    }

    float* Cb = C + (size_t)b * sC;
    #pragma unroll
    for (int i = 0; i < 8; i++) {
        int m = m0 + ty * 8 + i;
        float bv = (EPI >= 1) ? bias[m] : 0.f;
        size_t off = (size_t)m * N + n0 + tx * 8;
        float4 o0, o1;
        o0.x = acc[i][0] + bv; o0.y = acc[i][1] + bv;
        o0.z = acc[i][2] + bv; o0.w = acc[i][3] + bv;
        o1.x = acc[i][4] + bv; o1.y = acc[i][5] + bv;
        o1.z = acc[i][6] + bv; o1.w = acc[i][7] + bv;
        if (EPI == 2) {
            const float4* rp = (const float4*)(resid + (size_t)b * sR + off);
            float4 r0 = rp[0], r1 = rp[1];
            o0.x += r0.x; o0.y += r0.y; o0.z += r0.z; o0.w += r0.w;
            o1.x += r1.x; o1.y += r1.y; o1.z += r1.z; o1.w += r1.w;
        }
        *reinterpret_cast<float4*>(&Cb[off])     = o0;
        *reinterpret_cast<float4*>(&Cb[off + 4]) = o1;
    }
}

// ---------------- launch ---------------------------------------------------------
extern "C" void kernel_launch(void* const* d_in, const int* in_sizes, int n_in,
                              void* d_out, int out_size) {
    const float* content = (const float*)d_in[0];
    const float* style   = (const float*)d_in[1];
    const float* f_w     = (const float*)d_in[2];
    const float* f_b     = (const float*)d_in[3];
    const float* g_w     = (const float*)d_in[4];
    const float* g_b     = (const float*)d_in[5];
    const float* h_w     = (const float*)d_in[6];
    const float* h_b     = (const float*)d_in[7];
    const float* o_w     = (const float*)d_in[8];
    const float* o_b     = (const float*)d_in[9];
    float* out = (float*)d_out;

    float *normC, *normS, *F, *G, *Hs, *O, *E;
    cudaGetSymbolAddress((void**)&normC, g_normC);
    cudaGetSymbolAddress((void**)&normS, g_normS);
    cudaGetSymbolAddress((void**)&F,     g_Fbuf);
    cudaGetSymbolAddress((void**)&G,     g_Gbuf);
    cudaGetSymbolAddress((void**)&Hs,    g_Hbuf);
    cudaGetSymbolAddress((void**)&O,     g_Obuf);
    cudaGetSymbolAddress((void**)&E,     g_energy);

    const long sImg = (long)NC * NHW;      // per-batch stride of [C, HW] buffers
    const long sE   = (long)NHW * NHW;     // per-batch stride of energy

    // 1) mean/variance norms
    norm_kernel<<<NB * NC, 256>>>(content, normC);
    norm_kernel<<<NB * NC, 256>>>(style,   normS);

    // 2) conv1x1's: [512x512] x [512x4096] per batch
    dim3 gconv(NHW / 128, NC / 128, NB);   // (32, 4, 4)
    gemm128<0, 0, 1><<<gconv, 256>>>(f_w, normC, F,  NC, NHW, NC, 0, sImg, sImg, f_b, nullptr, 0);
    gemm128<0, 0, 1><<<gconv, 256>>>(g_w, normS, G,  NC, NHW, NC, 0, sImg, sImg, g_b, nullptr, 0);
    gemm128<0, 0, 1><<<gconv, 256>>>(h_w, style, Hs, NC, NHW, NC, 0, sImg, sImg, h_b, nullptr, 0);

    // 3) energy = F^T G : M=N=4096, K=512 (A accessed transposed)
    dim3 ge(NHW / 128, NHW / 128, NB);     // (32, 32, 4)
    gemm128<1, 0, 0><<<ge, 256>>>(F, G, E, NHW, NHW, NC, sImg, sImg, sE, nullptr, nullptr, 0);

    // 4) softmax rows (in place)
    dim3 gs(NHW, NB);
    softmax_kernel<<<gs, 256>>>(E);

    // 5) O[c,q] = sum_k Hs[c,k] * Att[q,k] : M=512, N=4096, K=4096, B transposed
    gemm128<0, 1, 0><<<gconv, 256>>>(Hs, E, O, NC, NHW, NHW, sImg, sE, sImg, nullptr, nullptr, 0);

    // 6) out = o_w @ O + o_b + content
    gemm128<0, 0, 2><<<gconv, 256>>>(o_w, O, out, NC, NHW, NC, 0, sImg, sImg, o_b, content, sImg);
}

// round 3
// speedup vs baseline: 1.9395x; 1.9395x over previous
#include <cuda_runtime.h>
#include <cuda_bf16.h>
#include <math.h>
#include <stdint.h>

constexpr int NB  = 4;
constexpr int NC  = 512;
constexpr int NHW = 4096;
#define EPSV 1e-5f

typedef __nv_bfloat16 bf16;

// ----------------------------- scratch (static; no allocation allowed) ----------
__device__ __align__(256) float  g_E[(size_t)NB * NHW * NHW];                 // 256MB
__device__ __align__(256) float2 g_statC[NB * NC];
__device__ __align__(256) float2 g_statS[NB * NC];
__device__ __align__(256) bf16 g_nCT_h[(size_t)NB * NHW * NC], g_nCT_l[(size_t)NB * NHW * NC];
__device__ __align__(256) bf16 g_nST_h[(size_t)NB * NHW * NC], g_nST_l[(size_t)NB * NHW * NC];
__device__ __align__(256) bf16 g_sT_h [(size_t)NB * NHW * NC], g_sT_l [(size_t)NB * NHW * NC];
__device__ __align__(256) bf16 g_FT_h [(size_t)NB * NHW * NC], g_FT_l [(size_t)NB * NHW * NC];
__device__ __align__(256) bf16 g_GT_h [(size_t)NB * NHW * NC], g_GT_l [(size_t)NB * NHW * NC];
__device__ __align__(256) bf16 g_Hs_h [(size_t)NB * NC * NHW], g_Hs_l [(size_t)NB * NC * NHW];
__device__ __align__(256) bf16 g_OT_h [(size_t)NB * NHW * NC], g_OT_l [(size_t)NB * NHW * NC];
__device__ __align__(256) bf16 g_at_h [(size_t)NB * NHW * NHW];               // 128MB
__device__ __align__(256) bf16 g_at_l [(size_t)NB * NHW * NHW];               // 128MB
__device__ __align__(256) bf16 g_fw_h[NC * NC], g_fw_l[NC * NC];
__device__ __align__(256) bf16 g_gw_h[NC * NC], g_gw_l[NC * NC];
__device__ __align__(256) bf16 g_hw_h[NC * NC], g_hw_l[NC * NC];
__device__ __align__(256) bf16 g_ow_h[NC * NC], g_ow_l[NC * NC];

// ----------------------------- PTX helpers --------------------------------------
__device__ __forceinline__ uint32_t s2u(const void* p) {
    uint32_t a;
    asm("{ .reg .u64 t; cvta.to.shared.u64 t, %1; cvt.u32.u64 %0, t; }" : "=r"(a) : "l"(p));
    return a;
}
__device__ __forceinline__ void cpa16(uint32_t s, const void* g) {
    asm volatile("cp.async.cg.shared.global [%0], [%1], 16;" :: "r"(s), "l"(g));
}
__device__ __forceinline__ void cpa_commit() {
    asm volatile("cp.async.commit_group;" ::: "memory");
}
__device__ __forceinline__ void cpa_wait1() {
    asm volatile("cp.async.wait_group 1;" ::: "memory");
}
__device__ __forceinline__ void ldsm4(uint32_t a, uint32_t& r0, uint32_t& r1,
                                      uint32_t& r2, uint32_t& r3) {
    asm volatile("ldmatrix.sync.aligned.m8n8.x4.shared.b16 {%0,%1,%2,%3}, [%4];"
                 : "=r"(r0), "=r"(r1), "=r"(r2), "=r"(r3) : "r"(a));
}
__device__ __forceinline__ void mma_bf16(float* d, uint32_t a0, uint32_t a1, uint32_t a2,
                                         uint32_t a3, uint32_t b0, uint32_t b1) {
    asm volatile("mma.sync.aligned.m16n8k16.row.col.f32.bf16.bf16.f32 "
                 "{%0,%1,%2,%3}, {%4,%5,%6,%7}, {%8,%9}, {%0,%1,%2,%3};"
                 : "+f"(d[0]), "+f"(d[1]), "+f"(d[2]), "+f"(d[3])
                 : "r"(a0), "r"(a1), "r"(a2), "r"(a3), "r"(b0), "r"(b1));
}
__device__ __forceinline__ void split2(float v, ushort& h, ushort& l) {
    bf16 hb = __float2bfloat16(v);
    bf16 lb = __float2bfloat16(v - __bfloat162float(hb));
    h = __bfloat16_as_ushort(hb);
    l = __bfloat16_as_ushort(lb);
}

// ----------------------------- reductions ---------------------------------------
__device__ __forceinline__ float2 block_reduce_sum2(float s, float s2) {
    __shared__ float2 sh[8];
    int lane = threadIdx.x & 31, w = threadIdx.x >> 5;
    #pragma unroll
    for (int o = 16; o > 0; o >>= 1) {
        s  += __shfl_down_sync(0xffffffffu, s, o);
        s2 += __shfl_down_sync(0xffffffffu, s2, o);
    }
    if (lane == 0) sh[w] = make_float2(s, s2);
    __syncthreads();
    if (w == 0) {
        float2 v = (lane < 8) ? sh[lane] : make_float2(0.f, 0.f);
        #pragma unroll
        for (int o = 4; o > 0; o >>= 1) {
            v.x += __shfl_down_sync(0xffffffffu, v.x, o);
            v.y += __shfl_down_sync(0xffffffffu, v.y, o);
        }
        if (lane == 0) sh[0] = v;
    }
    __syncthreads();
    return sh[0];
}
__device__ __forceinline__ float block_reduce_max(float v) {
    __shared__ float sh[8];
    int lane = threadIdx.x & 31, w = threadIdx.x >> 5;
    #pragma unroll
    for (int o = 16; o > 0; o >>= 1) v = fmaxf(v, __shfl_down_sync(0xffffffffu, v, o));
    if (lane == 0) sh[w] = v;
    __syncthreads();
    if (w == 0) {
        float t = (lane < 8) ? sh[lane] : -3.4e38f;
        #pragma unroll
        for (int o = 4; o > 0; o >>= 1) t = fmaxf(t, __shfl_down_sync(0xffffffffu, t, o));
        if (lane == 0) sh[0] = t;
    }
    __syncthreads();
    return sh[0];
}
__device__ __forceinline__ float block_reduce_sum(float v) {
    __shared__ float sh[8];
    int lane = threadIdx.x & 31, w = threadIdx.x >> 5;
    #pragma unroll
    for (int o = 16; o > 0; o >>= 1) v += __shfl_down_sync(0xffffffffu, v, o);
    if (lane == 0) sh[w] = v;
    __syncthreads();
    if (w == 0) {
        float t = (lane < 8) ? sh[lane] : 0.f;
        #pragma unroll
        for (int o = 4; o > 0; o >>= 1) t += __shfl_down_sync(0xffffffffu, t, o);
        if (lane == 0) sh[0] = t;
    }
    __syncthreads();
    return sh[0];
}

// ----------------------------- stats: per (b,c) mean/rstd ------------------------
__global__ __launch_bounds__(256) void stats_kernel(const float* __restrict__ x,
                                                    float2* __restrict__ st) {
    size_t row = blockIdx.x;
    const float4* xp = (const float4*)(x + row * NHW);
    float s = 0.f, s2 = 0.f;
    #pragma unroll
    for (int i = 0; i < 4; i++) {
        float4 v = xp[threadIdx.x + i * 256];
        s  += v.x + v.y + v.z + v.w;
        s2 += v.x * v.x + v.y * v.y + v.z * v.z + v.w * v.w;
    }
    float2 r = block_reduce_sum2(s, s2);
    if (threadIdx.x == 0) {
        float mean = r.x * (1.f / NHW);
        float var  = r.y * (1.f / NHW) - mean * mean;
        st[row] = make_float2(mean, rsqrtf(var + EPSV));
    }
}

// ---------------- transpose + norm + bf16 hi/lo split ----------------------------
template <int MODE>
__global__ __launch_bounds__(256) void tsplit_kernel(
    const float* __restrict__ x, const float2* __restrict__ st,
    bf16* __restrict__ nh, bf16* __restrict__ nl,
    bf16* __restrict__ rh, bf16* __restrict__ rl)
{
    __shared__ float tile[32][33];
    int b  = blockIdx.z;
    int c0 = blockIdx.y * 32, q0 = blockIdx.x * 32;
    int tx = threadIdx.x & 31, ty = threadIdx.x >> 5;
    const float* xb = x + (size_t)b * NC * NHW;
    #pragma unroll
    for (int i = 0; i < 4; i++) {
        int cc = ty + 8 * i;
        tile[cc][tx] = xb[(size_t)(c0 + cc) * NHW + q0 + tx];
    }
    __syncthreads();
    int c = c0 + tx;
    float2 s = st[b * NC + c];
    #pragma unroll
    for (int i = 0; i < 4; i++) {
        int qq = ty + 8 * i;
        float v = tile[tx][qq];
        size_t o = (size_t)b * NHW * NC + (size_t)(q0 + qq) * NC + c;
        float nv = (v - s.x) * s.y;
        ushort h, l;
        split2(nv, h, l);
        nh[o] = __ushort_as_bfloat16(h);
        nl[o] = __ushort_as_bfloat16(l);
        if (MODE == 2) {
            split2(v, h, l);
            rh[o] = __ushort_as_bfloat16(h);
            rl[o] = __ushort_as_bfloat16(l);
        }
    }
}

// ---------------- weight split ---------------------------------------------------
__global__ __launch_bounds__(256) void wsplit_kernel(const float* __restrict__ w,
                                                     bf16* __restrict__ h, bf16* __restrict__ l,
                                                     int n) {
    int i = blockIdx.x * 256 + threadIdx.x;
    if (i < n) {
        ushort hh, ll;
        split2(w[i], hh, ll);
        h[i] = __ushort_as_bfloat16(hh);
        l[i] = __ushort_as_bfloat16(ll);
    }
}

// ---------------- row softmax -> bf16 hi/lo split --------------------------------
__global__ __launch_bounds__(256) void softmax_split_kernel(const float* __restrict__ E,
                                                            bf16* __restrict__ ah,
                                                            bf16* __restrict__ al) {
    size_t base = ((size_t)blockIdx.y * NHW + blockIdx.x) * NHW;
    const float4* p = (const float4*)(E + base);
    float4 v[4];
    float mx = -3.4e38f;
    #pragma unroll
    for (int i = 0; i < 4; i++) {
        v[i] = p[threadIdx.x + i * 256];
        mx = fmaxf(mx, fmaxf(fmaxf(v[i].x, v[i].y), fmaxf(v[i].z, v[i].w)));
    }
    mx = block_reduce_max(mx);
    float s = 0.f;
    #pragma unroll
    for (int i = 0; i < 4; i++) {
        v[i].x = __expf(v[i].x - mx); s += v[i].x;
        v[i].y = __expf(v[i].y - mx); s += v[i].y;
        v[i].z = __expf(v[i].z - mx); s += v[i].z;
        v[i].w = __expf(v[i].w - mx); s += v[i].w;
    }
    s = block_reduce_sum(s);
    float inv = 1.0f / s;
    uint2* hp = (uint2*)(ah + base);
    uint2* lp = (uint2*)(al + base);
    #pragma unroll
    for (int i = 0; i < 4; i++) {
        float pv[4] = {v[i].x * inv, v[i].y * inv, v[i].z * inv, v[i].w * inv};
        ushort h[4], l[4];
        #pragma unroll
        for (int j = 0; j < 4; j++) split2(pv[j], h[j], l[j]);
        uint2 uh, ul;
        uh.x = (uint32_t)h[0] | ((uint32_t)h[1] << 16);
        uh.y = (uint32_t)h[2] | ((uint32_t)h[3] << 16);
        ul.x = (uint32_t)l[0] | ((uint32_t)l[1] << 16);
        ul.y = (uint32_t)l[2] | ((uint32_t)l[3] << 16);
        hp[threadIdx.x + i * 256] = uh;
        lp[threadIdx.x + i * 256] = ul;
    }
}

// ---------------- mma.sync split-bf16 GEMM ---------------------------------------
// D[m,n] = sum_k (Ahi+Alo)[m,k]*(Bhi+Blo)[n,k]  (lo*lo dropped)
// A: [M,K] K-major; B: [N,K] K-major; both bf16 hi/lo.  M,N %128==0, K %32==0.
// SPLIT=1: C as bf16 hi/lo. SPLIT=0: C fp32 (+biasRow/+biasCol/+resid).
constexpr int TILEB  = 8192;           // 128 rows x 64 bytes (BK=32 bf16)
constexpr int STAGEB = 4 * TILEB;      // Ahi, Alo, Bhi, Blo
constexpr int NSTG   = 3;
constexpr int DSMEM  = NSTG * STAGEB;  // 96 KB

// swizzled byte offset of 16B chunk c (0..3) in row r of a 128x64B tile
__device__ __forceinline__ uint32_t swz(int r, int c) {
    return (uint32_t)(r * 64 + ((c ^ ((r >> 1) & 3)) << 4));
}

template <int SPLIT>
__global__ __launch_bounds__(256) void mma_gemm(
    const bf16* __restrict__ Ahi, const bf16* __restrict__ Alo,
    const bf16* __restrict__ Bhi, const bf16* __restrict__ Blo,
    float* __restrict__ Cf, bf16* __restrict__ Chi, bf16* __restrict__ Clo,
    int M, int N, int K,
    long sA, long sB, long sC,
    const float* __restrict__ biasRow, const float* __restrict__ biasCol,
    const float* __restrict__ resid, long sR)
{
    extern __shared__ __align__(128) char dsm[];
    const uint32_t smb = s2u(dsm);

    const int tid = threadIdx.x, wid = tid >> 5, lane = tid & 31;
    const int m0 = blockIdx.y * 128, n0 = blockIdx.x * 128, b = blockIdx.z;
    const int warpM = wid & 3, warpN = wid >> 2;
    const int KT = K / 32;

    // producer role: tid<128 -> A rows, tid>=128 -> B rows
    const int prow  = tid & 127;
    const bf16* srcH = (tid < 128) ? Ahi + (size_t)b * sA + (size_t)(m0 + prow) * K
                                   : Bhi + (size_t)b * sB + (size_t)(n0 + prow) * K;
    const bf16* srcL = (tid < 128) ? Alo + (size_t)b * sA + (size_t)(m0 + prow) * K
                                   : Blo + (size_t)b * sB + (size_t)(n0 + prow) * K;
    const uint32_t smH = smb + ((tid < 128) ? 0 : 2 * TILEB);

    auto load_stage = [&](int s, int k0) {
        const uint32_t sb = smH + s * STAGEB;
        #pragma unroll
        for (int c = 0; c < 4; c++) {
            uint32_t so = swz(prow, c);
            cpa16(sb + so,         srcH + k0 + c * 8);
            cpa16(sb + TILEB + so, srcL + k0 + c * 8);
        }
    };

    float acc[2][8][4];
    #pragma unroll
    for (int i = 0; i < 2; i++)
        #pragma unroll
        for (int j = 0; j < 8; j++)
            #pragma unroll
            for (int q = 0; q < 4; q++) acc[i][j][q] = 0.f;

    // prologue: stages 0,1
    load_stage(0, 0);  cpa_commit();
    load_stage(1, 32); cpa_commit();

    for (int kt = 0; kt < KT; kt++) {
        cpa_wait1();
        __syncthreads();
        const int cur = kt % NSTG;
        if (kt + 2 < KT) load_stage((kt + 2) % NSTG, (kt + 2) * 32);
        cpa_commit();

        const uint32_t sAh = smb + cur * STAGEB;
        const uint32_t sAl = sAh + TILEB;
        const uint32_t sBh = sAh + 2 * TILEB;
        const uint32_t sBl = sAh + 3 * TILEB;
        const int arow = warpM * 32 + (lane & 15);
        const int brow = warpN * 64 + (lane & 15);

        #pragma unroll
        for (int kk = 0; kk < 2; kk++) {
            const int ch = kk * 2 + (lane >> 4);
            uint32_t ah[2][4], al[2][4];
            #pragma unroll
            for (int mi = 0; mi < 2; mi++) {
                uint32_t off = swz(arow + mi * 16, ch);
                ldsm4(sAh + off, ah[mi][0], ah[mi][1], ah[mi][2], ah[mi][3]);
                ldsm4(sAl + off, al[mi][0], al[mi][1], al[mi][2], al[mi][3]);
            }
            #pragma unroll
            for (int ng = 0; ng < 4; ng++) {
                uint32_t off = swz(brow + ng * 16, ch);
                uint32_t h0, h1, h2, h3, l0, l1, l2, l3;
                ldsm4(sBh + off, h0, h1, h2, h3);
                ldsm4(sBl + off, l0, l1, l2, l3);
                #pragma unroll
                for (int mi = 0; mi < 2; mi++) {
                    mma_bf16(acc[mi][2 * ng],     ah[mi][0], ah[mi][1], ah[mi][2], ah[mi][3], h0, h2);
                    mma_bf16(acc[mi][2 * ng],     ah[mi][0], ah[mi][1], ah[mi][2], ah[mi][3], l0, l2);
                    mma_bf16(acc[mi][2 * ng],     al[mi][0], al[mi][1], al[mi][2], al[mi][3], h0, h2);
                    mma_bf16(acc[mi][2 * ng + 1], ah[mi][0], ah[mi][1], ah[mi][2], ah[mi][3], h1, h3);
                    mma_bf16(acc[mi][2 * ng + 1], ah[mi][0], ah[mi][1], ah[mi][2], ah[mi][3], l1, l3);
                    mma_bf16(acc[mi][2 * ng + 1], al[mi][0], al[mi][1], al[mi][2], al[mi][3], h1, h3);
                }
            }
        }
        __syncthreads();
    }

    // ---------------- epilogue -------------------------------------------------
    #pragma unroll
    for (int mi = 0; mi < 2; mi++) {
        const int r0 = m0 + warpM * 32 + mi * 16 + (lane >> 2);
        #pragma unroll
        for (int f = 0; f < 8; f++) {
            const int col = n0 + warpN * 64 + f * 8 + (lane & 3) * 2;
            float v[4] = {acc[mi][f][0], acc[mi][f][1], acc[mi][f][2], acc[mi][f][3]};
            if (biasRow) {
                float b0 = biasRow[r0], b1 = biasRow[r0 + 8];
                v[0] += b0; v[1] += b0; v[2] += b1; v[3] += b1;
            }
            if (biasCol) {
                float c0 = biasCol[col], c1 = biasCol[col + 1];
                v[0] += c0; v[1] += c1; v[2] += c0; v[3] += c1;
            }
            const size_t o0 = (size_t)b * sC + (size_t)r0 * N + col;
            const size_t o1 = o0 + (size_t)8 * N;
            if (SPLIT) {
                ushort h0, l0, h1, l1;
                split2(v[0], h0, l0); split2(v[1], h1, l1);
                *(uint32_t*)(Chi + o0) = (uint32_t)h0 | ((uint32_t)h1 << 16);
                *(uint32_t*)(Clo + o0) = (uint32_t)l0 | ((uint32_t)l1 << 16);
                split2(v[2], h0, l0); split2(v[3], h1, l1);
                *(uint32_t*)(Chi + o1) = (uint32_t)h0 | ((uint32_t)h1 << 16);
                *(uint32_t*)(Clo + o1) = (uint32_t)l0 | ((uint32_t)l1 << 16);
            } else {
                if (resid) {
                    const float* rp = resid + (size_t)b * sR;
                    float2 r0v = *(const float2*)(rp + (size_t)r0 * N + col);
                    float2 r1v = *(const float2*)(rp + (size_t)(r0 + 8) * N + col);
                    v[0] += r0v.x; v[1] += r0v.y; v[2] += r1v.x; v[3] += r1v.y;
                }
                *(float2*)(Cf + o0) = make_float2(v[0], v[1]);
                *(float2*)(Cf + o1) = make_float2(v[2], v[3]);
            }
        }
    }
}

// ----------------------------- launch --------------------------------------------
extern "C" void kernel_launch(void* const* d_in, const int* in_sizes, int n_in,
                              void* d_out, int out_size) {
    const float* content = (const float*)d_in[0];
    const float* style   = (const float*)d_in[1];
    const float* f_w = (const float*)d_in[2];
    const float* f_b = (const float*)d_in[3];
    const float* g_w = (const float*)d_in[4];
    const float* g_b = (const float*)d_in[5];
    const float* h_w = (const float*)d_in[6];
    const float* h_b = (const float*)d_in[7];
    const float* o_w = (const float*)d_in[8];
    const float* o_b = (const float*)d_in[9];
    float* out = (float*)d_out;

    float *E; float2 *stC, *stS;
    bf16 *nCTh,*nCTl,*nSTh,*nSTl,*sTh,*sTl,*FTh,*FTl,*GTh,*GTl,*Hsh,*Hsl,*OTh,*OTl,*ath,*atl;
    bf16 *fwh,*fwl,*gwh,*gwl,*hwh,*hwl,*owh,*owl;
    cudaGetSymbolAddress((void**)&E,   g_E);
    cudaGetSymbolAddress((void**)&stC, g_statC);
    cudaGetSymbolAddress((void**)&stS, g_statS);
    cudaGetSymbolAddress((void**)&nCTh, g_nCT_h); cudaGetSymbolAddress((void**)&nCTl, g_nCT_l);
    cudaGetSymbolAddress((void**)&nSTh, g_nST_h); cudaGetSymbolAddress((void**)&nSTl, g_nST_l);
    cudaGetSymbolAddress((void**)&sTh,  g_sT_h);  cudaGetSymbolAddress((void**)&sTl,  g_sT_l);
    cudaGetSymbolAddress((void**)&FTh,  g_FT_h);  cudaGetSymbolAddress((void**)&FTl,  g_FT_l);
    cudaGetSymbolAddress((void**)&GTh,  g_GT_h);  cudaGetSymbolAddress((void**)&GTl,  g_GT_l);
    cudaGetSymbolAddress((void**)&Hsh,  g_Hs_h);  cudaGetSymbolAddress((void**)&Hsl,  g_Hs_l);
    cudaGetSymbolAddress((void**)&OTh,  g_OT_h);  cudaGetSymbolAddress((void**)&OTl,  g_OT_l);
    cudaGetSymbolAddress((void**)&ath,  g_at_h);  cudaGetSymbolAddress((void**)&atl,  g_at_l);
    cudaGetSymbolAddress((void**)&fwh,  g_fw_h);  cudaGetSymbolAddress((void**)&fwl,  g_fw_l);
    cudaGetSymbolAddress((void**)&gwh,  g_gw_h);  cudaGetSymbolAddress((void**)&gwl,  g_gw_l);
    cudaGetSymbolAddress((void**)&hwh,  g_hw_h);  cudaGetSymbolAddress((void**)&hwl,  g_hw_l);
    cudaGetSymbolAddress((void**)&owh,  g_ow_h);  cudaGetSymbolAddress((void**)&owl,  g_ow_l);

    cudaFuncSetAttribute(mma_gemm<0>, cudaFuncAttributeMaxDynamicSharedMemorySize, DSMEM);
    cudaFuncSetAttribute(mma_gemm<1>, cudaFuncAttributeMaxDynamicSharedMemorySize, DSMEM);

    const long sQC = (long)NHW * NC;   // [B, 4096, 512]
    const long sCQ = (long)NC * NHW;   // [B, 512, 4096]
    const long sE  = (long)NHW * NHW;

    // 1) stats
    stats_kernel<<<NB * NC, 256>>>(content, stC);
    stats_kernel<<<NB * NC, 256>>>(style,   stS);

    // 2) transpose + split
    dim3 gt(NHW / 32, NC / 32, NB);
    tsplit_kernel<1><<<gt, 256>>>(content, stC, nCTh, nCTl, nullptr, nullptr);
    tsplit_kernel<2><<<gt, 256>>>(style,   stS, nSTh, nSTl, sTh, sTl);

    // 3) weight splits
    wsplit_kernel<<<NC * NC / 256, 256>>>(f_w, fwh, fwl, NC * NC);
    wsplit_kernel<<<NC * NC / 256, 256>>>(g_w, gwh, gwl, NC * NC);
    wsplit_kernel<<<NC * NC / 256, 256>>>(h_w, hwh, hwl, NC * NC);
    wsplit_kernel<<<NC * NC / 256, 256>>>(o_w, owh, owl, NC * NC);

    // 4) F_T[q,co] = normC_T x f_w^T  (M=4096, N=512, K=512), bias over cols
    dim3 gA(NC / 128, NHW / 128, NB);
    mma_gemm<1><<<gA, 256, DSMEM>>>(nCTh, nCTl, fwh, fwl, nullptr, FTh, FTl,
                                    NHW, NC, NC, sQC, 0, sQC, nullptr, f_b, nullptr, 0);
    mma_gemm<1><<<gA, 256, DSMEM>>>(nSTh, nSTl, gwh, gwl, nullptr, GTh, GTl,
                                    NHW, NC, NC, sQC, 0, sQC, nullptr, g_b, nullptr, 0);

    // 5) Hs[co,s] = h_w x style_T^T  (M=512, N=4096, K=512), bias over rows
    dim3 gB(NHW / 128, NC / 128, NB);
    mma_gemm<1><<<gB, 256, DSMEM>>>(hwh, hwl, sTh, sTl, nullptr, Hsh, Hsl,
                                    NC, NHW, NC, 0, sQC, sCQ, h_b, nullptr, nullptr, 0);

    // 6) E[q,s] = F_T x G_T^T  (M=4096, N=4096, K=512), fp32 out
    dim3 gE(NHW / 128, NHW / 128, NB);
    mma_gemm<0><<<gE, 256, DSMEM>>>(FTh, FTl, GTh, GTl, E, nullptr, nullptr,
                                    NHW, NHW, NC, sQC, sQC, sE, nullptr, nullptr, nullptr, 0);

    // 7) softmax rows -> att hi/lo
    dim3 gs(NHW, NB);
    softmax_split_kernel<<<gs, 256>>>(E, ath, atl);

    // 8) O_T[q,c] = att x Hs^T  (M=4096, N=512, K=4096)
    mma_gemm<1><<<gA, 256, DSMEM>>>(ath, atl, Hsh, Hsl, nullptr, OTh, OTl,
                                    NHW, NC, NHW, sE, sCQ, sQC, nullptr, nullptr, nullptr, 0);

    // 9) out[co,q] = o_w x O_T^T + o_b + content  (M=512, N=4096, K=512), fp32 out
    mma_gemm<0><<<gB, 256, DSMEM>>>(owh, owl, OTh, OTl, out, nullptr, nullptr,
                                    NC, NHW, NC, 0, sQC, sCQ, o_b, nullptr, content, sCQ);
}

// round 4
// speedup vs baseline: 2.0515x; 1.0578x over previous
#include <cuda_runtime.h>
#include <cuda_bf16.h>
#include <math.h>
#include <stdint.h>

constexpr int NB  = 4;
constexpr int NC  = 512;
constexpr int NHW = 4096;
#define EPSV 1e-5f

typedef __nv_bfloat16 bf16;

// ----------------------------- scratch (static; no allocation allowed) ----------
__device__ __align__(256) float  g_E[(size_t)NB * NHW * NHW];                 // 256MB
__device__ __align__(256) float  g_v[NB * NHW];
__device__ __align__(256) float  g_vb[NC];
__device__ __align__(256) float  g_ob2[NC];
__device__ __align__(256) float2 g_statC[NB * NC];
__device__ __align__(256) float2 g_statS[NB * NC];
__device__ __align__(256) bf16 g_nCT_h[(size_t)NB * NHW * NC], g_nCT_l[(size_t)NB * NHW * NC];
__device__ __align__(256) bf16 g_nST_h[(size_t)NB * NHW * NC], g_nST_l[(size_t)NB * NHW * NC];
__device__ __align__(256) bf16 g_sR_h [(size_t)NB * NC * NHW], g_sR_l [(size_t)NB * NC * NHW];
__device__ __align__(256) bf16 g_TT_h [(size_t)NB * NHW * NC], g_TT_l [(size_t)NB * NHW * NC];
__device__ __align__(256) bf16 g_PT_h [(size_t)NB * NHW * NC], g_PT_l [(size_t)NB * NHW * NC];
__device__ __align__(256) bf16 g_at_h [(size_t)NB * NHW * NHW];               // 128MB
__device__ __align__(256) bf16 g_at_l [(size_t)NB * NHW * NHW];               // 128MB
__device__ __align__(256) bf16 g_W1_h[NC * NC], g_W1_l[NC * NC];
__device__ __align__(256) bf16 g_Wo_h[NC * NC], g_Wo_l[NC * NC];

// ----------------------------- PTX helpers --------------------------------------
__device__ __forceinline__ uint32_t s2u(const void* p) {
    uint32_t a;
    asm("{ .reg .u64 t; cvta.to.shared.u64 t, %1; cvt.u32.u64 %0, t; }" : "=r"(a) : "l"(p));
    return a;
}
__device__ __forceinline__ void cpa16(uint32_t s, const void* g) {
    asm volatile("cp.async.cg.shared.global [%0], [%1], 16;" :: "r"(s), "l"(g));
}
__device__ __forceinline__ void cpa_commit() {
    asm volatile("cp.async.commit_group;" ::: "memory");
}
__device__ __forceinline__ void cpa_wait1() {
    asm volatile("cp.async.wait_group 1;" ::: "memory");
}
__device__ __forceinline__ void ldsm4(uint32_t a, uint32_t& r0, uint32_t& r1,
                                      uint32_t& r2, uint32_t& r3) {
    asm volatile("ldmatrix.sync.aligned.m8n8.x4.shared.b16 {%0,%1,%2,%3}, [%4];"
                 : "=r"(r0), "=r"(r1), "=r"(r2), "=r"(r3) : "r"(a));
}
__device__ __forceinline__ void mma_bf16(float* d, uint32_t a0, uint32_t a1, uint32_t a2,
                                         uint32_t a3, uint32_t b0, uint32_t b1) {
    asm volatile("mma.sync.aligned.m16n8k16.row.col.f32.bf16.bf16.f32 "
                 "{%0,%1,%2,%3}, {%4,%5,%6,%7}, {%8,%9}, {%0,%1,%2,%3};"
                 : "+f"(d[0]), "+f"(d[1]), "+f"(d[2]), "+f"(d[3])
                 : "r"(a0), "r"(a1), "r"(a2), "r"(a3), "r"(b0), "r"(b1));
}
__device__ __forceinline__ void split2(float v, ushort& h, ushort& l) {
    bf16 hb = __float2bfloat16(v);
    bf16 lb = __float2bfloat16(v - __bfloat162float(hb));
    h = __bfloat16_as_ushort(hb);
    l = __bfloat16_as_ushort(lb);
}

// ----------------------------- reductions ---------------------------------------
__device__ __forceinline__ float2 block_reduce_sum2(float s, float s2) {
    __shared__ float2 sh[8];
    int lane = threadIdx.x & 31, w = threadIdx.x >> 5;
    #pragma unroll
    for (int o = 16; o > 0; o >>= 1) {
        s  += __shfl_down_sync(0xffffffffu, s, o);
        s2 += __shfl_down_sync(0xffffffffu, s2, o);
    }
    if (lane == 0) sh[w] = make_float2(s, s2);
    __syncthreads();
    if (w == 0) {
        float2 v = (lane < 8) ? sh[lane] : make_float2(0.f, 0.f);
        #pragma unroll
        for (int o = 4; o > 0; o >>= 1) {
            v.x += __shfl_down_sync(0xffffffffu, v.x, o);
            v.y += __shfl_down_sync(0xffffffffu, v.y, o);
        }
        if (lane == 0) sh[0] = v;
    }
    __syncthreads();
    return sh[0];
}
__device__ __forceinline__ float block_reduce_max(float v) {
    __shared__ float sh[8];
    int lane = threadIdx.x & 31, w = threadIdx.x >> 5;
    #pragma unroll
    for (int o = 16; o > 0; o >>= 1) v = fmaxf(v, __shfl_down_sync(0xffffffffu, v, o));
    if (lane == 0) sh[w] = v;
    __syncthreads();
    if (w == 0) {
        float t = (lane < 8) ? sh[lane] : -3.4e38f;
        #pragma unroll
        for (int o = 4; o > 0; o >>= 1) t = fmaxf(t, __shfl_down_sync(0xffffffffu, t, o));
        if (lane == 0) sh[0] = t;
    }
    __syncthreads();
    return sh[0];
}
__device__ __forceinline__ float block_reduce_sum(float v) {
    __shared__ float sh[8];
    int lane = threadIdx.x & 31, w = threadIdx.x >> 5;
    #pragma unroll
    for (int o = 16; o > 0; o >>= 1) v += __shfl_down_sync(0xffffffffu, v, o);
    if (lane == 0) sh[w] = v;
    __syncthreads();
    if (w == 0) {
        float t = (lane < 8) ? sh[lane] : 0.f;
        #pragma unroll
        for (int o = 4; o > 0; o >>= 1) t += __shfl_down_sync(0xffffffffu, t, o);
        if (lane == 0) sh[0] = t;
    }
    __syncthreads();
    return sh[0];
}

// ----------------------------- stats: per (b,c) mean/rstd ------------------------
__global__ __launch_bounds__(256) void stats_kernel(const float* __restrict__ x,
                                                    float2* __restrict__ st) {
    size_t row = blockIdx.x;
    const float4* xp = (const float4*)(x + row * NHW);
    float s = 0.f, s2 = 0.f;
    #pragma unroll
    for (int i = 0; i < 4; i++) {
        float4 v = xp[threadIdx.x + i * 256];
        s  += v.x + v.y + v.z + v.w;
        s2 += v.x * v.x + v.y * v.y + v.z * v.z + v.w * v.w;
    }
    float2 r = block_reduce_sum2(s, s2);
    if (threadIdx.x == 0) {
        float mean = r.x * (1.f / NHW);
        float var  = r.y * (1.f / NHW) - mean * mean;
        st[row] = make_float2(mean, rsqrtf(var + EPSV));
    }
}

// ---------------- transpose + norm + bf16 hi/lo split ----------------------------
__global__ __launch_bounds__(256) void tsplit_kernel(
    const float* __restrict__ x, const float2* __restrict__ st,
    bf16* __restrict__ nh, bf16* __restrict__ nl)
{
    __shared__ float tile[32][33];
    int b  = blockIdx.z;
    int c0 = blockIdx.y * 32, q0 = blockIdx.x * 32;
    int tx = threadIdx.x & 31, ty = threadIdx.x >> 5;
    const float* xb = x + (size_t)b * NC * NHW;
    #pragma unroll
    for (int i = 0; i < 4; i++) {
        int cc = ty + 8 * i;
        tile[cc][tx] = xb[(size_t)(c0 + cc) * NHW + q0 + tx];
    }
    __syncthreads();
    int c = c0 + tx;
    float2 s = st[b * NC + c];
    #pragma unroll
    for (int i = 0; i < 4; i++) {
        int qq = ty + 8 * i;
        float v = tile[tx][qq];
        size_t o = (size_t)b * NHW * NC + (size_t)(q0 + qq) * NC + c;
        float nv = (v - s.x) * s.y;
        ushort h, l;
        split2(nv, h, l);
        nh[o] = __ushort_as_bfloat16(h);
        nl[o] = __ushort_as_bfloat16(l);
    }
}

// ---------------- natural-layout elementwise split -------------------------------
__global__ __launch_bounds__(256) void rsplit_kernel(const float* __restrict__ x,
                                                     bf16* __restrict__ h, bf16* __restrict__ l,
                                                     size_t n) {
    size_t i = (size_t)blockIdx.x * 256 + threadIdx.x;
    if (i < n) {
        ushort hh, ll;
        split2(x[i], hh, ll);
        h[i] = __ushort_as_bfloat16(hh);
        l[i] = __ushort_as_bfloat16(ll);
    }
}

// ---------------- small fp32 GEMM (512x512x512) -> bf16 split --------------------
// TA=1: D[i,j] = sum_c A[c,i]*B[c,j].  TA=0: D[i,j] = sum_c A[i,c]*B[c,j].
template <int TA>
__global__ __launch_bounds__(256) void small_gemm_split(
    const float* __restrict__ A, const float* __restrict__ B,
    bf16* __restrict__ Dh, bf16* __restrict__ Dl)
{
    __shared__ float As[32][65];
    __shared__ float Bs[32][65];
    const int tid = threadIdx.x;
    const int i0 = blockIdx.y * 64, j0 = blockIdx.x * 64;
    const int ty = tid >> 4, tx = tid & 15;
    float acc[4][4] = {};
    for (int kc = 0; kc < NC; kc += 32) {
        if (TA) {
            int ii = tid & 63, kk = tid >> 6;
            #pragma unroll
            for (int p = 0; p < 8; p++)
                As[kk + 4 * p][ii] = A[(size_t)(kc + kk + 4 * p) * NC + i0 + ii];
        } else {
            int kk = tid & 31, ib = tid >> 5;
            #pragma unroll
            for (int p = 0; p < 8; p++)
                As[kk][ib + 8 * p] = A[(size_t)(i0 + ib + 8 * p) * NC + kc + kk];
        }
        {
            int jj = tid & 63, kk = tid >> 6;
            #pragma unroll
            for (int p = 0; p < 8; p++)
                Bs[kk + 4 * p][jj] = B[(size_t)(kc + kk + 4 * p) * NC + j0 + jj];
        }
        __syncthreads();
        #pragma unroll
        for (int k = 0; k < 32; k++) {
            float a[4], bv[4];
            #pragma unroll
            for (int u = 0; u < 4; u++) a[u]  = As[k][ty * 4 + u];
            #pragma unroll
            for (int u = 0; u < 4; u++) bv[u] = Bs[k][tx * 4 + u];
            #pragma unroll
            for (int u = 0; u < 4; u++)
                #pragma unroll
                for (int w = 0; w < 4; w++) acc[u][w] = fmaf(a[u], bv[w], acc[u][w]);
        }
        __syncthreads();
    }
    #pragma unroll
    for (int u = 0; u < 4; u++)
        #pragma unroll
        for (int w = 0; w < 4; w++) {
            size_t o = (size_t)(i0 + ty * 4 + u) * NC + j0 + tx * 4 + w;
            ushort h, l;
            split2(acc[u][w], h, l);
            Dh[o] = __ushort_as_bfloat16(h);
            Dl[o] = __ushort_as_bfloat16(l);
        }
}

// ---------------- vb[j] = sum_c fb[c]*gw[c,j] ------------------------------------
__global__ __launch_bounds__(256) void vb_kernel(const float* __restrict__ fb,
                                                 const float* __restrict__ gw,
                                                 float* __restrict__ vb) {
    int j = blockIdx.x * 256 + threadIdx.x;
    float s = 0.f;
    for (int c = 0; c < NC; c++) s = fmaf(fb[c], gw[(size_t)c * NC + j], s);
    vb[j] = s;
}

// ---------------- v[b,s] = sum_j vb[j]*(style[b,j,s]-mean)*rstd -------------------
__global__ __launch_bounds__(256) void vrow_kernel(const float* __restrict__ style,
                                                   const float2* __restrict__ st,
                                                   const float* __restrict__ vb,
                                                   float* __restrict__ v) {
    int b = blockIdx.y;
    int s = blockIdx.x * 256 + threadIdx.x;
    const float* sb = style + (size_t)b * NC * NHW;
    float acc = 0.f;
    for (int j = 0; j < NC; j++) {
        float2 m = st[b * NC + j];
        acc = fmaf(vb[j], (sb[(size_t)j * NHW + s] - m.x) * m.y, acc);
    }
    v[b * NHW + s] = acc;
}

// ---------------- ob2[c] = sum_m o_w[c,m]*h_b[m] + o_b[c] ------------------------
__global__ __launch_bounds__(256) void ob2_kernel(const float* __restrict__ ow,
                                                  const float* __restrict__ hb,
                                                  const float* __restrict__ ob,
                                                  float* __restrict__ ob2) {
    int c = blockIdx.x * 256 + threadIdx.x;
    float s = ob[c];
    for (int m = 0; m < NC; m++) s = fmaf(ow[(size_t)c * NC + m], hb[m], s);
    ob2[c] = s;
}

// ---------------- row softmax(E + v[s]) -> bf16 hi/lo split ----------------------
__global__ __launch_bounds__(256) void softmax_split_kernel(const float* __restrict__ E,
                                                            const float* __restrict__ vrow,
                                                            bf16* __restrict__ ah,
                                                            bf16* __restrict__ al) {
    size_t base = ((size_t)blockIdx.y * NHW + blockIdx.x) * NHW;
    const float4* p  = (const float4*)(E + base);
    const float4* vp = (const float4*)(vrow + (size_t)blockIdx.y * NHW);
    float4 v[4];
    float mx = -3.4e38f;
    #pragma unroll
    for (int i = 0; i < 4; i++) {
        v[i] = p[threadIdx.x + i * 256];
        float4 vv = vp[threadIdx.x + i * 256];
        v[i].x += vv.x; v[i].y += vv.y; v[i].z += vv.z; v[i].w += vv.w;
        mx = fmaxf(mx, fmaxf(fmaxf(v[i].x, v[i].y), fmaxf(v[i].z, v[i].w)));
    }
    mx = block_reduce_max(mx);
    float s = 0.f;
    #pragma unroll
    for (int i = 0; i < 4; i++) {
        v[i].x = __expf(v[i].x - mx); s += v[i].x;
        v[i].y = __expf(v[i].y - mx); s += v[i].y;
        v[i].z = __expf(v[i].z - mx); s += v[i].z;
        v[i].w = __expf(v[i].w - mx); s += v[i].w;
    }
    s = block_reduce_sum(s);
    float inv = 1.0f / s;
    uint2* hp = (uint2*)(ah + base);
    uint2* lp = (uint2*)(al + base);
    #pragma unroll
    for (int i = 0; i < 4; i++) {
        float pv[4] = {v[i].x * inv, v[i].y * inv, v[i].z * inv, v[i].w * inv};
        ushort h[4], l[4];
        #pragma unroll
        for (int j = 0; j < 4; j++) split2(pv[j], h[j], l[j]);
        uint2 uh, ul;
        uh.x = (uint32_t)h[0] | ((uint32_t)h[1] << 16);
        uh.y = (uint32_t)h[2] | ((uint32_t)h[3] << 16);
        ul.x = (uint32_t)l[0] | ((uint32_t)l[1] << 16);
        ul.y = (uint32_t)l[2] | ((uint32_t)l[3] << 16);
        hp[threadIdx.x + i * 256] = uh;
        lp[threadIdx.x + i * 256] = ul;
    }
}

// ---------------- mma.sync split-bf16 GEMM ---------------------------------------
constexpr int TILEB  = 8192;           // 128 rows x 64 bytes (BK=32 bf16)
constexpr int STAGEB = 4 * TILEB;      // Ahi, Alo, Bhi, Blo
constexpr int NSTG   = 3;
constexpr int DSMEM  = NSTG * STAGEB;  // 96 KB

__device__ __forceinline__ uint32_t swz(int r, int c) {
    return (uint32_t)(r * 64 + ((c ^ ((r >> 1) & 3)) << 4));
}

template <int SPLIT>
__global__ __launch_bounds__(256, 2) void mma_gemm(
    const bf16* __restrict__ Ahi, const bf16* __restrict__ Alo,
    const bf16* __restrict__ Bhi, const bf16* __restrict__ Blo,
    float* __restrict__ Cf, bf16* __restrict__ Chi, bf16* __restrict__ Clo,
    int M, int N, int K,
    long sA, long sB, long sC,
    const float* __restrict__ biasRow, const float* __restrict__ biasCol,
    const float* __restrict__ resid, long sR)
{
    extern __shared__ __align__(128) char dsm[];
    const uint32_t smb = s2u(dsm);

    const int tid = threadIdx.x, wid = tid >> 5, lane = tid & 31;
    const int m0 = blockIdx.y * 128, n0 = blockIdx.x * 128, b = blockIdx.z;
    const int warpM = wid & 3, warpN = wid >> 2;
    const int KT = K / 32;

    const int prow  = tid & 127;
    const bf16* srcH = (tid < 128) ? Ahi + (size_t)b * sA + (size_t)(m0 + prow) * K
                                   : Bhi + (size_t)b * sB + (size_t)(n0 + prow) * K;
    const bf16* srcL = (tid < 128) ? Alo + (size_t)b * sA + (size_t)(m0 + prow) * K
                                   : Blo + (size_t)b * sB + (size_t)(n0 + prow) * K;
    const uint32_t smH = smb + ((tid < 128) ? 0 : 2 * TILEB);

    auto load_stage = [&](int s, int k0) {
        const uint32_t sb = smH + s * STAGEB;
        #pragma unroll
        for (int c = 0; c < 4; c++) {
            uint32_t so = swz(prow, c);
            cpa16(sb + so,         srcH + k0 + c * 8);
            cpa16(sb + TILEB + so, srcL + k0 + c * 8);
        }
    };

    float acc[2][8][4];
    #pragma unroll
    for (int i = 0; i < 2; i++)
        #pragma unroll
        for (int j = 0; j < 8; j++)
            #pragma unroll
            for (int q = 0; q < 4; q++) acc[i][j][q] = 0.f;

    load_stage(0, 0);  cpa_commit();
    load_stage(1, 32); cpa_commit();

    for (int kt = 0; kt < KT; kt++) {
        cpa_wait1();
        __syncthreads();
        const int cur = kt % NSTG;
        if (kt + 2 < KT) load_stage((kt + 2) % NSTG, (kt + 2) * 32);
        cpa_commit();

        const uint32_t sAh = smb + cur * STAGEB;
        const uint32_t sAl = sAh + TILEB;
        const uint32_t sBh = sAh + 2 * TILEB;
        const uint32_t sBl = sAh + 3 * TILEB;
        const int arow = warpM * 32 + (lane & 15);
        const int brow = warpN * 64 + (lane & 15);

        #pragma unroll
        for (int kk = 0; kk < 2; kk++) {
            const int ch = kk * 2 + (lane >> 4);
            uint32_t ah[2][4], al[2][4];
            #pragma unroll
            for (int mi = 0; mi < 2; mi++) {
                uint32_t off = swz(arow + mi * 16, ch);
                ldsm4(sAh + off, ah[mi][0], ah[mi][1], ah[mi][2], ah[mi][3]);
                ldsm4(sAl + off, al[mi][0], al[mi][1], al[mi][2], al[mi][3]);
            }
            #pragma unroll
            for (int ng = 0; ng < 4; ng++) {
                uint32_t off = swz(brow + ng * 16, ch);
                uint32_t h0, h1, h2, h3, l0, l1, l2, l3;
                ldsm4(sBh + off, h0, h1, h2, h3);
                ldsm4(sBl + off, l0, l1, l2, l3);
                #pragma unroll
                for (int mi = 0; mi < 2; mi++) {
                    mma_bf16(acc[mi][2 * ng],     ah[mi][0], ah[mi][1], ah[mi][2], ah[mi][3], h0, h2);
                    mma_bf16(acc[mi][2 * ng],     ah[mi][0], ah[mi][1], ah[mi][2], ah[mi][3], l0, l2);
                    mma_bf16(acc[mi][2 * ng],     al[mi][0], al[mi][1], al[mi][2], al[mi][3], h0, h2);
                    mma_bf16(acc[mi][2 * ng + 1], ah[mi][0], ah[mi][1], ah[mi][2], ah[mi][3], h1, h3);
                    mma_bf16(acc[mi][2 * ng + 1], ah[mi][0], ah[mi][1], ah[mi][2], ah[mi][3], l1, l3);
                    mma_bf16(acc[mi][2 * ng + 1], al[mi][0], al[mi][1], al[mi][2], al[mi][3], h1, h3);
                }
            }
        }
        __syncthreads();
    }

    // ---------------- epilogue -------------------------------------------------
    #pragma unroll
    for (int mi = 0; mi < 2; mi++) {
        const int r0 = m0 + warpM * 32 + mi * 16 + (lane >> 2);
        #pragma unroll
        for (int f = 0; f < 8; f++) {
            const int col = n0 + warpN * 64 + f * 8 + (lane & 3) * 2;
            float v[4] = {acc[mi][f][0], acc[mi][f][1], acc[mi][f][2], acc[mi][f][3]};
            if (biasRow) {
                float b0 = biasRow[r0], b1 = biasRow[r0 + 8];
                v[0] += b0; v[1] += b0; v[2] += b1; v[3] += b1;
            }
            if (biasCol) {
                float c0 = biasCol[col], c1 = biasCol[col + 1];
                v[0] += c0; v[1] += c1; v[2] += c0; v[3] += c1;
            }
            const size_t o0 = (size_t)b * sC + (size_t)r0 * N + col;
            const size_t o1 = o0 + (size_t)8 * N;
            if (SPLIT) {
                ushort h0, l0, h1, l1;
                split2(v[0], h0, l0); split2(v[1], h1, l1);
                *(uint32_t*)(Chi + o0) = (uint32_t)h0 | ((uint32_t)h1 << 16);
                *(uint32_t*)(Clo + o0) = (uint32_t)l0 | ((uint32_t)l1 << 16);
                split2(v[2], h0, l0); split2(v[3], h1, l1);
                *(uint32_t*)(Chi + o1) = (uint32_t)h0 | ((uint32_t)h1 << 16);
                *(uint32_t*)(Clo + o1) = (uint32_t)l0 | ((uint32_t)l1 << 16);
            } else {
                if (resid) {
                    const float* rp = resid + (size_t)b * sR;
                    float2 r0v = *(const float2*)(rp + (size_t)r0 * N + col);
                    float2 r1v = *(const float2*)(rp + (size_t)(r0 + 8) * N + col);
                    v[0] += r0v.x; v[1] += r0v.y; v[2] += r1v.x; v[3] += r1v.y;
                }
                *(float2*)(Cf + o0) = make_float2(v[0], v[1]);
                *(float2*)(Cf + o1) = make_float2(v[2], v[3]);
            }
        }
    }
}

// ----------------------------- launch --------------------------------------------
extern "C" void kernel_launch(void* const* d_in, const int* in_sizes, int n_in,
                              void* d_out, int out_size) {
    const float* content = (const float*)d_in[0];
    const float* style   = (const float*)d_in[1];
    const float* f_w = (const float*)d_in[2];
    const float* f_b = (const float*)d_in[3];
    const float* g_w = (const float*)d_in[4];
    const float* g_b = (const float*)d_in[5];   // note: gb row-terms cancel in softmax
    const float* h_w = (const float*)d_in[6];
    const float* h_b = (const float*)d_in[7];
    const float* o_w = (const float*)d_in[8];
    const float* o_b = (const float*)d_in[9];
    float* out = (float*)d_out;
    (void)g_b;

    float *E, *v, *vb, *ob2; float2 *stC, *stS;
    bf16 *nCTh,*nCTl,*nSTh,*nSTl,*sRh,*sRl,*TTh,*TTl,*PTh,*PTl,*ath,*atl;
    bf16 *W1h,*W1l,*Woh,*Wol;
    cudaGetSymbolAddress((void**)&E,   g_E);
    cudaGetSymbolAddress((void**)&v,   g_v);
    cudaGetSymbolAddress((void**)&vb,  g_vb);
    cudaGetSymbolAddress((void**)&ob2, g_ob2);
    cudaGetSymbolAddress((void**)&stC, g_statC);
    cudaGetSymbolAddress((void**)&stS, g_statS);
    cudaGetSymbolAddress((void**)&nCTh, g_nCT_h); cudaGetSymbolAddress((void**)&nCTl, g_nCT_l);
    cudaGetSymbolAddress((void**)&nSTh, g_nST_h); cudaGetSymbolAddress((void**)&nSTl, g_nST_l);
    cudaGetSymbolAddress((void**)&sRh,  g_sR_h);  cudaGetSymbolAddress((void**)&sRl,  g_sR_l);
    cudaGetSymbolAddress((void**)&TTh,  g_TT_h);  cudaGetSymbolAddress((void**)&TTl,  g_TT_l);
    cudaGetSymbolAddress((void**)&PTh,  g_PT_h);  cudaGetSymbolAddress((void**)&PTl,  g_PT_l);
    cudaGetSymbolAddress((void**)&ath,  g_at_h);  cudaGetSymbolAddress((void**)&atl,  g_at_l);
    cudaGetSymbolAddress((void**)&W1h,  g_W1_h);  cudaGetSymbolAddress((void**)&W1l,  g_W1_l);
    cudaGetSymbolAddress((void**)&Woh,  g_Wo_h);  cudaGetSymbolAddress((void**)&Wol,  g_Wo_l);

    cudaFuncSetAttribute(mma_gemm<0>, cudaFuncAttributeMaxDynamicSharedMemorySize, DSMEM);
    cudaFuncSetAttribute(mma_gemm<1>, cudaFuncAttributeMaxDynamicSharedMemorySize, DSMEM);

    const long sQC = (long)NHW * NC;   // [B, 4096, 512]
    const long sCQ = (long)NC * NHW;   // [B, 512, 4096]
    const long sE  = (long)NHW * NHW;

    // 1) stats
    stats_kernel<<<NB * NC, 256>>>(content, stC);
    stats_kernel<<<NB * NC, 256>>>(style,   stS);

    // 2) transposed normalized splits + raw style split (natural layout)
    dim3 gt(NHW / 32, NC / 32, NB);
    tsplit_kernel<<<gt, 256>>>(content, stC, nCTh, nCTl);
    tsplit_kernel<<<gt, 256>>>(style,   stS, nSTh, nSTl);
    rsplit_kernel<<<(unsigned)(((size_t)NB * NC * NHW + 255) / 256), 256>>>(
        style, sRh, sRl, (size_t)NB * NC * NHW);

    // 3) folded weights: W1 = fw^T gw, Wo = o_w h_w; bias vectors
    dim3 gw64(NC / 64, NC / 64);
    small_gemm_split<1><<<gw64, 256>>>(f_w, g_w, W1h, W1l);
    small_gemm_split<0><<<gw64, 256>>>(o_w, h_w, Woh, Wol);
    vb_kernel<<<NC / 256, 256>>>(f_b, g_w, vb);
    vrow_kernel<<<dim3(NHW / 256, NB), 256>>>(style, stS, vb, v);
    ob2_kernel<<<NC / 256, 256>>>(o_w, h_b, o_b, ob2);

    // 4) TT[s,i] = sum_j nST[s,j] * W1[i,j]   (M=4096, N=512, K=512)
    dim3 gA(NC / 128, NHW / 128, NB);
    mma_gemm<1><<<gA, 256, DSMEM>>>(nSTh, nSTl, W1h, W1l, nullptr, TTh, TTl,
                                    NHW, NC, NC, sQC, 0, sQC, nullptr, nullptr, nullptr, 0);

    // 5) E[q,s] = sum_i nCT[q,i] * TT[s,i]   (M=4096, N=4096, K=512), fp32 out
    dim3 gE(NHW / 128, NHW / 128, NB);
    mma_gemm<0><<<gE, 256, DSMEM>>>(nCTh, nCTl, TTh, TTl, E, nullptr, nullptr,
                                    NHW, NHW, NC, sQC, sQC, sE, nullptr, nullptr, nullptr, 0);

    // 6) softmax(E + v[s]) -> att hi/lo
    dim3 gs(NHW, NB);
    softmax_split_kernel<<<gs, 256>>>(E, v, ath, atl);

    // 7) PT[q,j] = sum_k att[q,k] * style[j,k]   (M=4096, N=512, K=4096)
    mma_gemm<1><<<gA, 256, DSMEM>>>(ath, atl, sRh, sRl, nullptr, PTh, PTl,
                                    NHW, NC, NHW, sE, sCQ, sQC, nullptr, nullptr, nullptr, 0);

    // 8) out[c,q] = sum_j Wo[c,j] * PT[q,j] + ob2[c] + content   (M=512, N=4096, K=512)
    dim3 gB(NHW / 128, NC / 128, NB);
    mma_gemm<0><<<gB, 256, DSMEM>>>(Woh, Wol, PTh, PTl, out, nullptr, nullptr,
                                    NC, NHW, NC, 0, sQC, sCQ, ob2, nullptr, content, sCQ);
}

// round 5
// speedup vs baseline: 3.0120x; 1.4682x over previous
#include <cuda_runtime.h>
#include <cuda_bf16.h>
#include <cuda_fp16.h>
#include <math.h>
#include <stdint.h>

constexpr int NB  = 4;
constexpr int NC  = 512;
constexpr int NHW = 4096;
#define EPSV 1e-5f

typedef __nv_bfloat16 bf16;

// ----------------------------- scratch (static; no allocation allowed) ----------
__device__ __align__(256) float  g_E[(size_t)NB * NHW * NHW];                 // 256MB
__device__ __align__(256) float  g_v[NB * NHW];
__device__ __align__(256) float  g_vb[NC];
__device__ __align__(256) float  g_ob2[NC];
__device__ __align__(256) float2 g_statC[NB * NC];
__device__ __align__(256) float2 g_statS[NB * NC];
__device__ __align__(256) bf16   g_nCT_h[(size_t)NB * NHW * NC], g_nCT_l[(size_t)NB * NHW * NC];
__device__ __align__(256) bf16   g_nST_h[(size_t)NB * NHW * NC], g_nST_l[(size_t)NB * NHW * NC];
__device__ __align__(256) ushort g_sR_h [(size_t)NB * NC * NHW], g_sR_l [(size_t)NB * NC * NHW]; // fp16
__device__ __align__(256) bf16   g_TT_h [(size_t)NB * NHW * NC], g_TT_l [(size_t)NB * NHW * NC];
__device__ __align__(256) bf16   g_PT_h [(size_t)NB * NHW * NC], g_PT_l [(size_t)NB * NHW * NC];
__device__ __align__(256) ushort g_at   [(size_t)NB * NHW * NHW];             // fp16 att, 128MB
__device__ __align__(256) bf16   g_W1_h[NC * NC], g_W1_l[NC * NC];
__device__ __align__(256) bf16   g_Wo_h[NC * NC], g_Wo_l[NC * NC];

// ----------------------------- PTX helpers --------------------------------------
__device__ __forceinline__ uint32_t s2u(const void* p) {
    uint32_t a;
    asm("{ .reg .u64 t; cvta.to.shared.u64 t, %1; cvt.u32.u64 %0, t; }" : "=r"(a) : "l"(p));
    return a;
}
__device__ __forceinline__ void cpa16(uint32_t s, const void* g) {
    asm volatile("cp.async.cg.shared.global [%0], [%1], 16;" :: "r"(s), "l"(g));
}
__device__ __forceinline__ void cpa_commit() {
    asm volatile("cp.async.commit_group;" ::: "memory");
}
__device__ __forceinline__ void cpa_wait1() {
    asm volatile("cp.async.wait_group 1;" ::: "memory");
}
__device__ __forceinline__ void ldsm4(uint32_t a, uint32_t& r0, uint32_t& r1,
                                      uint32_t& r2, uint32_t& r3) {
    asm volatile("ldmatrix.sync.aligned.m8n8.x4.shared.b16 {%0,%1,%2,%3}, [%4];"
                 : "=r"(r0), "=r"(r1), "=r"(r2), "=r"(r3) : "r"(a));
}
__device__ __forceinline__ void mma_bf16(float* d, uint32_t a0, uint32_t a1, uint32_t a2,
                                         uint32_t a3, uint32_t b0, uint32_t b1) {
    asm volatile("mma.sync.aligned.m16n8k16.row.col.f32.bf16.bf16.f32 "
                 "{%0,%1,%2,%3}, {%4,%5,%6,%7}, {%8,%9}, {%0,%1,%2,%3};"
                 : "+f"(d[0]), "+f"(d[1]), "+f"(d[2]), "+f"(d[3])
                 : "r"(a0), "r"(a1), "r"(a2), "r"(a3), "r"(b0), "r"(b1));
}
__device__ __forceinline__ void mma_fp16(float* d, uint32_t a0, uint32_t a1, uint32_t a2,
                                         uint32_t a3, uint32_t b0, uint32_t b1) {
    asm volatile("mma.sync.aligned.m16n8k16.row.col.f32.f16.f16.f32 "
                 "{%0,%1,%2,%3}, {%4,%5,%6,%7}, {%8,%9}, {%0,%1,%2,%3};"
                 : "+f"(d[0]), "+f"(d[1]), "+f"(d[2]), "+f"(d[3])
                 : "r"(a0), "r"(a1), "r"(a2), "r"(a3), "r"(b0), "r"(b1));
}
__device__ __forceinline__ void split2(float v, ushort& h, ushort& l) {
    bf16 hb = __float2bfloat16(v);
    bf16 lb = __float2bfloat16(v - __bfloat162float(hb));
    h = __bfloat16_as_ushort(hb);
    l = __bfloat16_as_ushort(lb);
}
__device__ __forceinline__ void split2h(float v, ushort& h, ushort& l) {
    __half hb = __float2half(v);
    __half lb = __float2half(v - __half2float(hb));
    h = __half_as_ushort(hb);
    l = __half_as_ushort(lb);
}

// ----------------------------- reductions ---------------------------------------
__device__ __forceinline__ float2 block_reduce_sum2(float s, float s2) {
    __shared__ float2 sh[8];
    int lane = threadIdx.x & 31, w = threadIdx.x >> 5;
    #pragma unroll
    for (int o = 16; o > 0; o >>= 1) {
        s  += __shfl_down_sync(0xffffffffu, s, o);
        s2 += __shfl_down_sync(0xffffffffu, s2, o);
    }
    if (lane == 0) sh[w] = make_float2(s, s2);
    __syncthreads();
    if (w == 0) {
        float2 v = (lane < 8) ? sh[lane] : make_float2(0.f, 0.f);
        #pragma unroll
        for (int o = 4; o > 0; o >>= 1) {
            v.x += __shfl_down_sync(0xffffffffu, v.x, o);
            v.y += __shfl_down_sync(0xffffffffu, v.y, o);
        }
        if (lane == 0) sh[0] = v;
    }
    __syncthreads();
    return sh[0];
}
__device__ __forceinline__ float block_reduce_max(float v) {
    __shared__ float sh[8];
    int lane = threadIdx.x & 31, w = threadIdx.x >> 5;
    #pragma unroll
    for (int o = 16; o > 0; o >>= 1) v = fmaxf(v, __shfl_down_sync(0xffffffffu, v, o));
    if (lane == 0) sh[w] = v;
    __syncthreads();
    if (w == 0) {
        float t = (lane < 8) ? sh[lane] : -3.4e38f;
        #pragma unroll
        for (int o = 4; o > 0; o >>= 1) t = fmaxf(t, __shfl_down_sync(0xffffffffu, t, o));
        if (lane == 0) sh[0] = t;
    }
    __syncthreads();
    return sh[0];
}
__device__ __forceinline__ float block_reduce_sum(float v) {
    __shared__ float sh[8];
    int lane = threadIdx.x & 31, w = threadIdx.x >> 5;
    #pragma unroll
    for (int o = 16; o > 0; o >>= 1) v += __shfl_down_sync(0xffffffffu, v, o);
    if (lane == 0) sh[w] = v;
    __syncthreads();
    if (w == 0) {
        float t = (lane < 8) ? sh[lane] : 0.f;
        #pragma unroll
        for (int o = 4; o > 0; o >>= 1) t += __shfl_down_sync(0xffffffffu, t, o);
        if (lane == 0) sh[0] = t;
    }
    __syncthreads();
    return sh[0];
}

// ----------------------------- stats: per (b,c) mean/rstd ------------------------
__global__ __launch_bounds__(256) void stats_kernel(const float* __restrict__ x,
                                                    float2* __restrict__ st) {
    size_t row = blockIdx.x;
    const float4* xp = (const float4*)(x + row * NHW);
    float s = 0.f, s2 = 0.f;
    #pragma unroll
    for (int i = 0; i < 4; i++) {
        float4 v = xp[threadIdx.x + i * 256];
        s  += v.x + v.y + v.z + v.w;
        s2 += v.x * v.x + v.y * v.y + v.z * v.z + v.w * v.w;
    }
    float2 r = block_reduce_sum2(s, s2);
    if (threadIdx.x == 0) {
        float mean = r.x * (1.f / NHW);
        float var  = r.y * (1.f / NHW) - mean * mean;
        st[row] = make_float2(mean, rsqrtf(var + EPSV));
    }
}

// ---------------- transpose + norm + bf16 hi/lo split ----------------------------
__global__ __launch_bounds__(256) void tsplit_kernel(
    const float* __restrict__ x, const float2* __restrict__ st,
    bf16* __restrict__ nh, bf16* __restrict__ nl)
{
    __shared__ float tile[32][33];
    int b  = blockIdx.z;
    int c0 = blockIdx.y * 32, q0 = blockIdx.x * 32;
    int tx = threadIdx.x & 31, ty = threadIdx.x >> 5;
    const float* xb = x + (size_t)b * NC * NHW;
    #pragma unroll
    for (int i = 0; i < 4; i++) {
        int cc = ty + 8 * i;
        tile[cc][tx] = xb[(size_t)(c0 + cc) * NHW + q0 + tx];
    }
    __syncthreads();
    int c = c0 + tx;
    float2 s = st[b * NC + c];
    #pragma unroll
    for (int i = 0; i < 4; i++) {
        int qq = ty + 8 * i;
        float v = tile[tx][qq];
        size_t o = (size_t)b * NHW * NC + (size_t)(q0 + qq) * NC + c;
        float nv = (v - s.x) * s.y;
        ushort h, l;
        split2(nv, h, l);
        nh[o] = __ushort_as_bfloat16(h);
        nl[o] = __ushort_as_bfloat16(l);
    }
}

// ---------------- natural-layout elementwise split (fp16) ------------------------
__global__ __launch_bounds__(256) void rsplit_h_kernel(const float* __restrict__ x,
                                                       ushort* __restrict__ h,
                                                       ushort* __restrict__ l,
                                                       size_t n) {
    size_t i = (size_t)blockIdx.x * 256 + threadIdx.x;
    if (i < n) {
        ushort hh, ll;
        split2h(x[i], hh, ll);
        h[i] = hh;
        l[i] = ll;
    }
}

// ---------------- small fp32 GEMM (512x512x512) -> bf16 split --------------------
template <int TA>
__global__ __launch_bounds__(256) void small_gemm_split(
    const float* __restrict__ A, const float* __restrict__ B,
    bf16* __restrict__ Dh, bf16* __restrict__ Dl)
{
    __shared__ float As[32][65];
    __shared__ float Bs[32][65];
    const int tid = threadIdx.x;
    const int i0 = blockIdx.y * 64, j0 = blockIdx.x * 64;
    const int ty = tid >> 4, tx = tid & 15;
    float acc[4][4] = {};
    for (int kc = 0; kc < NC; kc += 32) {
        if (TA) {
            int ii = tid & 63, kk = tid >> 6;
            #pragma unroll
            for (int p = 0; p < 8; p++)
                As[kk + 4 * p][ii] = A[(size_t)(kc + kk + 4 * p) * NC + i0 + ii];
        } else {
            int kk = tid & 31, ib = tid >> 5;
            #pragma unroll
            for (int p = 0; p < 8; p++)
                As[kk][ib + 8 * p] = A[(size_t)(i0 + ib + 8 * p) * NC + kc + kk];
        }
        {
            int jj = tid & 63, kk = tid >> 6;
            #pragma unroll
            for (int p = 0; p < 8; p++)
                Bs[kk + 4 * p][jj] = B[(size_t)(kc + kk + 4 * p) * NC + j0 + jj];
        }
        __syncthreads();
        #pragma unroll
        for (int k = 0; k < 32; k++) {
            float a[4], bv[4];
            #pragma unroll
            for (int u = 0; u < 4; u++) a[u]  = As[k][ty * 4 + u];
            #pragma unroll
            for (int u = 0; u < 4; u++) bv[u] = Bs[k][tx * 4 + u];
            #pragma unroll
            for (int u = 0; u < 4; u++)
                #pragma unroll
                for (int w = 0; w < 4; w++) acc[u][w] = fmaf(a[u], bv[w], acc[u][w]);
        }
        __syncthreads();
    }
    #pragma unroll
    for (int u = 0; u < 4; u++)
        #pragma unroll
        for (int w = 0; w < 4; w++) {
            size_t o = (size_t)(i0 + ty * 4 + u) * NC + j0 + tx * 4 + w;
            ushort h, l;
            split2(acc[u][w], h, l);
            Dh[o] = __ushort_as_bfloat16(h);
            Dl[o] = __ushort_as_bfloat16(l);
        }
}

// ---------------- vb[j] = sum_c fb[c]*gw[c,j] ------------------------------------
__global__ __launch_bounds__(256) void vb_kernel(const float* __restrict__ fb,
                                                 const float* __restrict__ gw,
                                                 float* __restrict__ vb) {
    int j = blockIdx.x * 256 + threadIdx.x;
    float s = 0.f;
    for (int c = 0; c < NC; c++) s = fmaf(fb[c], gw[(size_t)c * NC + j], s);
    vb[j] = s;
}

// ---------------- v[b,s] = sum_j vb[j]*(style[b,j,s]-mean)*rstd -------------------
__global__ __launch_bounds__(256) void vrow_kernel(const float* __restrict__ style,
                                                   const float2* __restrict__ st,
                                                   const float* __restrict__ vb,
                                                   float* __restrict__ v) {
    int b = blockIdx.y;
    int s = blockIdx.x * 256 + threadIdx.x;
    const float* sb = style + (size_t)b * NC * NHW;
    float acc = 0.f;
    for (int j = 0; j < NC; j++) {
        float2 m = st[b * NC + j];
        acc = fmaf(vb[j], (sb[(size_t)j * NHW + s] - m.x) * m.y, acc);
    }
    v[b * NHW + s] = acc;
}

// ---------------- ob2[c] = sum_m o_w[c,m]*h_b[m] + o_b[c] ------------------------
__global__ __launch_bounds__(256) void ob2_kernel(const float* __restrict__ ow,
                                                  const float* __restrict__ hb,
                                                  const float* __restrict__ ob,
                                                  float* __restrict__ ob2) {
    int c = blockIdx.x * 256 + threadIdx.x;
    float s = ob[c];
    for (int m = 0; m < NC; m++) s = fmaf(ow[(size_t)c * NC + m], hb[m], s);
    ob2[c] = s;
}

// ---------------- row softmax(E + v[s]) -> fp16 ----------------------------------
__global__ __launch_bounds__(256) void softmax_h_kernel(const float* __restrict__ E,
                                                        const float* __restrict__ vrow,
                                                        ushort* __restrict__ att) {
    size_t base = ((size_t)blockIdx.y * NHW + blockIdx.x) * NHW;
    const float4* p  = (const float4*)(E + base);
    const float4* vp = (const float4*)(vrow + (size_t)blockIdx.y * NHW);
    float4 v[4];
    float mx = -3.4e38f;
    #pragma unroll
    for (int i = 0; i < 4; i++) {
        v[i] = p[threadIdx.x + i * 256];
        float4 vv = vp[threadIdx.x + i * 256];
        v[i].x += vv.x; v[i].y += vv.y; v[i].z += vv.z; v[i].w += vv.w;
        mx = fmaxf(mx, fmaxf(fmaxf(v[i].x, v[i].y), fmaxf(v[i].z, v[i].w)));
    }
    mx = block_reduce_max(mx);
    float s = 0.f;
    #pragma unroll
    for (int i = 0; i < 4; i++) {
        v[i].x = __expf(v[i].x - mx); s += v[i].x;
        v[i].y = __expf(v[i].y - mx); s += v[i].y;
        v[i].z = __expf(v[i].z - mx); s += v[i].z;
        v[i].w = __expf(v[i].w - mx); s += v[i].w;
    }
    s = block_reduce_sum(s);
    float inv = 1.0f / s;
    uint2* ap = (uint2*)(att + base);
    #pragma unroll
    for (int i = 0; i < 4; i++) {
        ushort h[4];
        h[0] = __half_as_ushort(__float2half(v[i].x * inv));
        h[1] = __half_as_ushort(__float2half(v[i].y * inv));
        h[2] = __half_as_ushort(__float2half(v[i].z * inv));
        h[3] = __half_as_ushort(__float2half(v[i].w * inv));
        uint2 u;
        u.x = (uint32_t)h[0] | ((uint32_t)h[1] << 16);
        u.y = (uint32_t)h[2] | ((uint32_t)h[3] << 16);
        ap[threadIdx.x + i * 256] = u;
    }
}

// ---------------- 256x128x32 mma.sync GEMM ---------------------------------------
// MODE 0: bf16 3-MMA split (Ahi,Alo,Bhi,Blo).  MODE 1: fp16 2-MMA (A single, B hi/lo).
// A: [M,K] K-major; B: [N,K] K-major (2-byte elems). M%256==0, N%128==0, K%32==0.
// SPLIT=1: C bf16 hi/lo; SPLIT=0: C fp32 (+biasRow/+resid).
constexpr int ATB = 16384;           // 256 rows x 64B component
constexpr int BTB = 8192;            // 128 rows x 64B component
constexpr int NSTG = 3;

__device__ __forceinline__ uint32_t swz(int r, int c) {
    return (uint32_t)(r * 64 + ((c ^ ((r >> 1) & 3)) << 4));
}

template <int MODE, int SPLIT>
__global__ __launch_bounds__(512, 1) void mma_gemm(
    const ushort* __restrict__ Ahi, const ushort* __restrict__ Alo,
    const ushort* __restrict__ Bhi, const ushort* __restrict__ Blo,
    float* __restrict__ Cf, bf16* __restrict__ Chi, bf16* __restrict__ Clo,
    int M, int N, int K,
    long sA, long sB, long sC,
    const float* __restrict__ biasRow,
    const float* __restrict__ resid, long sR)
{
    constexpr int STG    = (MODE == 0) ? (2 * ATB + 2 * BTB) : (ATB + 2 * BTB);
    constexpr int OFF_AL = ATB;
    constexpr int OFF_BH = (MODE == 0) ? 2 * ATB : ATB;
    constexpr int OFF_BL = OFF_BH + BTB;

    extern __shared__ __align__(128) char dsm[];
    const uint32_t smb = s2u(dsm);

    const int tid = threadIdx.x, wid = tid >> 5, lane = tid & 31;
    const int m0 = blockIdx.y * 256, n0 = blockIdx.x * 128, b = blockIdx.z;
    const int warpM = wid & 3, warpN = wid >> 2;
    const int KT = K / 32;

    // producer mapping: A rows 2 chunks/thread; B 1 hi + 1 lo chunk/thread
    const int rA = tid >> 1, cA = (tid & 1) * 2;
    const int rB = tid >> 2, cB = tid & 3;
    const ushort* pAh = Ahi + (size_t)b * sA + (size_t)(m0 + rA) * K + cA * 8;
    const ushort* pAl = (MODE == 0) ? Alo + (size_t)b * sA + (size_t)(m0 + rA) * K + cA * 8 : nullptr;
    const ushort* pBh = Bhi + (size_t)b * sB + (size_t)(n0 + rB) * K + cB * 8;
    const ushort* pBl = Blo + (size_t)b * sB + (size_t)(n0 + rB) * K + cB * 8;
    const uint32_t dA0 = swz(rA, cA), dA1 = swz(rA, cA + 1);
    const uint32_t dB  = swz(rB, cB);

    auto load_stage = [&](int s, int k0) {
        const uint32_t sb = smb + s * STG;
        cpa16(sb + dA0, pAh + k0);
        cpa16(sb + dA1, pAh + k0 + 8);
        if (MODE == 0) {
            cpa16(sb + OFF_AL + dA0, pAl + k0);
            cpa16(sb + OFF_AL + dA1, pAl + k0 + 8);
        }
        cpa16(sb + OFF_BH + dB, pBh + k0);
        cpa16(sb + OFF_BL + dB, pBl + k0);
    };

    float acc[4][4][4];
    #pragma unroll
    for (int i = 0; i < 4; i++)
        #pragma unroll
        for (int j = 0; j < 4; j++)
            #pragma unroll
            for (int q = 0; q < 4; q++) acc[i][j][q] = 0.f;

    load_stage(0, 0);  cpa_commit();
    load_stage(1, 32); cpa_commit();

    const int arow = warpM * 64 + (lane & 15);
    const int brow = warpN * 32 + (lane & 15);

    for (int kt = 0; kt < KT; kt++) {
        cpa_wait1();
        __syncthreads();
        const int cur = kt % NSTG;
        if (kt + 2 < KT) load_stage((kt + 2) % NSTG, (kt + 2) * 32);
        cpa_commit();

        const uint32_t sAh = smb + cur * STG;
        const uint32_t sAl = sAh + OFF_AL;
        const uint32_t sBh = sAh + OFF_BH;
        const uint32_t sBl = sAh + OFF_BL;

        #pragma unroll
        for (int kk = 0; kk < 2; kk++) {
            const int ch = kk * 2 + (lane >> 4);
            uint32_t ah[4][4], al[4][4];
            #pragma unroll
            for (int mi = 0; mi < 4; mi++) {
                uint32_t off = swz(arow + mi * 16, ch);
                ldsm4(sAh + off, ah[mi][0], ah[mi][1], ah[mi][2], ah[mi][3]);
                if (MODE == 0)
                    ldsm4(sAl + off, al[mi][0], al[mi][1], al[mi][2], al[mi][3]);
            }
            #pragma unroll
            for (int g = 0; g < 2; g++) {
                uint32_t off = swz(brow + g * 16, ch);
                uint32_t h0, h1, h2, h3, l0, l1, l2, l3;
                ldsm4(sBh + off, h0, h1, h2, h3);
                ldsm4(sBl + off, l0, l1, l2, l3);
                #pragma unroll
                for (int mi = 0; mi < 4; mi++) {
                    if (MODE == 0) {
                        mma_bf16(acc[mi][2 * g],     ah[mi][0], ah[mi][1], ah[mi][2], ah[mi][3], h0, h2);
                        mma_bf16(acc[mi][2 * g],     ah[mi][0], ah[mi][1], ah[mi][2], ah[mi][3], l0, l2);
                        mma_bf16(acc[mi][2 * g],     al[mi][0], al[mi][1], al[mi][2], al[mi][3], h0, h2);
                        mma_bf16(acc[mi][2 * g + 1], ah[mi][0], ah[mi][1], ah[mi][2], ah[mi][3], h1, h3);
                        mma_bf16(acc[mi][2 * g + 1], ah[mi][0], ah[mi][1], ah[mi][2], ah[mi][3], l1, l3);
                        mma_bf16(acc[mi][2 * g + 1], al[mi][0], al[mi][1], al[mi][2], al[mi][3], h1, h3);
                    } else {
                        mma_fp16(acc[mi][2 * g],     ah[mi][0], ah[mi][1], ah[mi][2], ah[mi][3], h0, h2);
                        mma_fp16(acc[mi][2 * g],     ah[mi][0], ah[mi][1], ah[mi][2], ah[mi][3], l0, l2);
                        mma_fp16(acc[mi][2 * g + 1], ah[mi][0], ah[mi][1], ah[mi][2], ah[mi][3], h1, h3);
                        mma_fp16(acc[mi][2 * g + 1], ah[mi][0], ah[mi][1], ah[mi][2], ah[mi][3], l1, l3);
                    }
                }
            }
        }
        __syncthreads();
    }

    // ---------------- epilogue -------------------------------------------------
    #pragma unroll
    for (int mi = 0; mi < 4; mi++) {
        const int r0 = m0 + warpM * 64 + mi * 16 + (lane >> 2);
        #pragma unroll
        for (int j = 0; j < 4; j++) {
            const int col = n0 + warpN * 32 + j * 8 + (lane & 3) * 2;
            float v[4] = {acc[mi][j][0], acc[mi][j][1], acc[mi][j][2], acc[mi][j][3]};
            if (biasRow) {
                float b0 = biasRow[r0], b1 = biasRow[r0 + 8];
                v[0] += b0; v[1] += b0; v[2] += b1; v[3] += b1;
            }
            const size_t o0 = (size_t)b * sC + (size_t)r0 * N + col;
            const size_t o1 = o0 + (size_t)8 * N;
            if (SPLIT) {
                ushort h0, l0, h1, l1;
                split2(v[0], h0, l0); split2(v[1], h1, l1);
                *(uint32_t*)(Chi + o0) = (uint32_t)h0 | ((uint32_t)h1 << 16);
                *(uint32_t*)(Clo + o0) = (uint32_t)l0 | ((uint32_t)l1 << 16);
                split2(v[2], h0, l0); split2(v[3], h1, l1);
                *(uint32_t*)(Chi + o1) = (uint32_t)h0 | ((uint32_t)h1 << 16);
                *(uint32_t*)(Clo + o1) = (uint32_t)l0 | ((uint32_t)l1 << 16);
            } else {
                if (resid) {
                    const float* rp = resid + (size_t)b * sR;
                    float2 r0v = *(const float2*)(rp + (size_t)r0 * N + col);
                    float2 r1v = *(const float2*)(rp + (size_t)(r0 + 8) * N + col);
                    v[0] += r0v.x; v[1] += r0v.y; v[2] += r1v.x; v[3] += r1v.y;
                }
                *(float2*)(Cf + o0) = make_float2(v[0], v[1]);
                *(float2*)(Cf + o1) = make_float2(v[2], v[3]);
            }
        }
    }
}

constexpr int DSMEM0 = NSTG * (2 * ATB + 2 * BTB);  // 144 KB
constexpr int DSMEM1 = NSTG * (ATB + 2 * BTB);      // 96 KB

// ----------------------------- launch --------------------------------------------
extern "C" void kernel_launch(void* const* d_in, const int* in_sizes, int n_in,
                              void* d_out, int out_size) {
    const float* content = (const float*)d_in[0];
    const float* style   = (const float*)d_in[1];
    const float* f_w = (const float*)d_in[2];
    const float* f_b = (const float*)d_in[3];
    const float* g_w = (const float*)d_in[4];
    const float* h_w = (const float*)d_in[6];
    const float* h_b = (const float*)d_in[7];
    const float* o_w = (const float*)d_in[8];
    const float* o_b = (const float*)d_in[9];
    float* out = (float*)d_out;

    float *E, *v, *vb, *ob2; float2 *stC, *stS;
    bf16 *nCTh,*nCTl,*nSTh,*nSTl,*TTh,*TTl,*PTh,*PTl,*W1h,*W1l,*Woh,*Wol;
    ushort *sRh, *sRl, *att;
    cudaGetSymbolAddress((void**)&E,   g_E);
    cudaGetSymbolAddress((void**)&v,   g_v);
    cudaGetSymbolAddress((void**)&vb,  g_vb);
    cudaGetSymbolAddress((void**)&ob2, g_ob2);
    cudaGetSymbolAddress((void**)&stC, g_statC);
    cudaGetSymbolAddress((void**)&stS, g_statS);
    cudaGetSymbolAddress((void**)&nCTh, g_nCT_h); cudaGetSymbolAddress((void**)&nCTl, g_nCT_l);
    cudaGetSymbolAddress((void**)&nSTh, g_nST_h); cudaGetSymbolAddress((void**)&nSTl, g_nST_l);
    cudaGetSymbolAddress((void**)&sRh,  g_sR_h);  cudaGetSymbolAddress((void**)&sRl,  g_sR_l);
    cudaGetSymbolAddress((void**)&TTh,  g_TT_h);  cudaGetSymbolAddress((void**)&TTl,  g_TT_l);
    cudaGetSymbolAddress((void**)&PTh,  g_PT_h);  cudaGetSymbolAddress((void**)&PTl,  g_PT_l);
    cudaGetSymbolAddress((void**)&att,  g_at);
    cudaGetSymbolAddress((void**)&W1h,  g_W1_h);  cudaGetSymbolAddress((void**)&W1l,  g_W1_l);
    cudaGetSymbolAddress((void**)&Woh,  g_Wo_h);  cudaGetSymbolAddress((void**)&Wol,  g_Wo_l);

    cudaFuncSetAttribute(mma_gemm<0,0>, cudaFuncAttributeMaxDynamicSharedMemorySize, DSMEM0);
    cudaFuncSetAttribute(mma_gemm<0,1>, cudaFuncAttributeMaxDynamicSharedMemorySize, DSMEM0);
    cudaFuncSetAttribute(mma_gemm<1,1>, cudaFuncAttributeMaxDynamicSharedMemorySize, DSMEM1);

    const long sQC = (long)NHW * NC;   // [B, 4096, 512]
    const long sCQ = (long)NC * NHW;   // [B, 512, 4096]
    const long sE  = (long)NHW * NHW;

    // 1) stats
    stats_kernel<<<NB * NC, 256>>>(content, stC);
    stats_kernel<<<NB * NC, 256>>>(style,   stS);

    // 2) transposed normalized splits (bf16) + raw style split (fp16, natural layout)
    dim3 gt(NHW / 32, NC / 32, NB);
    tsplit_kernel<<<gt, 256>>>(content, stC, nCTh, nCTl);
    tsplit_kernel<<<gt, 256>>>(style,   stS, nSTh, nSTl);
    rsplit_h_kernel<<<(unsigned)(((size_t)NB * NC * NHW + 255) / 256), 256>>>(
        style, sRh, sRl, (size_t)NB * NC * NHW);

    // 3) folded weights: W1 = fw^T gw, Wo = o_w h_w; bias vectors
    dim3 gw64(NC / 64, NC / 64);
    small_gemm_split<1><<<gw64, 256>>>(f_w, g_w, W1h, W1l);
    small_gemm_split<0><<<gw64, 256>>>(o_w, h_w, Woh, Wol);
    vb_kernel<<<NC / 256, 256>>>(f_b, g_w, vb);
    vrow_kernel<<<dim3(NHW / 256, NB), 256>>>(style, stS, vb, v);
    ob2_kernel<<<NC / 256, 256>>>(o_w, h_b, o_b, ob2);

    // 4) TT[s,i] = sum_j nST[s,j] * W1[i,j]   (M=4096, N=512, K=512)
    dim3 gTT(NC / 128, NHW / 256, NB);      // (4, 16, 4)
    mma_gemm<0,1><<<gTT, 512, DSMEM0>>>((const ushort*)nSTh, (const ushort*)nSTl,
                                        (const ushort*)W1h, (const ushort*)W1l,
                                        nullptr, TTh, TTl,
                                        NHW, NC, NC, sQC, 0, sQC, nullptr, nullptr, 0);

    // 5) E[q,s] = sum_i nCT[q,i] * TT[s,i]   (M=4096, N=4096, K=512), fp32 out
    dim3 gE(NHW / 128, NHW / 256, NB);      // (32, 16, 4)
    mma_gemm<0,0><<<gE, 512, DSMEM0>>>((const ushort*)nCTh, (const ushort*)nCTl,
                                       (const ushort*)TTh, (const ushort*)TTl,
                                       E, nullptr, nullptr,
                                       NHW, NHW, NC, sQC, sQC, sE, nullptr, nullptr, 0);

    // 6) softmax(E + v[s]) -> att fp16
    dim3 gs(NHW, NB);
    softmax_h_kernel<<<gs, 256>>>(E, v, att);

    // 7) PT[q,j] = sum_k att[q,k] * style[j,k]   (M=4096, N=512, K=4096) fp16 2-MMA
    dim3 gP(NC / 128, NHW / 256, NB);       // (4, 16, 4)
    mma_gemm<1,1><<<gP, 512, DSMEM1>>>(att, nullptr, sRh, sRl,
                                       nullptr, PTh, PTl,
                                       NHW, NC, NHW, sE, sCQ, sQC, nullptr, nullptr, 0);

    // 8) out[c,q] = sum_j Wo[c,j] * PT[q,j] + ob2[c] + content   (M=512, N=4096, K=512)
    dim3 gO(NHW / 128, NC / 256, NB);       // (32, 2, 4)
    mma_gemm<0,0><<<gO, 512, DSMEM0>>>((const ushort*)Woh, (const ushort*)Wol,
                                       (const ushort*)PTh, (const ushort*)PTl,
                                       out, nullptr, nullptr,
                                       NC, NHW, NC, 0, sQC, sCQ, ob2, content, sCQ);
}

// round 6
// speedup vs baseline: 3.4005x; 1.1290x over previous
#include <cuda_runtime.h>
#include <cuda_bf16.h>
#include <cuda_fp16.h>
#include <math.h>
#include <stdint.h>

constexpr int NB  = 4;
constexpr int NC  = 512;
constexpr int NHW = 4096;
#define EPSV 1e-5f

typedef __nv_bfloat16 bf16;

// ----------------------------- scratch (static; no allocation allowed) ----------
__device__ __align__(256) float  g_E[(size_t)NB * NHW * NHW];                 // 256MB
__device__ __align__(256) float  g_v[NB * NHW];
__device__ __align__(256) float  g_vb[NC];
__device__ __align__(256) float  g_ob2[NC];
__device__ __align__(256) float2 g_statC[NB * NC];
__device__ __align__(256) float2 g_statS[NB * NC];
__device__ __align__(256) bf16   g_nCT_h[(size_t)NB * NHW * NC], g_nCT_l[(size_t)NB * NHW * NC];
__device__ __align__(256) bf16   g_nST_h[(size_t)NB * NHW * NC], g_nST_l[(size_t)NB * NHW * NC];
__device__ __align__(256) ushort g_sR_h [(size_t)NB * NC * NHW];              // fp16 style
__device__ __align__(256) bf16   g_TT_h [(size_t)NB * NHW * NC], g_TT_l [(size_t)NB * NHW * NC];
__device__ __align__(256) bf16   g_PT_h [(size_t)NB * NHW * NC], g_PT_l [(size_t)NB * NHW * NC];
__device__ __align__(256) ushort g_at   [(size_t)NB * NHW * NHW];             // fp16 att, 128MB
__device__ __align__(256) bf16   g_W1_h[NC * NC], g_W1_l[NC * NC];
__device__ __align__(256) bf16   g_Wo_h[NC * NC], g_Wo_l[NC * NC];

// ----------------------------- PTX helpers --------------------------------------
__device__ __forceinline__ uint32_t s2u(const void* p) {
    uint32_t a;
    asm("{ .reg .u64 t; cvta.to.shared.u64 t, %1; cvt.u32.u64 %0, t; }" : "=r"(a) : "l"(p));
    return a;
}
__device__ __forceinline__ void cpa16(uint32_t s, const void* g) {
    asm volatile("cp.async.cg.shared.global [%0], [%1], 16;" :: "r"(s), "l"(g));
}
__device__ __forceinline__ void cpa_commit() {
    asm volatile("cp.async.commit_group;" ::: "memory");
}
__device__ __forceinline__ void cpa_wait1() {
    asm volatile("cp.async.wait_group 1;" ::: "memory");
}
__device__ __forceinline__ void ldsm4(uint32_t a, uint32_t& r0, uint32_t& r1,
                                      uint32_t& r2, uint32_t& r3) {
    asm volatile("ldmatrix.sync.aligned.m8n8.x4.shared.b16 {%0,%1,%2,%3}, [%4];"
                 : "=r"(r0), "=r"(r1), "=r"(r2), "=r"(r3) : "r"(a));
}
__device__ __forceinline__ void mma_bf16(float* d, uint32_t a0, uint32_t a1, uint32_t a2,
                                         uint32_t a3, uint32_t b0, uint32_t b1) {
    asm volatile("mma.sync.aligned.m16n8k16.row.col.f32.bf16.bf16.f32 "
                 "{%0,%1,%2,%3}, {%4,%5,%6,%7}, {%8,%9}, {%0,%1,%2,%3};"
                 : "+f"(d[0]), "+f"(d[1]), "+f"(d[2]), "+f"(d[3])
                 : "r"(a0), "r"(a1), "r"(a2), "r"(a3), "r"(b0), "r"(b1));
}
__device__ __forceinline__ void mma_fp16(float* d, uint32_t a0, uint32_t a1, uint32_t a2,
                                         uint32_t a3, uint32_t b0, uint32_t b1) {
    asm volatile("mma.sync.aligned.m16n8k16.row.col.f32.f16.f16.f32 "
                 "{%0,%1,%2,%3}, {%4,%5,%6,%7}, {%8,%9}, {%0,%1,%2,%3};"
                 : "+f"(d[0]), "+f"(d[1]), "+f"(d[2]), "+f"(d[3])
                 : "r"(a0), "r"(a1), "r"(a2), "r"(a3), "r"(b0), "r"(b1));
}
__device__ __forceinline__ void split2(float v, ushort& h, ushort& l) {
    bf16 hb = __float2bfloat16(v);
    bf16 lb = __float2bfloat16(v - __bfloat162float(hb));
    h = __bfloat16_as_ushort(hb);
    l = __bfloat16_as_ushort(lb);
}

// ----------------------------- reductions ---------------------------------------
__device__ __forceinline__ float2 block_reduce_sum2(float s, float s2) {
    __shared__ float2 sh[8];
    int lane = threadIdx.x & 31, w = threadIdx.x >> 5;
    #pragma unroll
    for (int o = 16; o > 0; o >>= 1) {
        s  += __shfl_down_sync(0xffffffffu, s, o);
        s2 += __shfl_down_sync(0xffffffffu, s2, o);
    }
    if (lane == 0) sh[w] = make_float2(s, s2);
    __syncthreads();
    if (w == 0) {
        float2 v = (lane < 8) ? sh[lane] : make_float2(0.f, 0.f);
        #pragma unroll
        for (int o = 4; o > 0; o >>= 1) {
            v.x += __shfl_down_sync(0xffffffffu, v.x, o);
            v.y += __shfl_down_sync(0xffffffffu, v.y, o);
        }
        if (lane == 0) sh[0] = v;
    }
    __syncthreads();
    return sh[0];
}
__device__ __forceinline__ float block_reduce_max(float v) {
    __shared__ float sh[8];
    int lane = threadIdx.x & 31, w = threadIdx.x >> 5;
    #pragma unroll
    for (int o = 16; o > 0; o >>= 1) v = fmaxf(v, __shfl_down_sync(0xffffffffu, v, o));
    if (lane == 0) sh[w] = v;
    __syncthreads();
    if (w == 0) {
        float t = (lane < 8) ? sh[lane] : -3.4e38f;
        #pragma unroll
        for (int o = 4; o > 0; o >>= 1) t = fmaxf(t, __shfl_down_sync(0xffffffffu, t, o));
        if (lane == 0) sh[0] = t;
    }
    __syncthreads();
    return sh[0];
}
__device__ __forceinline__ float block_reduce_sum(float v) {
    __shared__ float sh[8];
    int lane = threadIdx.x & 31, w = threadIdx.x >> 5;
    #pragma unroll
    for (int o = 16; o > 0; o >>= 1) v += __shfl_down_sync(0xffffffffu, v, o);
    if (lane == 0) sh[w] = v;
    __syncthreads();
    if (w == 0) {
        float t = (lane < 8) ? sh[lane] : 0.f;
        #pragma unroll
        for (int o = 4; o > 0; o >>= 1) t += __shfl_down_sync(0xffffffffu, t, o);
        if (lane == 0) sh[0] = t;
    }
    __syncthreads();
    return sh[0];
}

// ----------------------------- stats: per (b,c) mean/rstd ------------------------
__global__ __launch_bounds__(256) void stats_kernel(const float* __restrict__ x,
                                                    float2* __restrict__ st) {
    size_t row = blockIdx.x;
    const float4* xp = (const float4*)(x + row * NHW);
    float s = 0.f, s2 = 0.f;
    #pragma unroll
    for (int i = 0; i < 4; i++) {
        float4 v = xp[threadIdx.x + i * 256];
        s  += v.x + v.y + v.z + v.w;
        s2 += v.x * v.x + v.y * v.y + v.z * v.z + v.w * v.w;
    }
    float2 r = block_reduce_sum2(s, s2);
    if (threadIdx.x == 0) {
        float mean = r.x * (1.f / NHW);
        float var  = r.y * (1.f / NHW) - mean * mean;
        st[row] = make_float2(mean, rsqrtf(var + EPSV));
    }
}

// ---------------- transpose + norm + bf16 hi/lo split ----------------------------
__global__ __launch_bounds__(256) void tsplit_kernel(
    const float* __restrict__ x, const float2* __restrict__ st,
    bf16* __restrict__ nh, bf16* __restrict__ nl)
{
    __shared__ float tile[32][33];
    int b  = blockIdx.z;
    int c0 = blockIdx.y * 32, q0 = blockIdx.x * 32;
    int tx = threadIdx.x & 31, ty = threadIdx.x >> 5;
    const float* xb = x + (size_t)b * NC * NHW;
    #pragma unroll
    for (int i = 0; i < 4; i++) {
        int cc = ty + 8 * i;
        tile[cc][tx] = xb[(size_t)(c0 + cc) * NHW + q0 + tx];
    }
    __syncthreads();
    int c = c0 + tx;
    float2 s = st[b * NC + c];
    #pragma unroll
    for (int i = 0; i < 4; i++) {
        int qq = ty + 8 * i;
        float v = tile[tx][qq];
        size_t o = (size_t)b * NHW * NC + (size_t)(q0 + qq) * NC + c;
        float nv = (v - s.x) * s.y;
        ushort h, l;
        split2(nv, h, l);
        nh[o] = __ushort_as_bfloat16(h);
        nl[o] = __ushort_as_bfloat16(l);
    }
}

// ---------------- natural-layout fp16 convert ------------------------------------
__global__ __launch_bounds__(256) void rhalf_kernel(const float* __restrict__ x,
                                                    ushort* __restrict__ h, size_t n) {
    size_t i = ((size_t)blockIdx.x * 256 + threadIdx.x) * 4;
    if (i < n) {
        float4 v = *(const float4*)(x + i);
        ushort2 a, b;
        a.x = __half_as_ushort(__float2half(v.x));
        a.y = __half_as_ushort(__float2half(v.y));
        b.x = __half_as_ushort(__float2half(v.z));
        b.y = __half_as_ushort(__float2half(v.w));
        *(ushort2*)(h + i)     = a;
        *(ushort2*)(h + i + 2) = b;
    }
}

// ---------------- small fp32 GEMM (512x512x512) -> bf16 split --------------------
template <int TA>
__global__ __launch_bounds__(256) void small_gemm_split(
    const float* __restrict__ A, const float* __restrict__ B,
    bf16* __restrict__ Dh, bf16* __restrict__ Dl)
{
    __shared__ float As[32][65];
    __shared__ float Bs[32][65];
    const int tid = threadIdx.x;
    const int i0 = blockIdx.y * 64, j0 = blockIdx.x * 64;
    const int ty = tid >> 4, tx = tid & 15;
    float acc[4][4] = {};
    for (int kc = 0; kc < NC; kc += 32) {
        if (TA) {
            int ii = tid & 63, kk = tid >> 6;
            #pragma unroll
            for (int p = 0; p < 8; p++)
                As[kk + 4 * p][ii] = A[(size_t)(kc + kk + 4 * p) * NC + i0 + ii];
        } else {
            int kk = tid & 31, ib = tid >> 5;
            #pragma unroll
            for (int p = 0; p < 8; p++)
                As[kk][ib + 8 * p] = A[(size_t)(i0 + ib + 8 * p) * NC + kc + kk];
        }
        {
            int jj = tid & 63, kk = tid >> 6;
            #pragma unroll
            for (int p = 0; p < 8; p++)
                Bs[kk + 4 * p][jj] = B[(size_t)(kc + kk + 4 * p) * NC + j0 + jj];
        }
        __syncthreads();
        #pragma unroll
        for (int k = 0; k < 32; k++) {
            float a[4], bv[4];
            #pragma unroll
            for (int u = 0; u < 4; u++) a[u]  = As[k][ty * 4 + u];
            #pragma unroll
            for (int u = 0; u < 4; u++) bv[u] = Bs[k][tx * 4 + u];
            #pragma unroll
            for (int u = 0; u < 4; u++)
                #pragma unroll
                for (int w = 0; w < 4; w++) acc[u][w] = fmaf(a[u], bv[w], acc[u][w]);
        }
        __syncthreads();
    }
    #pragma unroll
    for (int u = 0; u < 4; u++)
        #pragma unroll
        for (int w = 0; w < 4; w++) {
            size_t o = (size_t)(i0 + ty * 4 + u) * NC + j0 + tx * 4 + w;
            ushort h, l;
            split2(acc[u][w], h, l);
            Dh[o] = __ushort_as_bfloat16(h);
            Dl[o] = __ushort_as_bfloat16(l);
        }
}

// ---------------- vb[j] = sum_c fb[c]*gw[c,j] ------------------------------------
__global__ __launch_bounds__(256) void vb_kernel(const float* __restrict__ fb,
                                                 const float* __restrict__ gw,
                                                 float* __restrict__ vb) {
    int j = blockIdx.x * 256 + threadIdx.x;
    float s = 0.f;
    for (int c = 0; c < NC; c++) s = fmaf(fb[c], gw[(size_t)c * NC + j], s);
    vb[j] = s;
}

// ---------------- v[b,s] = sum_j vb[j]*(style[b,j,s]-mean)*rstd -------------------
__global__ __launch_bounds__(256) void vrow_kernel(const float* __restrict__ style,
                                                   const float2* __restrict__ st,
                                                   const float* __restrict__ vb,
                                                   float* __restrict__ v) {
    int b = blockIdx.y;
    int s = blockIdx.x * 256 + threadIdx.x;
    const float* sb = style + (size_t)b * NC * NHW;
    float acc = 0.f;
    for (int j = 0; j < NC; j++) {
        float2 m = st[b * NC + j];
        acc = fmaf(vb[j], (sb[(size_t)j * NHW + s] - m.x) * m.y, acc);
    }
    v[b * NHW + s] = acc;
}

// ---------------- ob2[c] = sum_m o_w[c,m]*h_b[m] + o_b[c] ------------------------
__global__ __launch_bounds__(256) void ob2_kernel(const float* __restrict__ ow,
                                                  const float* __restrict__ hb,
                                                  const float* __restrict__ ob,
                                                  float* __restrict__ ob2) {
    int c = blockIdx.x * 256 + threadIdx.x;
    float s = ob[c];
    for (int m = 0; m < NC; m++) s = fmaf(ow[(size_t)c * NC + m], hb[m], s);
    ob2[c] = s;
}

// ---------------- row softmax(E + v[s]) -> fp16 ----------------------------------
__global__ __launch_bounds__(256) void softmax_h_kernel(const float* __restrict__ E,
                                                        const float* __restrict__ vrow,
                                                        ushort* __restrict__ att) {
    size_t base = ((size_t)blockIdx.y * NHW + blockIdx.x) * NHW;
    const float4* p  = (const float4*)(E + base);
    const float4* vp = (const float4*)(vrow + (size_t)blockIdx.y * NHW);
    float4 v[4];
    float mx = -3.4e38f;
    #pragma unroll
    for (int i = 0; i < 4; i++) {
        v[i] = p[threadIdx.x + i * 256];
        float4 vv = vp[threadIdx.x + i * 256];
        v[i].x += vv.x; v[i].y += vv.y; v[i].z += vv.z; v[i].w += vv.w;
        mx = fmaxf(mx, fmaxf(fmaxf(v[i].x, v[i].y), fmaxf(v[i].z, v[i].w)));
    }
    mx = block_reduce_max(mx);
    float s = 0.f;
    #pragma unroll
    for (int i = 0; i < 4; i++) {
        v[i].x = __expf(v[i].x - mx); s += v[i].x;
        v[i].y = __expf(v[i].y - mx); s += v[i].y;
        v[i].z = __expf(v[i].z - mx); s += v[i].z;
        v[i].w = __expf(v[i].w - mx); s += v[i].w;
    }
    s = block_reduce_sum(s);
    float inv = 1.0f / s;
    uint2* ap = (uint2*)(att + base);
    #pragma unroll
    for (int i = 0; i < 4; i++) {
        ushort h[4];
        h[0] = __half_as_ushort(__float2half(v[i].x * inv));
        h[1] = __half_as_ushort(__float2half(v[i].y * inv));
        h[2] = __half_as_ushort(__float2half(v[i].z * inv));
        h[3] = __half_as_ushort(__float2half(v[i].w * inv));
        uint2 u;
        u.x = (uint32_t)h[0] | ((uint32_t)h[1] << 16);
        u.y = (uint32_t)h[2] | ((uint32_t)h[3] << 16);
        ap[threadIdx.x + i * 256] = u;
    }
}

// ---------------- 256x128x32 mma.sync GEMM ---------------------------------------
// MODE 0: bf16 3-MMA split (Ahi,Alo,Bhi,Blo).
// MODE 2: fp16 1-MMA (A single, B single).
// A: [M,K] K-major; B: [N,K] K-major (2-byte elems). M%256==0, N%128==0, K%32==0.
// SPLIT=1: C bf16 hi/lo; SPLIT=0: C fp32 (+biasRow/+resid).
constexpr int ATB = 16384;           // 256 rows x 64B component
constexpr int BTB = 8192;            // 128 rows x 64B component
constexpr int NSTG = 3;

__device__ __forceinline__ uint32_t swz(int r, int c) {
    return (uint32_t)(r * 64 + ((c ^ ((r >> 1) & 3)) << 4));
}

template <int MODE, int SPLIT>
__global__ __launch_bounds__(512, 1) void mma_gemm(
    const ushort* __restrict__ Ahi, const ushort* __restrict__ Alo,
    const ushort* __restrict__ Bhi, const ushort* __restrict__ Blo,
    float* __restrict__ Cf, bf16* __restrict__ Chi, bf16* __restrict__ Clo,
    int M, int N, int K,
    long sA, long sB, long sC,
    const float* __restrict__ biasRow,
    const float* __restrict__ resid, long sR)
{
    constexpr int STG    = (MODE == 0) ? (2 * ATB + 2 * BTB) : (ATB + BTB);
    constexpr int OFF_AL = ATB;
    constexpr int OFF_BH = (MODE == 0) ? 2 * ATB : ATB;
    constexpr int OFF_BL = OFF_BH + BTB;

    extern __shared__ __align__(128) char dsm[];
    const uint32_t smb = s2u(dsm);

    const int tid = threadIdx.x, wid = tid >> 5, lane = tid & 31;
    const int m0 = blockIdx.y * 256, n0 = blockIdx.x * 128, b = blockIdx.z;
    const int warpM = wid & 3, warpN = wid >> 2;
    const int KT = K / 32;

    // producer mapping: A rows 2 chunks/thread; B 1 chunk/thread (+lo for MODE0)
    const int rA = tid >> 1, cA = (tid & 1) * 2;
    const int rB = tid >> 2, cB = tid & 3;
    const ushort* pAh = Ahi + (size_t)b * sA + (size_t)(m0 + rA) * K + cA * 8;
    const ushort* pAl = (MODE == 0) ? Alo + (size_t)b * sA + (size_t)(m0 + rA) * K + cA * 8 : nullptr;
    const ushort* pBh = Bhi + (size_t)b * sB + (size_t)(n0 + rB) * K + cB * 8;
    const ushort* pBl = (MODE == 0) ? Blo + (size_t)b * sB + (size_t)(n0 + rB) * K + cB * 8 : nullptr;
    const uint32_t dA0 = swz(rA, cA), dA1 = swz(rA, cA + 1);
    const uint32_t dB  = swz(rB, cB);

    auto load_stage = [&](int s, int k0) {
        const uint32_t sb = smb + s * STG;
        cpa16(sb + dA0, pAh + k0);
        cpa16(sb + dA1, pAh + k0 + 8);
        if (MODE == 0) {
            cpa16(sb + OFF_AL + dA0, pAl + k0);
            cpa16(sb + OFF_AL + dA1, pAl + k0 + 8);
        }
        cpa16(sb + OFF_BH + dB, pBh + k0);
        if (MODE == 0) cpa16(sb + OFF_BL + dB, pBl + k0);
    };

    float acc[4][4][4];
    #pragma unroll
    for (int i = 0; i < 4; i++)
        #pragma unroll
        for (int j = 0; j < 4; j++)
            #pragma unroll
            for (int q = 0; q < 4; q++) acc[i][j][q] = 0.f;

    load_stage(0, 0);  cpa_commit();
    load_stage(1, 32); cpa_commit();

    const int arow = warpM * 64 + (lane & 15);
    const int brow = warpN * 32 + (lane & 15);

    for (int kt = 0; kt < KT; kt++) {
        cpa_wait1();
        __syncthreads();
        const int cur = kt % NSTG;
        if (kt + 2 < KT) load_stage((kt + 2) % NSTG, (kt + 2) * 32);
        cpa_commit();

        const uint32_t sAh = smb + cur * STG;
        const uint32_t sAl = sAh + OFF_AL;
        const uint32_t sBh = sAh + OFF_BH;
        const uint32_t sBl = sAh + OFF_BL;

        #pragma unroll
        for (int kk = 0; kk < 2; kk++) {
            const int ch = kk * 2 + (lane >> 4);
            uint32_t ah[4][4], al[4][4];
            #pragma unroll
            for (int mi = 0; mi < 4; mi++) {
                uint32_t off = swz(arow + mi * 16, ch);
                ldsm4(sAh + off, ah[mi][0], ah[mi][1], ah[mi][2], ah[mi][3]);
                if (MODE == 0)
                    ldsm4(sAl + off, al[mi][0], al[mi][1], al[mi][2], al[mi][3]);
            }
            #pragma unroll
            for (int g = 0; g < 2; g++) {
                uint32_t off = swz(brow + g * 16, ch);
                uint32_t h0, h1, h2, h3, l0, l1, l2, l3;
                ldsm4(sBh + off, h0, h1, h2, h3);
                if (MODE == 0) ldsm4(sBl + off, l0, l1, l2, l3);
                #pragma unroll
                for (int mi = 0; mi < 4; mi++) {
                    if (MODE == 0) {
                        mma_bf16(acc[mi][2 * g],     ah[mi][0], ah[mi][1], ah[mi][2], ah[mi][3], h0, h2);
                        mma_bf16(acc[mi][2 * g],     ah[mi][0], ah[mi][1], ah[mi][2], ah[mi][3], l0, l2);
                        mma_bf16(acc[mi][2 * g],     al[mi][0], al[mi][1], al[mi][2], al[mi][3], h0, h2);
                        mma_bf16(acc[mi][2 * g + 1], ah[mi][0], ah[mi][1], ah[mi][2], ah[mi][3], h1, h3);
                        mma_bf16(acc[mi][2 * g + 1], ah[mi][0], ah[mi][1], ah[mi][2], ah[mi][3], l1, l3);
                        mma_bf16(acc[mi][2 * g + 1], al[mi][0], al[mi][1], al[mi][2], al[mi][3], h1, h3);
                    } else {
                        mma_fp16(acc[mi][2 * g],     ah[mi][0], ah[mi][1], ah[mi][2], ah[mi][3], h0, h2);
                        mma_fp16(acc[mi][2 * g + 1], ah[mi][0], ah[mi][1], ah[mi][2], ah[mi][3], h1, h3);
                    }
                }
            }
        }
        __syncthreads();
    }

    // ---------------- epilogue -------------------------------------------------
    #pragma unroll
    for (int mi = 0; mi < 4; mi++) {
        const int r0 = m0 + warpM * 64 + mi * 16 + (lane >> 2);
        #pragma unroll
        for (int j = 0; j < 4; j++) {
            const int col = n0 + warpN * 32 + j * 8 + (lane & 3) * 2;
            float v[4] = {acc[mi][j][0], acc[mi][j][1], acc[mi][j][2], acc[mi][j][3]};
            if (biasRow) {
                float b0 = biasRow[r0], b1 = biasRow[r0 + 8];
                v[0] += b0; v[1] += b0; v[2] += b1; v[3] += b1;
            }
            const size_t o0 = (size_t)b * sC + (size_t)r0 * N + col;
            const size_t o1 = o0 + (size_t)8 * N;
            if (SPLIT) {
                ushort h0, l0, h1, l1;
                split2(v[0], h0, l0); split2(v[1], h1, l1);
                *(uint32_t*)(Chi + o0) = (uint32_t)h0 | ((uint32_t)h1 << 16);
                *(uint32_t*)(Clo + o0) = (uint32_t)l0 | ((uint32_t)l1 << 16);
                split2(v[2], h0, l0); split2(v[3], h1, l1);
                *(uint32_t*)(Chi + o1) = (uint32_t)h0 | ((uint32_t)h1 << 16);
                *(uint32_t*)(Clo + o1) = (uint32_t)l0 | ((uint32_t)l1 << 16);
            } else {
                if (resid) {
                    const float* rp = resid + (size_t)b * sR;
                    float2 r0v = *(const float2*)(rp + (size_t)r0 * N + col);
                    float2 r1v = *(const float2*)(rp + (size_t)(r0 + 8) * N + col);
                    v[0] += r0v.x; v[1] += r0v.y; v[2] += r1v.x; v[3] += r1v.y;
                }
                *(float2*)(Cf + o0) = make_float2(v[0], v[1]);
                *(float2*)(Cf + o1) = make_float2(v[2], v[3]);
            }
        }
    }
}

constexpr int DSMEM0 = NSTG * (2 * ATB + 2 * BTB);  // 144 KB
constexpr int DSMEM2 = NSTG * (ATB + BTB);          // 72 KB

// ----------------------------- launch --------------------------------------------
extern "C" void kernel_launch(void* const* d_in, const int* in_sizes, int n_in,
                              void* d_out, int out_size) {
    const float* content = (const float*)d_in[0];
    const float* style   = (const float*)d_in[1];
    const float* f_w = (const float*)d_in[2];
    const float* f_b = (const float*)d_in[3];
    const float* g_w = (const float*)d_in[4];
    const float* h_w = (const float*)d_in[6];
    const float* h_b = (const float*)d_in[7];
    const float* o_w = (const float*)d_in[8];
    const float* o_b = (const float*)d_in[9];
    float* out = (float*)d_out;

    float *E, *v, *vb, *ob2; float2 *stC, *stS;
    bf16 *nCTh,*nCTl,*nSTh,*nSTl,*TTh,*TTl,*PTh,*PTl,*W1h,*W1l,*Woh,*Wol;
    ushort *sRh, *att;
    cudaGetSymbolAddress((void**)&E,   g_E);
    cudaGetSymbolAddress((void**)&v,   g_v);
    cudaGetSymbolAddress((void**)&vb,  g_vb);
    cudaGetSymbolAddress((void**)&ob2, g_ob2);
    cudaGetSymbolAddress((void**)&stC, g_statC);
    cudaGetSymbolAddress((void**)&stS, g_statS);
    cudaGetSymbolAddress((void**)&nCTh, g_nCT_h); cudaGetSymbolAddress((void**)&nCTl, g_nCT_l);
    cudaGetSymbolAddress((void**)&nSTh, g_nST_h); cudaGetSymbolAddress((void**)&nSTl, g_nST_l);
    cudaGetSymbolAddress((void**)&sRh,  g_sR_h);
    cudaGetSymbolAddress((void**)&TTh,  g_TT_h);  cudaGetSymbolAddress((void**)&TTl,  g_TT_l);
    cudaGetSymbolAddress((void**)&PTh,  g_PT_h);  cudaGetSymbolAddress((void**)&PTl,  g_PT_l);
    cudaGetSymbolAddress((void**)&att,  g_at);
    cudaGetSymbolAddress((void**)&W1h,  g_W1_h);  cudaGetSymbolAddress((void**)&W1l,  g_W1_l);
    cudaGetSymbolAddress((void**)&Woh,  g_Wo_h);  cudaGetSymbolAddress((void**)&Wol,  g_Wo_l);

    cudaFuncSetAttribute(mma_gemm<0,0>, cudaFuncAttributeMaxDynamicSharedMemorySize, DSMEM0);
    cudaFuncSetAttribute(mma_gemm<0,1>, cudaFuncAttributeMaxDynamicSharedMemorySize, DSMEM0);
    cudaFuncSetAttribute(mma_gemm<2,1>, cudaFuncAttributeMaxDynamicSharedMemorySize, DSMEM2);

    const long sQC = (long)NHW * NC;   // [B, 4096, 512]
    const long sCQ = (long)NC * NHW;   // [B, 512, 4096]
    const long sE  = (long)NHW * NHW;

    // 1) stats
    stats_kernel<<<NB * NC, 256>>>(content, stC);
    stats_kernel<<<NB * NC, 256>>>(style,   stS);

    // 2) transposed normalized splits (bf16) + raw style fp16 (natural layout)
    dim3 gt(NHW / 32, NC / 32, NB);
    tsplit_kernel<<<gt, 256>>>(content, stC, nCTh, nCTl);
    tsplit_kernel<<<gt, 256>>>(style,   stS, nSTh, nSTl);
    rhalf_kernel<<<(unsigned)(((size_t)NB * NC * NHW / 4 + 255) / 256), 256>>>(
        style, sRh, (size_t)NB * NC * NHW);

    // 3) folded weights: W1 = fw^T gw, Wo = o_w h_w; bias vectors
    dim3 gw64(NC / 64, NC / 64);
    small_gemm_split<1><<<gw64, 256>>>(f_w, g_w, W1h, W1l);
    small_gemm_split<0><<<gw64, 256>>>(o_w, h_w, Woh, Wol);
    vb_kernel<<<NC / 256, 256>>>(f_b, g_w, vb);
    vrow_kernel<<<dim3(NHW / 256, NB), 256>>>(style, stS, vb, v);
    ob2_kernel<<<NC / 256, 256>>>(o_w, h_b, o_b, ob2);

    // 4) TT[s,i] = sum_j nST[s,j] * W1[i,j]   (M=4096, N=512, K=512)
    dim3 gTT(NC / 128, NHW / 256, NB);      // (4, 16, 4)
    mma_gemm<0,1><<<gTT, 512, DSMEM0>>>((const ushort*)nSTh, (const ushort*)nSTl,
                                        (const ushort*)W1h, (const ushort*)W1l,
                                        nullptr, TTh, TTl,
                                        NHW, NC, NC, sQC, 0, sQC, nullptr, nullptr, 0);

    // 5) E[q,s] = sum_i nCT[q,i] * TT[s,i]   (M=4096, N=4096, K=512), fp32 out
    dim3 gE(NHW / 128, NHW / 256, NB);      // (32, 16, 4)
    mma_gemm<0,0><<<gE, 512, DSMEM0>>>((const ushort*)nCTh, (const ushort*)nCTl,
                                       (const ushort*)TTh, (const ushort*)TTl,
                                       E, nullptr, nullptr,
                                       NHW, NHW, NC, sQC, sQC, sE, nullptr, nullptr, 0);

    // 6) softmax(E + v[s]) -> att fp16
    dim3 gs(NHW, NB);
    softmax_h_kernel<<<gs, 256>>>(E, v, att);

    // 7) PT[q,j] = sum_k att[q,k] * style[j,k]   (M=4096, N=512, K=4096) fp16 1-MMA
    dim3 gP(NC / 128, NHW / 256, NB);       // (4, 16, 4)
    mma_gemm<2,1><<<gP, 512, DSMEM2>>>(att, nullptr, sRh, nullptr,
                                       nullptr, PTh, PTl,
                                       NHW, NC, NHW, sE, sCQ, sQC, nullptr, nullptr, 0);

    // 8) out[c,q] = sum_j Wo[c,j] * PT[q,j] + ob2[c] + content   (M=512, N=4096, K=512)
    dim3 gO(NHW / 128, NC / 256, NB);       // (32, 2, 4)
    mma_gemm<0,0><<<gO, 512, DSMEM0>>>((const ushort*)Woh, (const ushort*)Wol,
                                       (const ushort*)PTh, (const ushort*)PTl,
                                       out, nullptr, nullptr,
                                       NC, NHW, NC, 0, sQC, sCQ, ob2, content, sCQ);
}

// round 7
// speedup vs baseline: 3.8981x; 1.1463x over previous
#include <cuda_runtime.h>
#include <cuda_bf16.h>
#include <math.h>
#include <stdint.h>

constexpr int NB  = 4;
constexpr int NC  = 512;
constexpr int NHW = 4096;
constexpr int CAP = 1024;
#define EPSV 1e-5f

typedef __nv_bfloat16 bf16;

// ----------------------------- scratch (static; no allocation allowed) ----------
__device__ __align__(256) float  g_E[(size_t)NB * NHW * NHW];                 // 256MB
__device__ __align__(256) float  g_v[NB * NHW];
__device__ __align__(256) float  g_vb[NC];
__device__ __align__(256) float  g_ob2[NC];
__device__ __align__(256) float2 g_statC[NB * NC];
__device__ __align__(256) float2 g_statS[NB * NC];
__device__ __align__(256) bf16   g_nCT_h[(size_t)NB * NHW * NC], g_nCT_l[(size_t)NB * NHW * NC];
__device__ __align__(256) bf16   g_nST_h[(size_t)NB * NHW * NC], g_nST_l[(size_t)NB * NHW * NC];
__device__ __align__(256) bf16   g_sT_h [(size_t)NB * NHW * NC], g_sT_l [(size_t)NB * NHW * NC];
__device__ __align__(256) bf16   g_TT_h [(size_t)NB * NHW * NC], g_TT_l [(size_t)NB * NHW * NC];
__device__ __align__(256) float  g_WoS  [(size_t)NB * NHW * NC];              // 32MB
__device__ __align__(256) ushort g_lidx [(size_t)NB * NHW * CAP];             // 32MB
__device__ __align__(256) float  g_lw   [(size_t)NB * NHW * CAP];             // 64MB
__device__ __align__(256) int    g_lcnt [NB * NHW];
__device__ __align__(256) bf16   g_W1_h[NC * NC], g_W1_l[NC * NC];
__device__ __align__(256) bf16   g_Wo_h[NC * NC], g_Wo_l[NC * NC];

// ----------------------------- PTX helpers --------------------------------------
__device__ __forceinline__ uint32_t s2u(const void* p) {
    uint32_t a;
    asm("{ .reg .u64 t; cvta.to.shared.u64 t, %1; cvt.u32.u64 %0, t; }" : "=r"(a) : "l"(p));
    return a;
}
__device__ __forceinline__ void cpa16(uint32_t s, const void* g) {
    asm volatile("cp.async.cg.shared.global [%0], [%1], 16;" :: "r"(s), "l"(g));
}
__device__ __forceinline__ void cpa_commit() {
    asm volatile("cp.async.commit_group;" ::: "memory");
}
__device__ __forceinline__ void cpa_wait1() {
    asm volatile("cp.async.wait_group 1;" ::: "memory");
}
__device__ __forceinline__ void ldsm4(uint32_t a, uint32_t& r0, uint32_t& r1,
                                      uint32_t& r2, uint32_t& r3) {
    asm volatile("ldmatrix.sync.aligned.m8n8.x4.shared.b16 {%0,%1,%2,%3}, [%4];"
                 : "=r"(r0), "=r"(r1), "=r"(r2), "=r"(r3) : "r"(a));
}
__device__ __forceinline__ void mma_bf16(float* d, uint32_t a0, uint32_t a1, uint32_t a2,
                                         uint32_t a3, uint32_t b0, uint32_t b1) {
    asm volatile("mma.sync.aligned.m16n8k16.row.col.f32.bf16.bf16.f32 "
                 "{%0,%1,%2,%3}, {%4,%5,%6,%7}, {%8,%9}, {%0,%1,%2,%3};"
                 : "+f"(d[0]), "+f"(d[1]), "+f"(d[2]), "+f"(d[3])
                 : "r"(a0), "r"(a1), "r"(a2), "r"(a3), "r"(b0), "r"(b1));
}
__device__ __forceinline__ void split2(float v, ushort& h, ushort& l) {
    bf16 hb = __float2bfloat16(v);
    bf16 lb = __float2bfloat16(v - __bfloat162float(hb));
    h = __bfloat16_as_ushort(hb);
    l = __bfloat16_as_ushort(lb);
}

// ----------------------------- reductions ---------------------------------------
__device__ __forceinline__ float2 block_reduce_sum2(float s, float s2) {
    __shared__ float2 sh[8];
    int lane = threadIdx.x & 31, w = threadIdx.x >> 5;
    #pragma unroll
    for (int o = 16; o > 0; o >>= 1) {
        s  += __shfl_down_sync(0xffffffffu, s, o);
        s2 += __shfl_down_sync(0xffffffffu, s2, o);
    }
    if (lane == 0) sh[w] = make_float2(s, s2);
    __syncthreads();
    if (w == 0) {
        float2 v = (lane < 8) ? sh[lane] : make_float2(0.f, 0.f);
        #pragma unroll
        for (int o = 4; o > 0; o >>= 1) {
            v.x += __shfl_down_sync(0xffffffffu, v.x, o);
            v.y += __shfl_down_sync(0xffffffffu, v.y, o);
        }
        if (lane == 0) sh[0] = v;
    }
    __syncthreads();
    return sh[0];
}
__device__ __forceinline__ float block_reduce_max(float v) {
    __shared__ float sh[8];
    int lane = threadIdx.x & 31, w = threadIdx.x >> 5;
    #pragma unroll
    for (int o = 16; o > 0; o >>= 1) v = fmaxf(v, __shfl_down_sync(0xffffffffu, v, o));
    if (lane == 0) sh[w] = v;
    __syncthreads();
    if (w == 0) {
        float t = (lane < 8) ? sh[lane] : -3.4e38f;
        #pragma unroll
        for (int o = 4; o > 0; o >>= 1) t = fmaxf(t, __shfl_down_sync(0xffffffffu, t, o));
        if (lane == 0) sh[0] = t;
    }
    __syncthreads();
    return sh[0];
}
__device__ __forceinline__ float block_reduce_sum(float v) {
    __shared__ float sh[8];
    int lane = threadIdx.x & 31, w = threadIdx.x >> 5;
    #pragma unroll
    for (int o = 16; o > 0; o >>= 1) v += __shfl_down_sync(0xffffffffu, v, o);
    if (lane == 0) sh[w] = v;
    __syncthreads();
    if (w == 0) {
        float t = (lane < 8) ? sh[lane] : 0.f;
        #pragma unroll
        for (int o = 4; o > 0; o >>= 1) t += __shfl_down_sync(0xffffffffu, t, o);
        if (lane == 0) sh[0] = t;
    }
    __syncthreads();
    return sh[0];
}

// ----------------------------- stats: per (b,c) mean/rstd ------------------------
__global__ __launch_bounds__(256) void stats_kernel(const float* __restrict__ x,
                                                    float2* __restrict__ st) {
    size_t row = blockIdx.x;
    const float4* xp = (const float4*)(x + row * NHW);
    float s = 0.f, s2 = 0.f;
    #pragma unroll
    for (int i = 0; i < 4; i++) {
        float4 v = xp[threadIdx.x + i * 256];
        s  += v.x + v.y + v.z + v.w;
        s2 += v.x * v.x + v.y * v.y + v.z * v.z + v.w * v.w;
    }
    float2 r = block_reduce_sum2(s, s2);
    if (threadIdx.x == 0) {
        float mean = r.x * (1.f / NHW);
        float var  = r.y * (1.f / NHW) - mean * mean;
        st[row] = make_float2(mean, rsqrtf(var + EPSV));
    }
}

// ---------------- transpose + norm + bf16 hi/lo split (MODE2: also raw pair) -----
template <int MODE>
__global__ __launch_bounds__(256) void tsplit_kernel(
    const float* __restrict__ x, const float2* __restrict__ st,
    bf16* __restrict__ nh, bf16* __restrict__ nl,
    bf16* __restrict__ rh, bf16* __restrict__ rl)
{
    __shared__ float tile[32][33];
    int b  = blockIdx.z;
    int c0 = blockIdx.y * 32, q0 = blockIdx.x * 32;
    int tx = threadIdx.x & 31, ty = threadIdx.x >> 5;
    const float* xb = x + (size_t)b * NC * NHW;
    #pragma unroll
    for (int i = 0; i < 4; i++) {
        int cc = ty + 8 * i;
        tile[cc][tx] = xb[(size_t)(c0 + cc) * NHW + q0 + tx];
    }
    __syncthreads();
    int c = c0 + tx;
    float2 s = st[b * NC + c];
    #pragma unroll
    for (int i = 0; i < 4; i++) {
        int qq = ty + 8 * i;
        float v = tile[tx][qq];
        size_t o = (size_t)b * NHW * NC + (size_t)(q0 + qq) * NC + c;
        float nv = (v - s.x) * s.y;
        ushort h, l;
        split2(nv, h, l);
        nh[o] = __ushort_as_bfloat16(h);
        nl[o] = __ushort_as_bfloat16(l);
        if (MODE == 2) {
            split2(v, h, l);
            rh[o] = __ushort_as_bfloat16(h);
            rl[o] = __ushort_as_bfloat16(l);
        }
    }
}

// ---------------- small fp32 GEMM (512x512x512) -> bf16 split --------------------
template <int TA>
__global__ __launch_bounds__(256) void small_gemm_split(
    const float* __restrict__ A, const float* __restrict__ B,
    bf16* __restrict__ Dh, bf16* __restrict__ Dl)
{
    __shared__ float As[32][65];
    __shared__ float Bs[32][65];
    const int tid = threadIdx.x;
    const int i0 = blockIdx.y * 64, j0 = blockIdx.x * 64;
    const int ty = tid >> 4, tx = tid & 15;
    float acc[4][4] = {};
    for (int kc = 0; kc < NC; kc += 32) {
        if (TA) {
            int ii = tid & 63, kk = tid >> 6;
            #pragma unroll
            for (int p = 0; p < 8; p++)
                As[kk + 4 * p][ii] = A[(size_t)(kc + kk + 4 * p) * NC + i0 + ii];
        } else {
            int kk = tid & 31, ib = tid >> 5;
            #pragma unroll
            for (int p = 0; p < 8; p++)
                As[kk][ib + 8 * p] = A[(size_t)(i0 + ib + 8 * p) * NC + kc + kk];
        }
        {
            int jj = tid & 63, kk = tid >> 6;
            #pragma unroll
            for (int p = 0; p < 8; p++)
                Bs[kk + 4 * p][jj] = B[(size_t)(kc + kk + 4 * p) * NC + j0 + jj];
        }
        __syncthreads();
        #pragma unroll
        for (int k = 0; k < 32; k++) {
            float a[4], bv[4];
            #pragma unroll
            for (int u = 0; u < 4; u++) a[u]  = As[k][ty * 4 + u];
            #pragma unroll
            for (int u = 0; u < 4; u++) bv[u] = Bs[k][tx * 4 + u];
            #pragma unroll
            for (int u = 0; u < 4; u++)
                #pragma unroll
                for (int w = 0; w < 4; w++) acc[u][w] = fmaf(a[u], bv[w], acc[u][w]);
        }
        __syncthreads();
    }
    #pragma unroll
    for (int u = 0; u < 4; u++)
        #pragma unroll
        for (int w = 0; w < 4; w++) {
            size_t o = (size_t)(i0 + ty * 4 + u) * NC + j0 + tx * 4 + w;
            ushort h, l;
            split2(acc[u][w], h, l);
            Dh[o] = __ushort_as_bfloat16(h);
            Dl[o] = __ushort_as_bfloat16(l);
        }
}

// ---------------- vb[j] = sum_c fb[c]*gw[c,j] ------------------------------------
__global__ __launch_bounds__(256) void vb_kernel(const float* __restrict__ fb,
                                                 const float* __restrict__ gw,
                                                 float* __restrict__ vb) {
    int j = blockIdx.x * 256 + threadIdx.x;
    float s = 0.f;
    for (int c = 0; c < NC; c++) s = fmaf(fb[c], gw[(size_t)c * NC + j], s);
    vb[j] = s;
}

// ---------------- v[b,s] = sum_j vb[j]*(style[b,j,s]-mean)*rstd -------------------
__global__ __launch_bounds__(256) void vrow_kernel(const float* __restrict__ style,
                                                   const float2* __restrict__ st,
                                                   const float* __restrict__ vb,
                                                   float* __restrict__ v) {
    int b = blockIdx.y;
    int s = blockIdx.x * 256 + threadIdx.x;
    const float* sb = style + (size_t)b * NC * NHW;
    float acc = 0.f;
    for (int j = 0; j < NC; j++) {
        float2 m = st[b * NC + j];
        acc = fmaf(vb[j], (sb[(size_t)j * NHW + s] - m.x) * m.y, acc);
    }
    v[b * NHW + s] = acc;
}

// ---------------- ob2[c] = sum_m o_w[c,m]*h_b[m] + o_b[c] ------------------------
__global__ __launch_bounds__(256) void ob2_kernel(const float* __restrict__ ow,
                                                  const float* __restrict__ hb,
                                                  const float* __restrict__ ob,
                                                  float* __restrict__ ob2) {
    int c = blockIdx.x * 256 + threadIdx.x;
    float s = ob[c];
    for (int m = 0; m < NC; m++) s = fmaf(ow[(size_t)c * NC + m], hb[m], s);
    ob2[c] = s;
}

// ---------------- softmax(E + v[s]) -> compact significant (s, w) lists ----------
// weights below e^-14 of max are dropped (expected dropped mass ~2e-6).
__global__ __launch_bounds__(256) void softmax_compact_kernel(
    const float* __restrict__ E, const float* __restrict__ vrow,
    ushort* __restrict__ lidx, float* __restrict__ lw, int* __restrict__ lcnt)
{
    __shared__ int wsum[8], wbase[8];
    const size_t rowid = (size_t)blockIdx.y * NHW + blockIdx.x;
    const size_t base  = rowid * NHW;
    const float4* p  = (const float4*)(E + base);
    const float4* vp = (const float4*)(vrow + (size_t)blockIdx.y * NHW);
    const int tid = threadIdx.x, lane = tid & 31, w = tid >> 5;

    float4 v[4];
    float mx = -3.4e38f;
    #pragma unroll
    for (int i = 0; i < 4; i++) {
        v[i] = p[tid + i * 256];
        float4 vv = vp[tid + i * 256];
        v[i].x += vv.x; v[i].y += vv.y; v[i].z += vv.z; v[i].w += vv.w;
        mx = fmaxf(mx, fmaxf(fmaxf(v[i].x, v[i].y), fmaxf(v[i].z, v[i].w)));
    }
    mx = block_reduce_max(mx);
    float s = 0.f;
    #pragma unroll
    for (int i = 0; i < 4; i++) {
        v[i].x = __expf(v[i].x - mx); s += v[i].x;
        v[i].y = __expf(v[i].y - mx); s += v[i].y;
        v[i].z = __expf(v[i].z - mx); s += v[i].z;
        v[i].w = __expf(v[i].w - mx); s += v[i].w;
    }
    s = block_reduce_sum(s);
    const float inv = 1.0f / s;
    const float THR = 8.3153e-7f;   // e^-14 (relative to max exp = 1)

    // count qualifying per thread
    int cnt = 0;
    #pragma unroll
    for (int i = 0; i < 4; i++)
        cnt += (v[i].x > THR) + (v[i].y > THR) + (v[i].z > THR) + (v[i].w > THR);

    // deterministic exclusive scan
    int incl = cnt;
    #pragma unroll
    for (int o = 1; o < 32; o <<= 1) {
        int n = __shfl_up_sync(0xffffffffu, incl, o);
        if (lane >= o) incl += n;
    }
    if (lane == 31) wsum[w] = incl;
    __syncthreads();
    if (tid == 0) {
        int r = 0;
        #pragma unroll
        for (int i = 0; i < 8; i++) { wbase[i] = r; r += wsum[i]; }
        lcnt[rowid] = (r < CAP) ? r : CAP;
    }
    __syncthreads();
    int k = wbase[w] + incl - cnt;

    ushort* ip = lidx + rowid * CAP;
    float*  wp = lw   + rowid * CAP;
    #pragma unroll
    for (int i = 0; i < 4; i++) {
        int s4 = 4 * (tid + i * 256);
        float c4[4] = {v[i].x, v[i].y, v[i].z, v[i].w};
        #pragma unroll
        for (int c = 0; c < 4; c++) {
            if (c4[c] > THR) {
                if (k < CAP) { ip[k] = (ushort)(s4 + c); wp[k] = c4[c] * inv; }
                k++;
            }
        }
    }
}

// ---------------- sparse apply: out[c,q] = ob2 + content + sum_k w*WoS[s_k,c] ----
__global__ __launch_bounds__(256) void sparse_apply_kernel(
    const float* __restrict__ WoS, const ushort* __restrict__ lidx,
    const float* __restrict__ lw, const int* __restrict__ lcnt,
    const float* __restrict__ ob2, const float* __restrict__ content,
    float* __restrict__ out)
{
    extern __shared__ float sacc[];   // [512][33]
    const int b = blockIdx.y, q0 = blockIdx.x * 32;
    const int tid = threadIdx.x, wid = tid >> 5, lane = tid & 31;
    const float* WoSb = WoS + (size_t)b * NHW * NC;

    #pragma unroll 1
    for (int j = 0; j < 4; j++) {
        const int q = q0 + wid * 4 + j;
        const size_t row = (size_t)b * NHW + q;
        const int cnt = lcnt[row];
        const ushort* ip = lidx + row * CAP;
        const float*  wp = lw   + row * CAP;
        float4 acc[4] = {};
        for (int k = 0; k < cnt; k++) {
            const int s = ip[k];
            const float wgt = wp[k];
            const float4* src = (const float4*)(WoSb + (size_t)s * NC) + lane;
            #pragma unroll
            for (int u = 0; u < 4; u++) {
                float4 vv = src[u * 32];
                acc[u].x = fmaf(wgt, vv.x, acc[u].x);
                acc[u].y = fmaf(wgt, vv.y, acc[u].y);
                acc[u].z = fmaf(wgt, vv.z, acc[u].z);
                acc[u].w = fmaf(wgt, vv.w, acc[u].w);
            }
        }
        const int qq = q - q0;
        #pragma unroll
        for (int u = 0; u < 4; u++) {
            const int c = lane * 4 + u * 128;
            sacc[(c + 0) * 33 + qq] = acc[u].x;
            sacc[(c + 1) * 33 + qq] = acc[u].y;
            sacc[(c + 2) * 33 + qq] = acc[u].z;
            sacc[(c + 3) * 33 + qq] = acc[u].w;
        }
    }
    __syncthreads();

    const float* cb = content + (size_t)b * NC * NHW;
    float* ob = out + (size_t)b * NC * NHW;
    #pragma unroll 1
    for (int p = 0; p < 16; p++) {
        const int c  = p * 32 + (tid >> 3);
        const int ch = (tid & 7) * 4;
        const float bias = ob2[c];
        float4 vv;
        vv.x = sacc[c * 33 + ch + 0] + bias;
        vv.y = sacc[c * 33 + ch + 1] + bias;
        vv.z = sacc[c * 33 + ch + 2] + bias;
        vv.w = sacc[c * 33 + ch + 3] + bias;
        const size_t o = (size_t)c * NHW + q0 + ch;
        const float4 cv = *(const float4*)(cb + o);
        vv.x += cv.x; vv.y += cv.y; vv.z += cv.z; vv.w += cv.w;
        *(float4*)(ob + o) = vv;
    }
}

// ---------------- 256x128x32 mma.sync GEMM (bf16 3-MMA split) --------------------
// A: [M,K] K-major bf16 pair; B: [N,K] K-major bf16 pair. M%256==0, N%128==0, K%32==0.
// SPLIT=1: C bf16 hi/lo; SPLIT=0: C fp32 (+biasRow/+resid).
constexpr int ATB = 16384;           // 256 rows x 64B component
constexpr int BTB = 8192;            // 128 rows x 64B component
constexpr int NSTG = 3;
constexpr int STGB = 2 * ATB + 2 * BTB;
constexpr int DSMEM0 = NSTG * STGB;  // 144 KB

__device__ __forceinline__ uint32_t swz(int r, int c) {
    return (uint32_t)(r * 64 + ((c ^ ((r >> 1) & 3)) << 4));
}

template <int SPLIT>
__global__ __launch_bounds__(512, 1) void mma_gemm(
    const bf16* __restrict__ Ahi, const bf16* __restrict__ Alo,
    const bf16* __restrict__ Bhi, const bf16* __restrict__ Blo,
    float* __restrict__ Cf, bf16* __restrict__ Chi, bf16* __restrict__ Clo,
    int M, int N, int K,
    long sA, long sB, long sC,
    const float* __restrict__ biasRow,
    const float* __restrict__ resid, long sR)
{
    extern __shared__ __align__(128) char dsm[];
    const uint32_t smb = s2u(dsm);

    const int tid = threadIdx.x, wid = tid >> 5, lane = tid & 31;
    const int m0 = blockIdx.y * 256, n0 = blockIdx.x * 128, b = blockIdx.z;
    const int warpM = wid & 3, warpN = wid >> 2;
    const int KT = K / 32;

    const int rA = tid >> 1, cA = (tid & 1) * 2;
    const int rB = tid >> 2, cB = tid & 3;
    const bf16* pAh = Ahi + (size_t)b * sA + (size_t)(m0 + rA) * K + cA * 8;
    const bf16* pAl = Alo + (size_t)b * sA + (size_t)(m0 + rA) * K + cA * 8;
    const bf16* pBh = Bhi + (size_t)b * sB + (size_t)(n0 + rB) * K + cB * 8;
    const bf16* pBl = Blo + (size_t)b * sB + (size_t)(n0 + rB) * K + cB * 8;
    const uint32_t dA0 = swz(rA, cA), dA1 = swz(rA, cA + 1);
    const uint32_t dB  = swz(rB, cB);

    auto load_stage = [&](int s, int k0) {
        const uint32_t sb = smb + s * STGB;
        cpa16(sb + dA0, pAh + k0);
        cpa16(sb + dA1, pAh + k0 + 8);
        cpa16(sb + ATB + dA0, pAl + k0);
        cpa16(sb + ATB + dA1, pAl + k0 + 8);
        cpa16(sb + 2 * ATB + dB, pBh + k0);
        cpa16(sb + 2 * ATB + BTB + dB, pBl + k0);
    };

    float acc[4][4][4];
    #pragma unroll
    for (int i = 0; i < 4; i++)
        #pragma unroll
        for (int j = 0; j < 4; j++)
            #pragma unroll
            for (int q = 0; q < 4; q++) acc[i][j][q] = 0.f;

    load_stage(0, 0);  cpa_commit();
    load_stage(1, 32); cpa_commit();

    const int arow = warpM * 64 + (lane & 15);
    const int brow = warpN * 32 + (lane & 15);

    for (int kt = 0; kt < KT; kt++) {
        cpa_wait1();
        __syncthreads();
        const int cur = kt % NSTG;
        if (kt + 2 < KT) load_stage((kt + 2) % NSTG, (kt + 2) * 32);
        cpa_commit();

        const uint32_t sAh = smb + cur * STGB;
        const uint32_t sAl = sAh + ATB;
        const uint32_t sBh = sAh + 2 * ATB;
        const uint32_t sBl = sBh + BTB;

        #pragma unroll
        for (int kk = 0; kk < 2; kk++) {
            const int ch = kk * 2 + (lane >> 4);
            uint32_t ah[4][4], al[4][4];
            #pragma unroll
            for (int mi = 0; mi < 4; mi++) {
                uint32_t off = swz(arow + mi * 16, ch);
                ldsm4(sAh + off, ah[mi][0], ah[mi][1], ah[mi][2], ah[mi][3]);
                ldsm4(sAl + off, al[mi][0], al[mi][1], al[mi][2], al[mi][3]);
            }
            #pragma unroll
            for (int g = 0; g < 2; g++) {
                uint32_t off = swz(brow + g * 16, ch);
                uint32_t h0, h1, h2, h3, l0, l1, l2, l3;
                ldsm4(sBh + off, h0, h1, h2, h3);
                ldsm4(sBl + off, l0, l1, l2, l3);
                #pragma unroll
                for (int mi = 0; mi < 4; mi++) {
                    mma_bf16(acc[mi][2 * g],     ah[mi][0], ah[mi][1], ah[mi][2], ah[mi][3], h0, h2);
                    mma_bf16(acc[mi][2 * g],     ah[mi][0], ah[mi][1], ah[mi][2], ah[mi][3], l0, l2);
                    mma_bf16(acc[mi][2 * g],     al[mi][0], al[mi][1], al[mi][2], al[mi][3], h0, h2);
                    mma_bf16(acc[mi][2 * g + 1], ah[mi][0], ah[mi][1], ah[mi][2], ah[mi][3], h1, h3);
                    mma_bf16(acc[mi][2 * g + 1], ah[mi][0], ah[mi][1], ah[mi][2], ah[mi][3], l1, l3);
                    mma_bf16(acc[mi][2 * g + 1], al[mi][0], al[mi][1], al[mi][2], al[mi][3], h1, h3);
                }
            }
        }
        __syncthreads();
    }

    // ---------------- epilogue -------------------------------------------------
    #pragma unroll
    for (int mi = 0; mi < 4; mi++) {
        const int r0 = m0 + warpM * 64 + mi * 16 + (lane >> 2);
        #pragma unroll
        for (int j = 0; j < 4; j++) {
            const int col = n0 + warpN * 32 + j * 8 + (lane & 3) * 2;
            float v[4] = {acc[mi][j][0], acc[mi][j][1], acc[mi][j][2], acc[mi][j][3]};
            if (biasRow) {
                float b0 = biasRow[r0], b1 = biasRow[r0 + 8];
                v[0] += b0; v[1] += b0; v[2] += b1; v[3] += b1;
            }
            const size_t o0 = (size_t)b * sC + (size_t)r0 * N + col;
            const size_t o1 = o0 + (size_t)8 * N;
            if (SPLIT) {
                ushort h0, l0, h1, l1;
                split2(v[0], h0, l0); split2(v[1], h1, l1);
                *(uint32_t*)(Chi + o0) = (uint32_t)h0 | ((uint32_t)h1 << 16);
                *(uint32_t*)(Clo + o0) = (uint32_t)l0 | ((uint32_t)l1 << 16);
                split2(v[2], h0, l0); split2(v[3], h1, l1);
                *(uint32_t*)(Chi + o1) = (uint32_t)h0 | ((uint32_t)h1 << 16);
                *(uint32_t*)(Clo + o1) = (uint32_t)l0 | ((uint32_t)l1 << 16);
            } else {
                if (resid) {
                    const float* rp = resid + (size_t)b * sR;
                    float2 r0v = *(const float2*)(rp + (size_t)r0 * N + col);
                    float2 r1v = *(const float2*)(rp + (size_t)(r0 + 8) * N + col);
                    v[0] += r0v.x; v[1] += r0v.y; v[2] += r1v.x; v[3] += r1v.y;
                }
                *(float2*)(Cf + o0) = make_float2(v[0], v[1]);
                *(float2*)(Cf + o1) = make_float2(v[2], v[3]);
            }
        }
    }
}

// ----------------------------- launch --------------------------------------------
extern "C" void kernel_launch(void* const* d_in, const int* in_sizes, int n_in,
                              void* d_out, int out_size) {
    const float* content = (const float*)d_in[0];
    const float* style   = (const float*)d_in[1];
    const float* f_w = (const float*)d_in[2];
    const float* f_b = (const float*)d_in[3];
    const float* g_w = (const float*)d_in[4];
    const float* h_w = (const float*)d_in[6];
    const float* h_b = (const float*)d_in[7];
    const float* o_w = (const float*)d_in[8];
    const float* o_b = (const float*)d_in[9];
    float* out = (float*)d_out;

    float *E, *v, *vb, *ob2, *WoS, *lwp; float2 *stC, *stS;
    bf16 *nCTh,*nCTl,*nSTh,*nSTl,*sTh,*sTl,*TTh,*TTl,*W1h,*W1l,*Woh,*Wol;
    ushort *lip; int *lcp;
    cudaGetSymbolAddress((void**)&E,   g_E);
    cudaGetSymbolAddress((void**)&v,   g_v);
    cudaGetSymbolAddress((void**)&vb,  g_vb);
    cudaGetSymbolAddress((void**)&ob2, g_ob2);
    cudaGetSymbolAddress((void**)&WoS, g_WoS);
    cudaGetSymbolAddress((void**)&stC, g_statC);
    cudaGetSymbolAddress((void**)&stS, g_statS);
    cudaGetSymbolAddress((void**)&nCTh, g_nCT_h); cudaGetSymbolAddress((void**)&nCTl, g_nCT_l);
    cudaGetSymbolAddress((void**)&nSTh, g_nST_h); cudaGetSymbolAddress((void**)&nSTl, g_nST_l);
    cudaGetSymbolAddress((void**)&sTh,  g_sT_h);  cudaGetSymbolAddress((void**)&sTl,  g_sT_l);
    cudaGetSymbolAddress((void**)&TTh,  g_TT_h);  cudaGetSymbolAddress((void**)&TTl,  g_TT_l);
    cudaGetSymbolAddress((void**)&W1h,  g_W1_h);  cudaGetSymbolAddress((void**)&W1l,  g_W1_l);
    cudaGetSymbolAddress((void**)&Woh,  g_Wo_h);  cudaGetSymbolAddress((void**)&Wol,  g_Wo_l);
    cudaGetSymbolAddress((void**)&lip,  g_lidx);
    cudaGetSymbolAddress((void**)&lwp,  g_lw);
    cudaGetSymbolAddress((void**)&lcp,  g_lcnt);

    cudaFuncSetAttribute(mma_gemm<0>, cudaFuncAttributeMaxDynamicSharedMemorySize, DSMEM0);
    cudaFuncSetAttribute(mma_gemm<1>, cudaFuncAttributeMaxDynamicSharedMemorySize, DSMEM0);
    cudaFuncSetAttribute(sparse_apply_kernel, cudaFuncAttributeMaxDynamicSharedMemorySize, 512 * 33 * 4);

    const long sQC = (long)NHW * NC;   // [B, 4096, 512]
    const long sE  = (long)NHW * NHW;

    // 1) stats
    stats_kernel<<<NB * NC, 256>>>(content, stC);
    stats_kernel<<<NB * NC, 256>>>(style,   stS);

    // 2) transposed splits: content normalized; style normalized + raw pair
    dim3 gt(NHW / 32, NC / 32, NB);
    tsplit_kernel<1><<<gt, 256>>>(content, stC, nCTh, nCTl, nullptr, nullptr);
    tsplit_kernel<2><<<gt, 256>>>(style,   stS, nSTh, nSTl, sTh, sTl);

    // 3) folded weights: W1 = fw^T gw, Wo = o_w h_w; bias vectors
    dim3 gw64(NC / 64, NC / 64);
    small_gemm_split<1><<<gw64, 256>>>(f_w, g_w, W1h, W1l);
    small_gemm_split<0><<<gw64, 256>>>(o_w, h_w, Woh, Wol);
    vb_kernel<<<NC / 256, 256>>>(f_b, g_w, vb);
    vrow_kernel<<<dim3(NHW / 256, NB), 256>>>(style, stS, vb, v);
    ob2_kernel<<<NC / 256, 256>>>(o_w, h_b, o_b, ob2);

    // 4) WoS[s,c] = sum_j sT[s,j] * Wo[c,j]   (M=4096, N=512, K=512), fp32 out
    dim3 gW(NC / 128, NHW / 256, NB);       // (4, 16, 4)
    mma_gemm<0><<<gW, 512, DSMEM0>>>(sTh, sTl, Woh, Wol, WoS, nullptr, nullptr,
                                     NHW, NC, NC, sQC, 0, sQC, nullptr, nullptr, 0);

    // 5) TT[s,i] = sum_j nST[s,j] * W1[i,j]   (M=4096, N=512, K=512)
    mma_gemm<1><<<gW, 512, DSMEM0>>>(nSTh, nSTl, W1h, W1l, nullptr, TTh, TTl,
                                     NHW, NC, NC, sQC, 0, sQC, nullptr, nullptr, 0);

    // 6) E[q,s] = sum_i nCT[q,i] * TT[s,i]   (M=4096, N=4096, K=512), fp32 out
    dim3 gE(NHW / 128, NHW / 256, NB);      // (32, 16, 4)
    mma_gemm<0><<<gE, 512, DSMEM0>>>(nCTh, nCTl, TTh, TTl, E, nullptr, nullptr,
                                     NHW, NHW, NC, sQC, sQC, sE, nullptr, nullptr, 0);

    // 7) softmax(E + v[s]) -> compact (s, w) lists
    dim3 gs(NHW, NB);
    softmax_compact_kernel<<<gs, 256>>>(E, v, lip, lwp, lcp);

    // 8) sparse apply: out[c,q] = ob2[c] + content[c,q] + sum w * WoS[s,c]
    dim3 ga(NHW / 32, NB);
    sparse_apply_kernel<<<ga, 256, 512 * 33 * 4>>>(WoS, lip, lwp, lcp, ob2, content, out);
}

// round 8
// speedup vs baseline: 5.2188x; 1.3388x over previous
#include <cuda_runtime.h>
#include <cuda_bf16.h>
#include <math.h>
#include <stdint.h>

constexpr int NB  = 4;
constexpr int NC  = 512;
constexpr int NHW = 4096;
constexpr int CAP = 1024;     // global list capacity per row
constexpr int CC  = 512;      // in-kernel candidate cap
#define EPSV 1e-5f

typedef __nv_bfloat16 bf16;

// ----------------------------- scratch (static; no allocation allowed) ----------
__device__ __align__(256) float  g_E[(size_t)NB * NHW * NHW];                 // 256MB
__device__ __align__(256) float  g_v[NB * NHW];
__device__ __align__(256) float  g_vb[NC];
__device__ __align__(256) float  g_ob2[NC];
__device__ __align__(256) float2 g_statC[NB * NC];
__device__ __align__(256) float2 g_statS[NB * NC];
__device__ __align__(256) bf16   g_nCT_h[(size_t)NB * NHW * NC];              // 16MB
__device__ __align__(256) float  g_nCT_f[(size_t)NB * NHW * NC];              // 32MB
__device__ __align__(256) bf16   g_nST_h[(size_t)NB * NHW * NC], g_nST_l[(size_t)NB * NHW * NC];
__device__ __align__(256) bf16   g_sT_h [(size_t)NB * NHW * NC], g_sT_l [(size_t)NB * NHW * NC];
__device__ __align__(256) bf16   g_TT_h [(size_t)NB * NHW * NC];              // 16MB
__device__ __align__(256) float  g_TT_f [(size_t)NB * NHW * NC];              // 32MB
__device__ __align__(256) float  g_WoS  [(size_t)NB * NHW * NC];              // 32MB
__device__ __align__(256) ushort g_lidx [(size_t)NB * NHW * CAP];             // 32MB
__device__ __align__(256) float  g_lw   [(size_t)NB * NHW * CAP];             // 64MB
__device__ __align__(256) int    g_lcnt [NB * NHW];
__device__ __align__(256) bf16   g_W1_h[NC * NC], g_W1_l[NC * NC];
__device__ __align__(256) bf16   g_Wo_h[NC * NC], g_Wo_l[NC * NC];

// ----------------------------- PTX helpers --------------------------------------
__device__ __forceinline__ uint32_t s2u(const void* p) {
    uint32_t a;
    asm("{ .reg .u64 t; cvta.to.shared.u64 t, %1; cvt.u32.u64 %0, t; }" : "=r"(a) : "l"(p));
    return a;
}
__device__ __forceinline__ void cpa16(uint32_t s, const void* g) {
    asm volatile("cp.async.cg.shared.global [%0], [%1], 16;" :: "r"(s), "l"(g));
}
__device__ __forceinline__ void cpa_commit() {
    asm volatile("cp.async.commit_group;" ::: "memory");
}
__device__ __forceinline__ void cpa_wait1() {
    asm volatile("cp.async.wait_group 1;" ::: "memory");
}
__device__ __forceinline__ void ldsm4(uint32_t a, uint32_t& r0, uint32_t& r1,
                                      uint32_t& r2, uint32_t& r3) {
    asm volatile("ldmatrix.sync.aligned.m8n8.x4.shared.b16 {%0,%1,%2,%3}, [%4];"
                 : "=r"(r0), "=r"(r1), "=r"(r2), "=r"(r3) : "r"(a));
}
__device__ __forceinline__ void mma_bf16(float* d, uint32_t a0, uint32_t a1, uint32_t a2,
                                         uint32_t a3, uint32_t b0, uint32_t b1) {
    asm volatile("mma.sync.aligned.m16n8k16.row.col.f32.bf16.bf16.f32 "
                 "{%0,%1,%2,%3}, {%4,%5,%6,%7}, {%8,%9}, {%0,%1,%2,%3};"
                 : "+f"(d[0]), "+f"(d[1]), "+f"(d[2]), "+f"(d[3])
                 : "r"(a0), "r"(a1), "r"(a2), "r"(a3), "r"(b0), "r"(b1));
}
__device__ __forceinline__ void split2(float v, ushort& h, ushort& l) {
    bf16 hb = __float2bfloat16(v);
    bf16 lb = __float2bfloat16(v - __bfloat162float(hb));
    h = __bfloat16_as_ushort(hb);
    l = __bfloat16_as_ushort(lb);
}

// ----------------------------- reductions ---------------------------------------
__device__ __forceinline__ float2 block_reduce_sum2(float s, float s2) {
    __shared__ float2 sh[8];
    int lane = threadIdx.x & 31, w = threadIdx.x >> 5;
    #pragma unroll
    for (int o = 16; o > 0; o >>= 1) {
        s  += __shfl_down_sync(0xffffffffu, s, o);
        s2 += __shfl_down_sync(0xffffffffu, s2, o);
    }
    if (lane == 0) sh[w] = make_float2(s, s2);
    __syncthreads();
    if (w == 0) {
        float2 v = (lane < 8) ? sh[lane] : make_float2(0.f, 0.f);
        #pragma unroll
        for (int o = 4; o > 0; o >>= 1) {
            v.x += __shfl_down_sync(0xffffffffu, v.x, o);
            v.y += __shfl_down_sync(0xffffffffu, v.y, o);
        }
        if (lane == 0) sh[0] = v;
    }
    __syncthreads();
    return sh[0];
}
__device__ __forceinline__ float block_reduce_max(float v) {
    __shared__ float sh[8];
    int lane = threadIdx.x & 31, w = threadIdx.x >> 5;
    #pragma unroll
    for (int o = 16; o > 0; o >>= 1) v = fmaxf(v, __shfl_down_sync(0xffffffffu, v, o));
    if (lane == 0) sh[w] = v;
    __syncthreads();
    if (w == 0) {
        float t = (lane < 8) ? sh[lane] : -3.4e38f;
        #pragma unroll
        for (int o = 4; o > 0; o >>= 1) t = fmaxf(t, __shfl_down_sync(0xffffffffu, t, o));
        if (lane == 0) sh[0] = t;
    }
    __syncthreads();
    return sh[0];
}
__device__ __forceinline__ float block_reduce_sum(float v) {
    __shared__ float sh[8];
    int lane = threadIdx.x & 31, w = threadIdx.x >> 5;
    #pragma unroll
    for (int o = 16; o > 0; o >>= 1) v += __shfl_down_sync(0xffffffffu, v, o);
    if (lane == 0) sh[w] = v;
    __syncthreads();
    if (w == 0) {
        float t = (lane < 8) ? sh[lane] : 0.f;
        #pragma unroll
        for (int o = 4; o > 0; o >>= 1) t += __shfl_down_sync(0xffffffffu, t, o);
        if (lane == 0) sh[0] = t;
    }
    __syncthreads();
    return sh[0];
}

// ----------------------------- stats: per (b,c) mean/rstd ------------------------
__global__ __launch_bounds__(256) void stats_kernel(const float* __restrict__ x,
                                                    float2* __restrict__ st) {
    size_t row = blockIdx.x;
    const float4* xp = (const float4*)(x + row * NHW);
    float s = 0.f, s2 = 0.f;
    #pragma unroll
    for (int i = 0; i < 4; i++) {
        float4 v = xp[threadIdx.x + i * 256];
        s  += v.x + v.y + v.z + v.w;
        s2 += v.x * v.x + v.y * v.y + v.z * v.z + v.w * v.w;
    }
    float2 r = block_reduce_sum2(s, s2);
    if (threadIdx.x == 0) {
        float mean = r.x * (1.f / NHW);
        float var  = r.y * (1.f / NHW) - mean * mean;
        st[row] = make_float2(mean, rsqrtf(var + EPSV));
    }
}

// ---------------- content transpose + norm: bf16 hi + fp32 ------------------------
__global__ __launch_bounds__(256) void tsplit_c_kernel(
    const float* __restrict__ x, const float2* __restrict__ st,
    bf16* __restrict__ nh, float* __restrict__ nf)
{
    __shared__ float tile[32][33];
    int b  = blockIdx.z;
    int c0 = blockIdx.y * 32, q0 = blockIdx.x * 32;
    int tx = threadIdx.x & 31, ty = threadIdx.x >> 5;
    const float* xb = x + (size_t)b * NC * NHW;
    #pragma unroll
    for (int i = 0; i < 4; i++) {
        int cc = ty + 8 * i;
        tile[cc][tx] = xb[(size_t)(c0 + cc) * NHW + q0 + tx];
    }
    __syncthreads();
    int c = c0 + tx;
    float2 s = st[b * NC + c];
    #pragma unroll
    for (int i = 0; i < 4; i++) {
        int qq = ty + 8 * i;
        float v = tile[tx][qq];
        size_t o = (size_t)b * NHW * NC + (size_t)(q0 + qq) * NC + c;
        float nv = (v - s.x) * s.y;
        nh[o] = __float2bfloat16(nv);
        nf[o] = nv;
    }
}

// ---------------- style transpose: norm hi/lo + raw hi/lo -------------------------
__global__ __launch_bounds__(256) void tsplit_s_kernel(
    const float* __restrict__ x, const float2* __restrict__ st,
    bf16* __restrict__ nh, bf16* __restrict__ nl,
    bf16* __restrict__ rh, bf16* __restrict__ rl)
{
    __shared__ float tile[32][33];
    int b  = blockIdx.z;
    int c0 = blockIdx.y * 32, q0 = blockIdx.x * 32;
    int tx = threadIdx.x & 31, ty = threadIdx.x >> 5;
    const float* xb = x + (size_t)b * NC * NHW;
    #pragma unroll
    for (int i = 0; i < 4; i++) {
        int cc = ty + 8 * i;
        tile[cc][tx] = xb[(size_t)(c0 + cc) * NHW + q0 + tx];
    }
    __syncthreads();
    int c = c0 + tx;
    float2 s = st[b * NC + c];
    #pragma unroll
    for (int i = 0; i < 4; i++) {
        int qq = ty + 8 * i;
        float v = tile[tx][qq];
        size_t o = (size_t)b * NHW * NC + (size_t)(q0 + qq) * NC + c;
        float nv = (v - s.x) * s.y;
        ushort h, l;
        split2(nv, h, l);
        nh[o] = __ushort_as_bfloat16(h);
        nl[o] = __ushort_as_bfloat16(l);
        split2(v, h, l);
        rh[o] = __ushort_as_bfloat16(h);
        rl[o] = __ushort_as_bfloat16(l);
    }
}

// ---------------- small fp32 GEMM (512x512x512) -> bf16 split --------------------
template <int TA>
__global__ __launch_bounds__(256) void small_gemm_split(
    const float* __restrict__ A, const float* __restrict__ B,
    bf16* __restrict__ Dh, bf16* __restrict__ Dl)
{
    __shared__ float As[32][65];
    __shared__ float Bs[32][65];
    const int tid = threadIdx.x;
    const int i0 = blockIdx.y * 64, j0 = blockIdx.x * 64;
    const int ty = tid >> 4, tx = tid & 15;
    float acc[4][4] = {};
    for (int kc = 0; kc < NC; kc += 32) {
        if (TA) {
            int ii = tid & 63, kk = tid >> 6;
            #pragma unroll
            for (int p = 0; p < 8; p++)
                As[kk + 4 * p][ii] = A[(size_t)(kc + kk + 4 * p) * NC + i0 + ii];
        } else {
            int kk = tid & 31, ib = tid >> 5;
            #pragma unroll
            for (int p = 0; p < 8; p++)
                As[kk][ib + 8 * p] = A[(size_t)(i0 + ib + 8 * p) * NC + kc + kk];
        }
        {
            int jj = tid & 63, kk = tid >> 6;
            #pragma unroll
            for (int p = 0; p < 8; p++)
                Bs[kk + 4 * p][jj] = B[(size_t)(kc + kk + 4 * p) * NC + j0 + jj];
        }
        __syncthreads();
        #pragma unroll
        for (int k = 0; k < 32; k++) {
            float a[4], bv[4];
            #pragma unroll
            for (int u = 0; u < 4; u++) a[u]  = As[k][ty * 4 + u];
            #pragma unroll
            for (int u = 0; u < 4; u++) bv[u] = Bs[k][tx * 4 + u];
            #pragma unroll
            for (int u = 0; u < 4; u++)
                #pragma unroll
                for (int w = 0; w < 4; w++) acc[u][w] = fmaf(a[u], bv[w], acc[u][w]);
        }
        __syncthreads();
    }
    #pragma unroll
    for (int u = 0; u < 4; u++)
        #pragma unroll
        for (int w = 0; w < 4; w++) {
            size_t o = (size_t)(i0 + ty * 4 + u) * NC + j0 + tx * 4 + w;
            ushort h, l;
            split2(acc[u][w], h, l);
            Dh[o] = __ushort_as_bfloat16(h);
            Dl[o] = __ushort_as_bfloat16(l);
        }
}

// ---------------- vb[j] = sum_c fb[c]*gw[c,j] ------------------------------------
__global__ __launch_bounds__(256) void vb_kernel(const float* __restrict__ fb,
                                                 const float* __restrict__ gw,
                                                 float* __restrict__ vb) {
    int j = blockIdx.x * 256 + threadIdx.x;
    float s = 0.f;
    for (int c = 0; c < NC; c++) s = fmaf(fb[c], gw[(size_t)c * NC + j], s);
    vb[j] = s;
}

// ---------------- v[b,s] = sum_j vb[j]*(style[b,j,s]-mean)*rstd -------------------
__global__ __launch_bounds__(256) void vrow_kernel(const float* __restrict__ style,
                                                   const float2* __restrict__ st,
                                                   const float* __restrict__ vb,
                                                   float* __restrict__ v) {
    int b = blockIdx.y;
    int s = blockIdx.x * 256 + threadIdx.x;
    const float* sb = style + (size_t)b * NC * NHW;
    float acc = 0.f;
    for (int j = 0; j < NC; j++) {
        float2 m = st[b * NC + j];
        acc = fmaf(vb[j], (sb[(size_t)j * NHW + s] - m.x) * m.y, acc);
    }
    v[b * NHW + s] = acc;
}

// ---------------- ob2[c] = sum_m o_w[c,m]*h_b[m] + o_b[c] ------------------------
__global__ __launch_bounds__(256) void ob2_kernel(const float* __restrict__ ow,
                                                  const float* __restrict__ hb,
                                                  const float* __restrict__ ob,
                                                  float* __restrict__ ob2) {
    int c = blockIdx.x * 256 + threadIdx.x;
    float s = ob[c];
    for (int m = 0; m < NC; m++) s = fmaf(ow[(size_t)c * NC + m], hb[m], s);
    ob2[c] = s;
}

// ---------------- sparse softmax with exact candidate recompute ------------------
// E is a 1-MMA bf16 approximation (abs err ~0.04, 3sig ~0.11). Candidates =
// entries above approx-max - 16.3. Exact E recomputed via fp32 dot nCf . TTf.
__global__ __launch_bounds__(256) void softmax_sparse_kernel(
    const float* __restrict__ E, const float* __restrict__ vrow,
    const float* __restrict__ nCf, const float* __restrict__ TTf,
    ushort* __restrict__ lidx, float* __restrict__ lw, int* __restrict__ lcnt)
{
    __shared__ float  s_nc[NC];
    __shared__ ushort s_idx[CC];
    __shared__ float  s_ex[CC];
    __shared__ int    wsum[8], wbase[8], s_n;
    const int b = blockIdx.y, q = blockIdx.x;
    const size_t rowid = (size_t)b * NHW + q;
    const size_t base  = rowid * NHW;
    const int tid = threadIdx.x, lane = tid & 31, w = tid >> 5;

    // load E row + v, find approx max
    const float4* p  = (const float4*)(E + base);
    const float4* vp = (const float4*)(vrow + (size_t)b * NHW);
    float4 v[4];
    float mx = -3.4e38f;
    #pragma unroll
    for (int i = 0; i < 4; i++) {
        v[i] = p[tid + i * 256];
        float4 vv = vp[tid + i * 256];
        v[i].x += vv.x; v[i].y += vv.y; v[i].z += vv.z; v[i].w += vv.w;
        mx = fmaxf(mx, fmaxf(fmaxf(v[i].x, v[i].y), fmaxf(v[i].z, v[i].w)));
    }
    const float mxa = block_reduce_max(mx);
    const float T = mxa - 16.3f;

    // load content row (fp32) into smem
    const float2* ncp = (const float2*)(nCf + rowid * NC);
    *(float2*)&s_nc[tid * 2] = ncp[tid];

    // candidate count + deterministic scan
    int cnt = 0;
    #pragma unroll
    for (int i = 0; i < 4; i++)
        cnt += (v[i].x > T) + (v[i].y > T) + (v[i].z > T) + (v[i].w > T);
    int incl = cnt;
    #pragma unroll
    for (int o = 1; o < 32; o <<= 1) {
        int n = __shfl_up_sync(0xffffffffu, incl, o);
        if (lane >= o) incl += n;
    }
    if (lane == 31) wsum[w] = incl;
    __syncthreads();
    if (tid == 0) {
        int r = 0;
        #pragma unroll
        for (int i = 0; i < 8; i++) { wbase[i] = r; r += wsum[i]; }
        s_n = (r < CC) ? r : CC;
    }
    __syncthreads();
    const int ncand = s_n;
    int k = wbase[w] + incl - cnt;

    // non-candidate approx exp-sum; record candidate indices
    float sn = 0.f;
    #pragma unroll
    for (int i = 0; i < 4; i++) {
        int s4 = 4 * (tid + i * 256);
        float c4[4] = {v[i].x, v[i].y, v[i].z, v[i].w};
        #pragma unroll
        for (int c = 0; c < 4; c++) {
            if (c4[c] > T) {
                if (k < CC) s_idx[k] = (ushort)(s4 + c);
                k++;
            } else {
                sn += __expf(c4[c] - mxa);
            }
        }
    }
    const float Snon = block_reduce_sum(sn);   // includes __syncthreads barriers

    // exact recompute: one warp per candidate
    for (int c = w; c < ncand; c += 8) {
        const int sidx = s_idx[c];
        const float4* tt = (const float4*)(TTf + ((size_t)b * NHW + sidx) * NC);
        float acc = 0.f;
        #pragma unroll
        for (int u = 0; u < 4; u++) {
            float4 t4 = tt[lane + 32 * u];
            const int o = (lane + 32 * u) * 4;
            acc = fmaf(t4.x, s_nc[o], acc);
            acc = fmaf(t4.y, s_nc[o + 1], acc);
            acc = fmaf(t4.z, s_nc[o + 2], acc);
            acc = fmaf(t4.w, s_nc[o + 3], acc);
        }
        #pragma unroll
        for (int o = 16; o > 0; o >>= 1) acc += __shfl_down_sync(0xffffffffu, acc, o);
        if (lane == 0) s_ex[c] = acc + vrow[(size_t)b * NHW + sidx];
    }
    __syncthreads();

    // denominator: non-candidates (approx) + candidates (exact)
    float cs = 0.f;
    for (int c = tid; c < ncand; c += 256) cs += __expf(s_ex[c] - mxa);
    const float Scand = block_reduce_sum(cs);
    const float inv = 1.0f / (Snon + Scand);

    // emit all candidates
    ushort* ip = lidx + rowid * CAP;
    float*  wp = lw   + rowid * CAP;
    for (int c = tid; c < ncand; c += 256) {
        ip[c] = s_idx[c];
        wp[c] = __expf(s_ex[c] - mxa) * inv;
    }
    if (tid == 0) lcnt[rowid] = ncand;
}

// ---------------- sparse apply: out[c,q] = ob2 + content + sum_k w*WoS[s_k,c] ----
__global__ __launch_bounds__(256) void sparse_apply_kernel(
    const float* __restrict__ WoS, const ushort* __restrict__ lidx,
    const float* __restrict__ lw, const int* __restrict__ lcnt,
    const float* __restrict__ ob2, const float* __restrict__ content,
    float* __restrict__ out)
{
    extern __shared__ float sacc[];   // [512][33]
    const int b = blockIdx.y, q0 = blockIdx.x * 32;
    const int tid = threadIdx.x, wid = tid >> 5, lane = tid & 31;
    const float* WoSb = WoS + (size_t)b * NHW * NC;

    #pragma unroll 1
    for (int j = 0; j < 4; j++) {
        const int q = q0 + wid * 4 + j;
        const size_t row = (size_t)b * NHW + q;
        const int cnt = lcnt[row];
        const ushort* ip = lidx + row * CAP;
        const float*  wp = lw   + row * CAP;
        float4 acc[4] = {};
        for (int k = 0; k < cnt; k++) {
            const int s = ip[k];
            const float wgt = wp[k];
            const float4* src = (const float4*)(WoSb + (size_t)s * NC) + lane;
            #pragma unroll
            for (int u = 0; u < 4; u++) {
                float4 vv = src[u * 32];
                acc[u].x = fmaf(wgt, vv.x, acc[u].x);
                acc[u].y = fmaf(wgt, vv.y, acc[u].y);
                acc[u].z = fmaf(wgt, vv.z, acc[u].z);
                acc[u].w = fmaf(wgt, vv.w, acc[u].w);
            }
        }
        const int qq = q - q0;
        #pragma unroll
        for (int u = 0; u < 4; u++) {
            const int c = lane * 4 + u * 128;
            sacc[(c + 0) * 33 + qq] = acc[u].x;
            sacc[(c + 1) * 33 + qq] = acc[u].y;
            sacc[(c + 2) * 33 + qq] = acc[u].z;
            sacc[(c + 3) * 33 + qq] = acc[u].w;
        }
    }
    __syncthreads();

    const float* cb = content + (size_t)b * NC * NHW;
    float* ob = out + (size_t)b * NC * NHW;
    #pragma unroll 1
    for (int p = 0; p < 16; p++) {
        const int c  = p * 32 + (tid >> 3);
        const int ch = (tid & 7) * 4;
        const float bias = ob2[c];
        float4 vv;
        vv.x = sacc[c * 33 + ch + 0] + bias;
        vv.y = sacc[c * 33 + ch + 1] + bias;
        vv.z = sacc[c * 33 + ch + 2] + bias;
        vv.w = sacc[c * 33 + ch + 3] + bias;
        const size_t o = (size_t)c * NHW + q0 + ch;
        const float4 cv = *(const float4*)(cb + o);
        vv.x += cv.x; vv.y += cv.y; vv.z += cv.z; vv.w += cv.w;
        *(float4*)(ob + o) = vv;
    }
}

// ---------------- 256x128x32 mma.sync GEMM ---------------------------------------
// NMMA 3: bf16 hi/lo 3-MMA split.  NMMA 1: single bf16 MMA (Ahi, Bhi only).
// SPLIT 0: C fp32 (+biasRow/+resid). SPLIT 1: C bf16 hi/lo. SPLIT 2: C bf16 hi + fp32.
constexpr int ATB = 16384;           // 256 rows x 64B component
constexpr int BTB = 8192;            // 128 rows x 64B component
constexpr int NSTG = 3;

__device__ __forceinline__ uint32_t swz(int r, int c) {
    return (uint32_t)(r * 64 + ((c ^ ((r >> 1) & 3)) << 4));
}

template <int NMMA, int SPLIT>
__global__ __launch_bounds__(512, 1) void mma_gemm(
    const bf16* __restrict__ Ahi, const bf16* __restrict__ Alo,
    const bf16* __restrict__ Bhi, const bf16* __restrict__ Blo,
    float* __restrict__ Cf, bf16* __restrict__ Chi, bf16* __restrict__ Clo,
    int M, int N, int K,
    long sA, long sB, long sC,
    const float* __restrict__ biasRow,
    const float* __restrict__ resid, long sR)
{
    constexpr int STGB   = (NMMA == 3) ? (2 * ATB + 2 * BTB) : (ATB + BTB);
    constexpr int OFF_BH = (NMMA == 3) ? 2 * ATB : ATB;

    extern __shared__ __align__(128) char dsm[];
    const uint32_t smb = s2u(dsm);

    const int tid = threadIdx.x, wid = tid >> 5, lane = tid & 31;
    const int m0 = blockIdx.y * 256, n0 = blockIdx.x * 128, b = blockIdx.z;
    const int warpM = wid & 3, warpN = wid >> 2;
    const int KT = K / 32;

    const int rA = tid >> 1, cA = (tid & 1) * 2;
    const int rB = tid >> 2, cB = tid & 3;
    const bf16* pAh = Ahi + (size_t)b * sA + (size_t)(m0 + rA) * K + cA * 8;
    const bf16* pAl = (NMMA == 3) ? Alo + (size_t)b * sA + (size_t)(m0 + rA) * K + cA * 8 : nullptr;
    const bf16* pBh = Bhi + (size_t)b * sB + (size_t)(n0 + rB) * K + cB * 8;
    const bf16* pBl = (NMMA == 3) ? Blo + (size_t)b * sB + (size_t)(n0 + rB) * K + cB * 8 : nullptr;
    const uint32_t dA0 = swz(rA, cA), dA1 = swz(rA, cA + 1);
    const uint32_t dB  = swz(rB, cB);

    auto load_stage = [&](int s, int k0) {
        const uint32_t sb = smb + s * STGB;
        cpa16(sb + dA0, pAh + k0);
        cpa16(sb + dA1, pAh + k0 + 8);
        if (NMMA == 3) {
            cpa16(sb + ATB + dA0, pAl + k0);
            cpa16(sb + ATB + dA1, pAl + k0 + 8);
        }
        cpa16(sb + OFF_BH + dB, pBh + k0);
        if (NMMA == 3) cpa16(sb + OFF_BH + BTB + dB, pBl + k0);
    };

    float acc[4][4][4];
    #pragma unroll
    for (int i = 0; i < 4; i++)
        #pragma unroll
        for (int j = 0; j < 4; j++)
            #pragma unroll
            for (int q = 0; q < 4; q++) acc[i][j][q] = 0.f;

    load_stage(0, 0);  cpa_commit();
    load_stage(1, 32); cpa_commit();

    const int arow = warpM * 64 + (lane & 15);
    const int brow = warpN * 32 + (lane & 15);

    for (int kt = 0; kt < KT; kt++) {
        cpa_wait1();
        __syncthreads();
        const int cur = kt % NSTG;
        if (kt + 2 < KT) load_stage((kt + 2) % NSTG, (kt + 2) * 32);
        cpa_commit();

        const uint32_t sAh = smb + cur * STGB;
        const uint32_t sAl = sAh + ATB;
        const uint32_t sBh = sAh + OFF_BH;
        const uint32_t sBl = sBh + BTB;

        #pragma unroll
        for (int kk = 0; kk < 2; kk++) {
            const int ch = kk * 2 + (lane >> 4);
            uint32_t ah[4][4], al[4][4];
            #pragma unroll
            for (int mi = 0; mi < 4; mi++) {
                uint32_t off = swz(arow + mi * 16, ch);
                ldsm4(sAh + off, ah[mi][0], ah[mi][1], ah[mi][2], ah[mi][3]);
                if (NMMA == 3)
                    ldsm4(sAl + off, al[mi][0], al[mi][1], al[mi][2], al[mi][3]);
            }
            #pragma unroll
            for (int g = 0; g < 2; g++) {
                uint32_t off = swz(brow + g * 16, ch);
                uint32_t h0, h1, h2, h3, l0, l1, l2, l3;
                ldsm4(sBh + off, h0, h1, h2, h3);
                if (NMMA == 3) ldsm4(sBl + off, l0, l1, l2, l3);
                #pragma unroll
                for (int mi = 0; mi < 4; mi++) {
                    mma_bf16(acc[mi][2 * g],     ah[mi][0], ah[mi][1], ah[mi][2], ah[mi][3], h0, h2);
                    mma_bf16(acc[mi][2 * g + 1], ah[mi][0], ah[mi][1], ah[mi][2], ah[mi][3], h1, h3);
                    if (NMMA == 3) {
                        mma_bf16(acc[mi][2 * g],     ah[mi][0], ah[mi][1], ah[mi][2], ah[mi][3], l0, l2);
                        mma_bf16(acc[mi][2 * g],     al[mi][0], al[mi][1], al[mi][2], al[mi][3], h0, h2);
                        mma_bf16(acc[mi][2 * g + 1], ah[mi][0], ah[mi][1], ah[mi][2], ah[mi][3], l1, l3);
                        mma_bf16(acc[mi][2 * g + 1], al[mi][0], al[mi][1], al[mi][2], al[mi][3], h1, h3);
                    }
                }
            }
        }
        __syncthreads();
    }

    // ---------------- epilogue -------------------------------------------------
    #pragma unroll
    for (int mi = 0; mi < 4; mi++) {
        const int r0 = m0 + warpM * 64 + mi * 16 + (lane >> 2);
        #pragma unroll
        for (int j = 0; j < 4; j++) {
            const int col = n0 + warpN * 32 + j * 8 + (lane & 3) * 2;
            float v[4] = {acc[mi][j][0], acc[mi][j][1], acc[mi][j][2], acc[mi][j][3]};
            if (biasRow) {
                float b0 = biasRow[r0], b1 = biasRow[r0 + 8];
                v[0] += b0; v[1] += b0; v[2] += b1; v[3] += b1;
            }
            const size_t o0 = (size_t)b * sC + (size_t)r0 * N + col;
            const size_t o1 = o0 + (size_t)8 * N;
            if (SPLIT == 1) {
                ushort h0, l0, h1, l1;
                split2(v[0], h0, l0); split2(v[1], h1, l1);
                *(uint32_t*)(Chi + o0) = (uint32_t)h0 | ((uint32_t)h1 << 16);
                *(uint32_t*)(Clo + o0) = (uint32_t)l0 | ((uint32_t)l1 << 16);
                split2(v[2], h0, l0); split2(v[3], h1, l1);
                *(uint32_t*)(Chi + o1) = (uint32_t)h0 | ((uint32_t)h1 << 16);
                *(uint32_t*)(Clo + o1) = (uint32_t)l0 | ((uint32_t)l1 << 16);
            } else if (SPLIT == 2) {
                ushort h0 = __bfloat16_as_ushort(__float2bfloat16(v[0]));
                ushort h1 = __bfloat16_as_ushort(__float2bfloat16(v[1]));
                *(uint32_t*)(Chi + o0) = (uint32_t)h0 | ((uint32_t)h1 << 16);
                h0 = __bfloat16_as_ushort(__float2bfloat16(v[2]));
                h1 = __bfloat16_as_ushort(__float2bfloat16(v[3]));
                *(uint32_t*)(Chi + o1) = (uint32_t)h0 | ((uint32_t)h1 << 16);
                *(float2*)(Cf + o0) = make_float2(v[0], v[1]);
                *(float2*)(Cf + o1) = make_float2(v[2], v[3]);
            } else {
                if (resid) {
                    const float* rp = resid + (size_t)b * sR;
                    float2 r0v = *(const float2*)(rp + (size_t)r0 * N + col);
                    float2 r1v = *(const float2*)(rp + (size_t)(r0 + 8) * N + col);
                    v[0] += r0v.x; v[1] += r0v.y; v[2] += r1v.x; v[3] += r1v.y;
                }
                *(float2*)(Cf + o0) = make_float2(v[0], v[1]);
                *(float2*)(Cf + o1) = make_float2(v[2], v[3]);
            }
        }
    }
}

constexpr int DSMEM3 = NSTG * (2 * ATB + 2 * BTB);  // 144 KB
constexpr int DSMEM1 = NSTG * (ATB + BTB);          // 72 KB

// ----------------------------- launch --------------------------------------------
extern "C" void kernel_launch(void* const* d_in, const int* in_sizes, int n_in,
                              void* d_out, int out_size) {
    const float* content = (const float*)d_in[0];
    const float* style   = (const float*)d_in[1];
    const float* f_w = (const float*)d_in[2];
    const float* f_b = (const float*)d_in[3];
    const float* g_w = (const float*)d_in[4];
    const float* h_w = (const float*)d_in[6];
    const float* h_b = (const float*)d_in[7];
    const float* o_w = (const float*)d_in[8];
    const float* o_b = (const float*)d_in[9];
    float* out = (float*)d_out;

    float *E, *v, *vb, *ob2, *WoS, *lwp, *nCf, *TTf; float2 *stC, *stS;
    bf16 *nCTh,*nSTh,*nSTl,*sTh,*sTl,*TTh,*W1h,*W1l,*Woh,*Wol;
    ushort *lip; int *lcp;
    cudaGetSymbolAddress((void**)&E,   g_E);
    cudaGetSymbolAddress((void**)&v,   g_v);
    cudaGetSymbolAddress((void**)&vb,  g_vb);
    cudaGetSymbolAddress((void**)&ob2, g_ob2);
    cudaGetSymbolAddress((void**)&WoS, g_WoS);
    cudaGetSymbolAddress((void**)&stC, g_statC);
    cudaGetSymbolAddress((void**)&stS, g_statS);
    cudaGetSymbolAddress((void**)&nCTh, g_nCT_h);
    cudaGetSymbolAddress((void**)&nCf,  g_nCT_f);
    cudaGetSymbolAddress((void**)&nSTh, g_nST_h); cudaGetSymbolAddress((void**)&nSTl, g_nST_l);
    cudaGetSymbolAddress((void**)&sTh,  g_sT_h);  cudaGetSymbolAddress((void**)&sTl,  g_sT_l);
    cudaGetSymbolAddress((void**)&TTh,  g_TT_h);
    cudaGetSymbolAddress((void**)&TTf,  g_TT_f);
    cudaGetSymbolAddress((void**)&W1h,  g_W1_h);  cudaGetSymbolAddress((void**)&W1l,  g_W1_l);
    cudaGetSymbolAddress((void**)&Woh,  g_Wo_h);  cudaGetSymbolAddress((void**)&Wol,  g_Wo_l);
    cudaGetSymbolAddress((void**)&lip,  g_lidx);
    cudaGetSymbolAddress((void**)&lwp,  g_lw);
    cudaGetSymbolAddress((void**)&lcp,  g_lcnt);

    cudaFuncSetAttribute(mma_gemm<3,0>, cudaFuncAttributeMaxDynamicSharedMemorySize, DSMEM3);
    cudaFuncSetAttribute(mma_gemm<3,2>, cudaFuncAttributeMaxDynamicSharedMemorySize, DSMEM3);
    cudaFuncSetAttribute(mma_gemm<1,0>, cudaFuncAttributeMaxDynamicSharedMemorySize, DSMEM1);
    cudaFuncSetAttribute(sparse_apply_kernel, cudaFuncAttributeMaxDynamicSharedMemorySize, 512 * 33 * 4);

    const long sQC = (long)NHW * NC;   // [B, 4096, 512]
    const long sE  = (long)NHW * NHW;

    // 1) stats
    stats_kernel<<<NB * NC, 256>>>(content, stC);
    stats_kernel<<<NB * NC, 256>>>(style,   stS);

    // 2) transposed operands
    dim3 gt(NHW / 32, NC / 32, NB);
    tsplit_c_kernel<<<gt, 256>>>(content, stC, nCTh, nCf);
    tsplit_s_kernel<<<gt, 256>>>(style,   stS, nSTh, nSTl, sTh, sTl);

    // 3) folded weights: W1 = fw^T gw, Wo = o_w h_w; bias vectors
    dim3 gw64(NC / 64, NC / 64);
    small_gemm_split<1><<<gw64, 256>>>(f_w, g_w, W1h, W1l);
    small_gemm_split<0><<<gw64, 256>>>(o_w, h_w, Woh, Wol);
    vb_kernel<<<NC / 256, 256>>>(f_b, g_w, vb);
    vrow_kernel<<<dim3(NHW / 256, NB), 256>>>(style, stS, vb, v);
    ob2_kernel<<<NC / 256, 256>>>(o_w, h_b, o_b, ob2);

    // 4) WoS[s,c] = sum_j sT[s,j] * Wo[c,j]   (M=4096, N=512, K=512), fp32 out
    dim3 gW(NC / 128, NHW / 256, NB);       // (4, 16, 4)
    mma_gemm<3,0><<<gW, 512, DSMEM3>>>(sTh, sTl, Woh, Wol, WoS, nullptr, nullptr,
                                       NHW, NC, NC, sQC, 0, sQC, nullptr, nullptr, 0);

    // 5) TT[s,i] = sum_j nST[s,j] * W1[i,j]   (M=4096, N=512, K=512), bf16-hi + fp32
    mma_gemm<3,2><<<gW, 512, DSMEM3>>>(nSTh, nSTl, W1h, W1l, TTf, TTh, nullptr,
                                       NHW, NC, NC, sQC, 0, sQC, nullptr, nullptr, 0);

    // 6) E approx[q,s] = sum_i nCT_h[q,i] * TT_h[s,i]  (1-MMA bf16), fp32 out
    dim3 gE(NHW / 128, NHW / 256, NB);      // (32, 16, 4)
    mma_gemm<1,0><<<gE, 512, DSMEM1>>>(nCTh, nullptr, TTh, nullptr, E, nullptr, nullptr,
                                       NHW, NHW, NC, sQC, sQC, sE, nullptr, nullptr, 0);

    // 7) sparse softmax: candidates from approx E, exact fp32 recompute
    dim3 gs(NHW, NB);
    softmax_sparse_kernel<<<gs, 256>>>(E, v, nCf, TTf, lip, lwp, lcp);

    // 8) sparse apply: out[c,q] = ob2[c] + content[c,q] + sum w * WoS[s,c]
    dim3 ga(NHW / 32, NB);
    sparse_apply_kernel<<<ga, 256, 512 * 33 * 4>>>(WoS, lip, lwp, lcp, ob2, content, out);
}

// round 9
// speedup vs baseline: 5.2397x; 1.0040x over previous
#include <cuda_runtime.h>
#include <cuda_bf16.h>
#include <math.h>
#include <stdint.h>

constexpr int NB  = 4;
constexpr int NC  = 512;
constexpr int NHW = 4096;
constexpr int CAP = 1024;     // global list capacity per row
constexpr int CC  = 512;      // in-kernel candidate cap
#define EPSV 1e-5f

typedef __nv_bfloat16 bf16;

// ----------------------------- scratch (static; no allocation allowed) ----------
__device__ __align__(256) bf16   g_E[(size_t)NB * NHW * NHW];                 // 128MB
__device__ __align__(256) float  g_v[NB * NHW];
__device__ __align__(256) float  g_vb[NC];
__device__ __align__(256) float  g_ob2[NC];
__device__ __align__(256) float2 g_statC[NB * NC];
__device__ __align__(256) float2 g_statS[NB * NC];
__device__ __align__(256) bf16   g_nCT_h[(size_t)NB * NHW * NC];              // 16MB
__device__ __align__(256) float  g_nCT_f[(size_t)NB * NHW * NC];              // 32MB
__device__ __align__(256) bf16   g_nST_h[(size_t)NB * NHW * NC], g_nST_l[(size_t)NB * NHW * NC];
__device__ __align__(256) bf16   g_sT_h [(size_t)NB * NHW * NC], g_sT_l [(size_t)NB * NHW * NC];
__device__ __align__(256) bf16   g_TT_h [(size_t)NB * NHW * NC];              // 16MB
__device__ __align__(256) float  g_TT_f [(size_t)NB * NHW * NC];              // 32MB
__device__ __align__(256) float  g_WoS  [(size_t)NB * NHW * NC];              // 32MB
__device__ __align__(256) ushort g_lidx [(size_t)NB * NHW * CAP];             // 32MB
__device__ __align__(256) float  g_lw   [(size_t)NB * NHW * CAP];             // 64MB
__device__ __align__(256) int    g_lcnt [NB * NHW];
__device__ __align__(256) bf16   g_W1_h[NC * NC], g_W1_l[NC * NC];
__device__ __align__(256) bf16   g_Wo_h[NC * NC], g_Wo_l[NC * NC];

// ----------------------------- PTX helpers --------------------------------------
__device__ __forceinline__ uint32_t s2u(const void* p) {
    uint32_t a;
    asm("{ .reg .u64 t; cvta.to.shared.u64 t, %1; cvt.u32.u64 %0, t; }" : "=r"(a) : "l"(p));
    return a;
}
__device__ __forceinline__ void cpa16(uint32_t s, const void* g) {
    asm volatile("cp.async.cg.shared.global [%0], [%1], 16;" :: "r"(s), "l"(g));
}
__device__ __forceinline__ void cpa_commit() {
    asm volatile("cp.async.commit_group;" ::: "memory");
}
__device__ __forceinline__ void cpa_wait1() {
    asm volatile("cp.async.wait_group 1;" ::: "memory");
}
__device__ __forceinline__ void ldsm4(uint32_t a, uint32_t& r0, uint32_t& r1,
                                      uint32_t& r2, uint32_t& r3) {
    asm volatile("ldmatrix.sync.aligned.m8n8.x4.shared.b16 {%0,%1,%2,%3}, [%4];"
                 : "=r"(r0), "=r"(r1), "=r"(r2), "=r"(r3) : "r"(a));
}
__device__ __forceinline__ void mma_bf16(float* d, uint32_t a0, uint32_t a1, uint32_t a2,
                                         uint32_t a3, uint32_t b0, uint32_t b1) {
    asm volatile("mma.sync.aligned.m16n8k16.row.col.f32.bf16.bf16.f32 "
                 "{%0,%1,%2,%3}, {%4,%5,%6,%7}, {%8,%9}, {%0,%1,%2,%3};"
                 : "+f"(d[0]), "+f"(d[1]), "+f"(d[2]), "+f"(d[3])
                 : "r"(a0), "r"(a1), "r"(a2), "r"(a3), "r"(b0), "r"(b1));
}
__device__ __forceinline__ void split2(float v, ushort& h, ushort& l) {
    bf16 hb = __float2bfloat16(v);
    bf16 lb = __float2bfloat16(v - __bfloat162float(hb));
    h = __bfloat16_as_ushort(hb);
    l = __bfloat16_as_ushort(lb);
}

// ----------------------------- reductions ---------------------------------------
__device__ __forceinline__ float2 block_reduce_sum2(float s, float s2) {
    __shared__ float2 sh[8];
    int lane = threadIdx.x & 31, w = threadIdx.x >> 5;
    #pragma unroll
    for (int o = 16; o > 0; o >>= 1) {
        s  += __shfl_down_sync(0xffffffffu, s, o);
        s2 += __shfl_down_sync(0xffffffffu, s2, o);
    }
    if (lane == 0) sh[w] = make_float2(s, s2);
    __syncthreads();
    if (w == 0) {
        float2 v = (lane < 8) ? sh[lane] : make_float2(0.f, 0.f);
        #pragma unroll
        for (int o = 4; o > 0; o >>= 1) {
            v.x += __shfl_down_sync(0xffffffffu, v.x, o);
            v.y += __shfl_down_sync(0xffffffffu, v.y, o);
        }
        if (lane == 0) sh[0] = v;
    }
    __syncthreads();
    return sh[0];
}
__device__ __forceinline__ float block_reduce_max(float v) {
    __shared__ float sh[8];
    int lane = threadIdx.x & 31, w = threadIdx.x >> 5;
    #pragma unroll
    for (int o = 16; o > 0; o >>= 1) v = fmaxf(v, __shfl_down_sync(0xffffffffu, v, o));
    if (lane == 0) sh[w] = v;
    __syncthreads();
    if (w == 0) {
        float t = (lane < 8) ? sh[lane] : -3.4e38f;
        #pragma unroll
        for (int o = 4; o > 0; o >>= 1) t = fmaxf(t, __shfl_down_sync(0xffffffffu, t, o));
        if (lane == 0) sh[0] = t;
    }
    __syncthreads();
    return sh[0];
}
__device__ __forceinline__ float block_reduce_sum(float v) {
    __shared__ float sh[8];
    int lane = threadIdx.x & 31, w = threadIdx.x >> 5;
    #pragma unroll
    for (int o = 16; o > 0; o >>= 1) v += __shfl_down_sync(0xffffffffu, v, o);
    if (lane == 0) sh[w] = v;
    __syncthreads();
    if (w == 0) {
        float t = (lane < 8) ? sh[lane] : 0.f;
        #pragma unroll
        for (int o = 4; o > 0; o >>= 1) t += __shfl_down_sync(0xffffffffu, t, o);
        if (lane == 0) sh[0] = t;
    }
    __syncthreads();
    return sh[0];
}

// ----------------------------- stats: per (b,c) mean/rstd ------------------------
__global__ __launch_bounds__(256) void stats_kernel(const float* __restrict__ x,
                                                    float2* __restrict__ st) {
    size_t row = blockIdx.x;
    const float4* xp = (const float4*)(x + row * NHW);
    float s = 0.f, s2 = 0.f;
    #pragma unroll
    for (int i = 0; i < 4; i++) {
        float4 v = xp[threadIdx.x + i * 256];
        s  += v.x + v.y + v.z + v.w;
        s2 += v.x * v.x + v.y * v.y + v.z * v.z + v.w * v.w;
    }
    float2 r = block_reduce_sum2(s, s2);
    if (threadIdx.x == 0) {
        float mean = r.x * (1.f / NHW);
        float var  = r.y * (1.f / NHW) - mean * mean;
        st[row] = make_float2(mean, rsqrtf(var + EPSV));
    }
}

// ---------------- content transpose + norm: bf16 hi + fp32 ------------------------
__global__ __launch_bounds__(256) void tsplit_c_kernel(
    const float* __restrict__ x, const float2* __restrict__ st,
    bf16* __restrict__ nh, float* __restrict__ nf)
{
    __shared__ float tile[32][33];
    int b  = blockIdx.z;
    int c0 = blockIdx.y * 32, q0 = blockIdx.x * 32;
    int tx = threadIdx.x & 31, ty = threadIdx.x >> 5;
    const float* xb = x + (size_t)b * NC * NHW;
    #pragma unroll
    for (int i = 0; i < 4; i++) {
        int cc = ty + 8 * i;
        tile[cc][tx] = xb[(size_t)(c0 + cc) * NHW + q0 + tx];
    }
    __syncthreads();
    int c = c0 + tx;
    float2 s = st[b * NC + c];
    #pragma unroll
    for (int i = 0; i < 4; i++) {
        int qq = ty + 8 * i;
        float v = tile[tx][qq];
        size_t o = (size_t)b * NHW * NC + (size_t)(q0 + qq) * NC + c;
        float nv = (v - s.x) * s.y;
        nh[o] = __float2bfloat16(nv);
        nf[o] = nv;
    }
}

// ---------------- style transpose: norm hi/lo + raw hi/lo -------------------------
__global__ __launch_bounds__(256) void tsplit_s_kernel(
    const float* __restrict__ x, const float2* __restrict__ st,
    bf16* __restrict__ nh, bf16* __restrict__ nl,
    bf16* __restrict__ rh, bf16* __restrict__ rl)
{
    __shared__ float tile[32][33];
    int b  = blockIdx.z;
    int c0 = blockIdx.y * 32, q0 = blockIdx.x * 32;
    int tx = threadIdx.x & 31, ty = threadIdx.x >> 5;
    const float* xb = x + (size_t)b * NC * NHW;
    #pragma unroll
    for (int i = 0; i < 4; i++) {
        int cc = ty + 8 * i;
        tile[cc][tx] = xb[(size_t)(c0 + cc) * NHW + q0 + tx];
    }
    __syncthreads();
    int c = c0 + tx;
    float2 s = st[b * NC + c];
    #pragma unroll
    for (int i = 0; i < 4; i++) {
        int qq = ty + 8 * i;
        float v = tile[tx][qq];
        size_t o = (size_t)b * NHW * NC + (size_t)(q0 + qq) * NC + c;
        float nv = (v - s.x) * s.y;
        ushort h, l;
        split2(nv, h, l);
        nh[o] = __ushort_as_bfloat16(h);
        nl[o] = __ushort_as_bfloat16(l);
        split2(v, h, l);
        rh[o] = __ushort_as_bfloat16(h);
        rl[o] = __ushort_as_bfloat16(l);
    }
}

// ---------------- small fp32 GEMM (512x512x512) -> bf16 split --------------------
template <int TA>
__global__ __launch_bounds__(256) void small_gemm_split(
    const float* __restrict__ A, const float* __restrict__ B,
    bf16* __restrict__ Dh, bf16* __restrict__ Dl)
{
    __shared__ float As[32][65];
    __shared__ float Bs[32][65];
    const int tid = threadIdx.x;
    const int i0 = blockIdx.y * 64, j0 = blockIdx.x * 64;
    const int ty = tid >> 4, tx = tid & 15;
    float acc[4][4] = {};
    for (int kc = 0; kc < NC; kc += 32) {
        if (TA) {
            int ii = tid & 63, kk = tid >> 6;
            #pragma unroll
            for (int p = 0; p < 8; p++)
                As[kk + 4 * p][ii] = A[(size_t)(kc + kk + 4 * p) * NC + i0 + ii];
        } else {
            int kk = tid & 31, ib = tid >> 5;
            #pragma unroll
            for (int p = 0; p < 8; p++)
                As[kk][ib + 8 * p] = A[(size_t)(i0 + ib + 8 * p) * NC + kc + kk];
        }
        {
            int jj = tid & 63, kk = tid >> 6;
            #pragma unroll
            for (int p = 0; p < 8; p++)
                Bs[kk + 4 * p][jj] = B[(size_t)(kc + kk + 4 * p) * NC + j0 + jj];
        }
        __syncthreads();
        #pragma unroll
        for (int k = 0; k < 32; k++) {
            float a[4], bv[4];
            #pragma unroll
            for (int u = 0; u < 4; u++) a[u]  = As[k][ty * 4 + u];
            #pragma unroll
            for (int u = 0; u < 4; u++) bv[u] = Bs[k][tx * 4 + u];
            #pragma unroll
            for (int u = 0; u < 4; u++)
                #pragma unroll
                for (int w = 0; w < 4; w++) acc[u][w] = fmaf(a[u], bv[w], acc[u][w]);
        }
        __syncthreads();
    }
    #pragma unroll
    for (int u = 0; u < 4; u++)
        #pragma unroll
        for (int w = 0; w < 4; w++) {
            size_t o = (size_t)(i0 + ty * 4 + u) * NC + j0 + tx * 4 + w;
            ushort h, l;
            split2(acc[u][w], h, l);
            Dh[o] = __ushort_as_bfloat16(h);
            Dl[o] = __ushort_as_bfloat16(l);
        }
}

// ---------------- vb[j] = sum_c fb[c]*gw[c,j] ------------------------------------
__global__ __launch_bounds__(256) void vb_kernel(const float* __restrict__ fb,
                                                 const float* __restrict__ gw,
                                                 float* __restrict__ vb) {
    int j = blockIdx.x * 256 + threadIdx.x;
    float s = 0.f;
    for (int c = 0; c < NC; c++) s = fmaf(fb[c], gw[(size_t)c * NC + j], s);
    vb[j] = s;
}

// ---------------- v[b,s] = sum_j vb[j]*(style[b,j,s]-mean)*rstd -------------------
__global__ __launch_bounds__(256) void vrow_kernel(const float* __restrict__ style,
                                                   const float2* __restrict__ st,
                                                   const float* __restrict__ vb,
                                                   float* __restrict__ v) {
    int b = blockIdx.y;
    int s = blockIdx.x * 256 + threadIdx.x;
    const float* sb = style + (size_t)b * NC * NHW;
    float acc = 0.f;
    for (int j = 0; j < NC; j++) {
        float2 m = st[b * NC + j];
        acc = fmaf(vb[j], (sb[(size_t)j * NHW + s] - m.x) * m.y, acc);
    }
    v[b * NHW + s] = acc;
}

// ---------------- ob2[c] = sum_m o_w[c,m]*h_b[m] + o_b[c] ------------------------
__global__ __launch_bounds__(256) void ob2_kernel(const float* __restrict__ ow,
                                                  const float* __restrict__ hb,
                                                  const float* __restrict__ ob,
                                                  float* __restrict__ ob2) {
    int c = blockIdx.x * 256 + threadIdx.x;
    float s = ob[c];
    for (int m = 0; m < NC; m++) s = fmaf(ow[(size_t)c * NC + m], hb[m], s);
    ob2[c] = s;
}

// ---------------- sparse softmax with exact candidate recompute ------------------
// E is a bf16-stored 1-MMA approximation (abs err ~0.3 total). Candidates =
// entries above approx-max - 16.3. Exact E recomputed via fp32 dot nCf . TTf.
__global__ __launch_bounds__(256) void softmax_sparse_kernel(
    const bf16* __restrict__ E, const float* __restrict__ vrow,
    const float* __restrict__ nCf, const float* __restrict__ TTf,
    ushort* __restrict__ lidx, float* __restrict__ lw, int* __restrict__ lcnt)
{
    __shared__ float  s_nc[NC];
    __shared__ ushort s_idx[CC];
    __shared__ float  s_ex[CC];
    __shared__ int    wsum[8], wbase[8], s_n;
    const int b = blockIdx.y, q = blockIdx.x;
    const size_t rowid = (size_t)b * NHW + q;
    const size_t base  = rowid * NHW;
    const int tid = threadIdx.x, lane = tid & 31, w = tid >> 5;

    // load E row (bf16) + v, find approx max
    const uint2* p  = (const uint2*)(E + base);          // 4 bf16 per uint2
    const float4* vp = (const float4*)(vrow + (size_t)b * NHW);
    float4 v[4];
    float mx = -3.4e38f;
    #pragma unroll
    for (int i = 0; i < 4; i++) {
        uint2 e2 = p[tid + i * 256];
        v[i].x = __bfloat162float(__ushort_as_bfloat16((ushort)(e2.x & 0xffff)));
        v[i].y = __bfloat162float(__ushort_as_bfloat16((ushort)(e2.x >> 16)));
        v[i].z = __bfloat162float(__ushort_as_bfloat16((ushort)(e2.y & 0xffff)));
        v[i].w = __bfloat162float(__ushort_as_bfloat16((ushort)(e2.y >> 16)));
        float4 vv = vp[tid + i * 256];
        v[i].x += vv.x; v[i].y += vv.y; v[i].z += vv.z; v[i].w += vv.w;
        mx = fmaxf(mx, fmaxf(fmaxf(v[i].x, v[i].y), fmaxf(v[i].z, v[i].w)));
    }
    const float mxa = block_reduce_max(mx);
    const float T = mxa - 16.3f;

    // load content row (fp32) into smem
    const float2* ncp = (const float2*)(nCf + rowid * NC);
    *(float2*)&s_nc[tid * 2] = ncp[tid];

    // candidate count + deterministic scan
    int cnt = 0;
    #pragma unroll
    for (int i = 0; i < 4; i++)
        cnt += (v[i].x > T) + (v[i].y > T) + (v[i].z > T) + (v[i].w > T);
    int incl = cnt;
    #pragma unroll
    for (int o = 1; o < 32; o <<= 1) {
        int n = __shfl_up_sync(0xffffffffu, incl, o);
        if (lane >= o) incl += n;
    }
    if (lane == 31) wsum[w] = incl;
    __syncthreads();
    if (tid == 0) {
        int r = 0;
        #pragma unroll
        for (int i = 0; i < 8; i++) { wbase[i] = r; r += wsum[i]; }
        s_n = (r < CC) ? r : CC;
    }
    __syncthreads();
    const int ncand = s_n;
    int k = wbase[w] + incl - cnt;

    // non-candidate approx exp-sum; record candidate indices
    float sn = 0.f;
    #pragma unroll
    for (int i = 0; i < 4; i++) {
        int s4 = 4 * (tid + i * 256);
        float c4[4] = {v[i].x, v[i].y, v[i].z, v[i].w};
        #pragma unroll
        for (int c = 0; c < 4; c++) {
            if (c4[c] > T) {
                if (k < CC) s_idx[k] = (ushort)(s4 + c);
                k++;
            } else {
                sn += __expf(c4[c] - mxa);
            }
        }
    }
    const float Snon = block_reduce_sum(sn);   // includes __syncthreads barriers

    // exact recompute: one warp per candidate
    for (int c = w; c < ncand; c += 8) {
        const int sidx = s_idx[c];
        const float4* tt = (const float4*)(TTf + ((size_t)b * NHW + sidx) * NC);
        float acc = 0.f;
        #pragma unroll
        for (int u = 0; u < 4; u++) {
            float4 t4 = tt[lane + 32 * u];
            const int o = (lane + 32 * u) * 4;
            acc = fmaf(t4.x, s_nc[o], acc);
            acc = fmaf(t4.y, s_nc[o + 1], acc);
            acc = fmaf(t4.z, s_nc[o + 2], acc);
            acc = fmaf(t4.w, s_nc[o + 3], acc);
        }
        #pragma unroll
        for (int o = 16; o > 0; o >>= 1) acc += __shfl_down_sync(0xffffffffu, acc, o);
        if (lane == 0) s_ex[c] = acc + vrow[(size_t)b * NHW + sidx];
    }
    __syncthreads();

    // denominator: non-candidates (approx) + candidates (exact)
    float cs = 0.f;
    for (int c = tid; c < ncand; c += 256) cs += __expf(s_ex[c] - mxa);
    const float Scand = block_reduce_sum(cs);
    const float inv = 1.0f / (Snon + Scand);

    // emit all candidates
    ushort* ip = lidx + rowid * CAP;
    float*  wp = lw   + rowid * CAP;
    for (int c = tid; c < ncand; c += 256) {
        ip[c] = s_idx[c];
        wp[c] = __expf(s_ex[c] - mxa) * inv;
    }
    if (tid == 0) lcnt[rowid] = ncand;
}

// ---------------- sparse apply: out[c,q] = ob2 + content + sum_k w*WoS[s_k,c] ----
__global__ __launch_bounds__(256) void sparse_apply_kernel(
    const float* __restrict__ WoS, const ushort* __restrict__ lidx,
    const float* __restrict__ lw, const int* __restrict__ lcnt,
    const float* __restrict__ ob2, const float* __restrict__ content,
    float* __restrict__ out)
{
    extern __shared__ float sacc[];   // [512][33]
    const int b = blockIdx.y, q0 = blockIdx.x * 32;
    const int tid = threadIdx.x, wid = tid >> 5, lane = tid & 31;
    const float* WoSb = WoS + (size_t)b * NHW * NC;

    #pragma unroll 1
    for (int j = 0; j < 4; j++) {
        const int q = q0 + wid * 4 + j;
        const size_t row = (size_t)b * NHW + q;
        const int cnt = lcnt[row];
        const ushort* ip = lidx + row * CAP;
        const float*  wp = lw   + row * CAP;
        float4 acc[4] = {};
        for (int k = 0; k < cnt; k++) {
            const int s = ip[k];
            const float wgt = wp[k];
            const float4* src = (const float4*)(WoSb + (size_t)s * NC) + lane;
            #pragma unroll
            for (int u = 0; u < 4; u++) {
                float4 vv = src[u * 32];
                acc[u].x = fmaf(wgt, vv.x, acc[u].x);
                acc[u].y = fmaf(wgt, vv.y, acc[u].y);
                acc[u].z = fmaf(wgt, vv.z, acc[u].z);
                acc[u].w = fmaf(wgt, vv.w, acc[u].w);
            }
        }
        const int qq = q - q0;
        #pragma unroll
        for (int u = 0; u < 4; u++) {
            const int c = lane * 4 + u * 128;
            sacc[(c + 0) * 33 + qq] = acc[u].x;
            sacc[(c + 1) * 33 + qq] = acc[u].y;
            sacc[(c + 2) * 33 + qq] = acc[u].z;
            sacc[(c + 3) * 33 + qq] = acc[u].w;
        }
    }
    __syncthreads();

    const float* cb = content + (size_t)b * NC * NHW;
    float* ob = out + (size_t)b * NC * NHW;
    #pragma unroll 1
    for (int p = 0; p < 16; p++) {
        const int c  = p * 32 + (tid >> 3);
        const int ch = (tid & 7) * 4;
        const float bias = ob2[c];
        float4 vv;
        vv.x = sacc[c * 33 + ch + 0] + bias;
        vv.y = sacc[c * 33 + ch + 1] + bias;
        vv.z = sacc[c * 33 + ch + 2] + bias;
        vv.w = sacc[c * 33 + ch + 3] + bias;
        const size_t o = (size_t)c * NHW + q0 + ch;
        const float4 cv = *(const float4*)(cb + o);
        vv.x += cv.x; vv.y += cv.y; vv.z += cv.z; vv.w += cv.w;
        *(float4*)(ob + o) = vv;
    }
}

// ---------------- 256x128x32 mma.sync GEMM ---------------------------------------
// NMMA 3: bf16 hi/lo 3-MMA split.  NMMA 1: single bf16 MMA (Ahi, Bhi only).
// SPLIT 0: C fp32 (+biasRow/+resid). SPLIT 1: C bf16 hi/lo.
// SPLIT 2: C bf16 hi + fp32.        SPLIT 3: C bf16 hi only.
constexpr int ATB = 16384;           // 256 rows x 64B component
constexpr int BTB = 8192;            // 128 rows x 64B component
constexpr int NSTG = 3;

__device__ __forceinline__ uint32_t swz(int r, int c) {
    return (uint32_t)(r * 64 + ((c ^ ((r >> 1) & 3)) << 4));
}

template <int NMMA, int SPLIT>
__global__ __launch_bounds__(512, 1) void mma_gemm(
    const bf16* __restrict__ Ahi, const bf16* __restrict__ Alo,
    const bf16* __restrict__ Bhi, const bf16* __restrict__ Blo,
    float* __restrict__ Cf, bf16* __restrict__ Chi, bf16* __restrict__ Clo,
    int M, int N, int K,
    long sA, long sB, long sC,
    const float* __restrict__ biasRow,
    const float* __restrict__ resid, long sR)
{
    constexpr int STGB   = (NMMA == 3) ? (2 * ATB + 2 * BTB) : (ATB + BTB);
    constexpr int OFF_BH = (NMMA == 3) ? 2 * ATB : ATB;

    extern __shared__ __align__(128) char dsm[];
    const uint32_t smb = s2u(dsm);

    const int tid = threadIdx.x, wid = tid >> 5, lane = tid & 31;
    const int m0 = blockIdx.y * 256, n0 = blockIdx.x * 128, b = blockIdx.z;
    const int warpM = wid & 3, warpN = wid >> 2;
    const int KT = K / 32;

    const int rA = tid >> 1, cA = (tid & 1) * 2;
    const int rB = tid >> 2, cB = tid & 3;
    const bf16* pAh = Ahi + (size_t)b * sA + (size_t)(m0 + rA) * K + cA * 8;
    const bf16* pAl = (NMMA == 3) ? Alo + (size_t)b * sA + (size_t)(m0 + rA) * K + cA * 8 : nullptr;
    const bf16* pBh = Bhi + (size_t)b * sB + (size_t)(n0 + rB) * K + cB * 8;
    const bf16* pBl = (NMMA == 3) ? Blo + (size_t)b * sB + (size_t)(n0 + rB) * K + cB * 8 : nullptr;
    const uint32_t dA0 = swz(rA, cA), dA1 = swz(rA, cA + 1);
    const uint32_t dB  = swz(rB, cB);

    auto load_stage = [&](int s, int k0) {
        const uint32_t sb = smb + s * STGB;
        cpa16(sb + dA0, pAh + k0);
        cpa16(sb + dA1, pAh + k0 + 8);
        if (NMMA == 3) {
            cpa16(sb + ATB + dA0, pAl + k0);
            cpa16(sb + ATB + dA1, pAl + k0 + 8);
        }
        cpa16(sb + OFF_BH + dB, pBh + k0);
        if (NMMA == 3) cpa16(sb + OFF_BH + BTB + dB, pBl + k0);
    };

    float acc[4][4][4];
    #pragma unroll
    for (int i = 0; i < 4; i++)
        #pragma unroll
        for (int j = 0; j < 4; j++)
            #pragma unroll
            for (int q = 0; q < 4; q++) acc[i][j][q] = 0.f;

    load_stage(0, 0);  cpa_commit();
    load_stage(1, 32); cpa_commit();

    const int arow = warpM * 64 + (lane & 15);
    const int brow = warpN * 32 + (lane & 15);

    for (int kt = 0; kt < KT; kt++) {
        cpa_wait1();
        __syncthreads();
        const int cur = kt % NSTG;
        if (kt + 2 < KT) load_stage((kt + 2) % NSTG, (kt + 2) * 32);
        cpa_commit();

        const uint32_t sAh = smb + cur * STGB;
        const uint32_t sAl = sAh + ATB;
        const uint32_t sBh = sAh + OFF_BH;
        const uint32_t sBl = sBh + BTB;

        #pragma unroll
        for (int kk = 0; kk < 2; kk++) {
            const int ch = kk * 2 + (lane >> 4);
            uint32_t ah[4][4], al[4][4];
            #pragma unroll
            for (int mi = 0; mi < 4; mi++) {
                uint32_t off = swz(arow + mi * 16, ch);
                ldsm4(sAh + off, ah[mi][0], ah[mi][1], ah[mi][2], ah[mi][3]);
                if (NMMA == 3)
                    ldsm4(sAl + off, al[mi][0], al[mi][1], al[mi][2], al[mi][3]);
            }
            #pragma unroll
            for (int g = 0; g < 2; g++) {
                uint32_t off = swz(brow + g * 16, ch);
                uint32_t h0, h1, h2, h3, l0, l1, l2, l3;
                ldsm4(sBh + off, h0, h1, h2, h3);
                if (NMMA == 3) ldsm4(sBl + off, l0, l1, l2, l3);
                #pragma unroll
                for (int mi = 0; mi < 4; mi++) {
                    mma_bf16(acc[mi][2 * g],     ah[mi][0], ah[mi][1], ah[mi][2], ah[mi][3], h0, h2);
                    mma_bf16(acc[mi][2 * g + 1], ah[mi][0], ah[mi][1], ah[mi][2], ah[mi][3], h1, h3);
                    if (NMMA == 3) {
                        mma_bf16(acc[mi][2 * g],     ah[mi][0], ah[mi][1], ah[mi][2], ah[mi][3], l0, l2);
                        mma_bf16(acc[mi][2 * g],     al[mi][0], al[mi][1], al[mi][2], al[mi][3], h0, h2);
                        mma_bf16(acc[mi][2 * g + 1], ah[mi][0], ah[mi][1], ah[mi][2], ah[mi][3], l1, l3);
                        mma_bf16(acc[mi][2 * g + 1], al[mi][0], al[mi][1], al[mi][2], al[mi][3], h1, h3);
                    }
                }
            }
        }
        __syncthreads();
    }

    // ---------------- epilogue -------------------------------------------------
    #pragma unroll
    for (int mi = 0; mi < 4; mi++) {
        const int r0 = m0 + warpM * 64 + mi * 16 + (lane >> 2);
        #pragma unroll
        for (int j = 0; j < 4; j++) {
            const int col = n0 + warpN * 32 + j * 8 + (lane & 3) * 2;
            float v[4] = {acc[mi][j][0], acc[mi][j][1], acc[mi][j][2], acc[mi][j][3]};
            if (biasRow) {
                float b0 = biasRow[r0], b1 = biasRow[r0 + 8];
                v[0] += b0; v[1] += b0; v[2] += b1; v[3] += b1;
            }
            const size_t o0 = (size_t)b * sC + (size_t)r0 * N + col;
            const size_t o1 = o0 + (size_t)8 * N;
            if (SPLIT == 1) {
                ushort h0, l0, h1, l1;
                split2(v[0], h0, l0); split2(v[1], h1, l1);
                *(uint32_t*)(Chi + o0) = (uint32_t)h0 | ((uint32_t)h1 << 16);
                *(uint32_t*)(Clo + o0) = (uint32_t)l0 | ((uint32_t)l1 << 16);
                split2(v[2], h0, l0); split2(v[3], h1, l1);
                *(uint32_t*)(Chi + o1) = (uint32_t)h0 | ((uint32_t)h1 << 16);
                *(uint32_t*)(Clo + o1) = (uint32_t)l0 | ((uint32_t)l1 << 16);
            } else if (SPLIT == 2) {
                ushort h0 = __bfloat16_as_ushort(__float2bfloat16(v[0]));
                ushort h1 = __bfloat16_as_ushort(__float2bfloat16(v[1]));
                *(uint32_t*)(Chi + o0) = (uint32_t)h0 | ((uint32_t)h1 << 16);
                h0 = __bfloat16_as_ushort(__float2bfloat16(v[2]));
                h1 = __bfloat16_as_ushort(__float2bfloat16(v[3]));
                *(uint32_t*)(Chi + o1) = (uint32_t)h0 | ((uint32_t)h1 << 16);
                *(float2*)(Cf + o0) = make_float2(v[0], v[1]);
                *(float2*)(Cf + o1) = make_float2(v[2], v[3]);
            } else if (SPLIT == 3) {
                ushort h0 = __bfloat16_as_ushort(__float2bfloat16(v[0]));
                ushort h1 = __bfloat16_as_ushort(__float2bfloat16(v[1]));
                *(uint32_t*)(Chi + o0) = (uint32_t)h0 | ((uint32_t)h1 << 16);
                h0 = __bfloat16_as_ushort(__float2bfloat16(v[2]));
                h1 = __bfloat16_as_ushort(__float2bfloat16(v[3]));
                *(uint32_t*)(Chi + o1) = (uint32_t)h0 | ((uint32_t)h1 << 16);
            } else {
                if (resid) {
                    const float* rp = resid + (size_t)b * sR;
                    float2 r0v = *(const float2*)(rp + (size_t)r0 * N + col);
                    float2 r1v = *(const float2*)(rp + (size_t)(r0 + 8) * N + col);
                    v[0] += r0v.x; v[1] += r0v.y; v[2] += r1v.x; v[3] += r1v.y;
                }
                *(float2*)(Cf + o0) = make_float2(v[0], v[1]);
                *(float2*)(Cf + o1) = make_float2(v[2], v[3]);
            }
        }
    }
}

constexpr int DSMEM3 = NSTG * (2 * ATB + 2 * BTB);  // 144 KB
constexpr int DSMEM1 = NSTG * (ATB + BTB);          // 72 KB

// ----------------------------- launch --------------------------------------------
extern "C" void kernel_launch(void* const* d_in, const int* in_sizes, int n_in,
                              void* d_out, int out_size) {
    const float* content = (const float*)d_in[0];
    const float* style   = (const float*)d_in[1];
    const float* f_w = (const float*)d_in[2];
    const float* f_b = (const float*)d_in[3];
    const float* g_w = (const float*)d_in[4];
    const float* h_w = (const float*)d_in[6];
    const float* h_b = (const float*)d_in[7];
    const float* o_w = (const float*)d_in[8];
    const float* o_b = (const float*)d_in[9];
    float* out = (float*)d_out;

    float *v, *vb, *ob2, *WoS, *lwp, *nCf, *TTf; float2 *stC, *stS;
    bf16 *E, *nCTh, *nSTh, *nSTl, *sTh, *sTl, *TTh, *W1h, *W1l, *Woh, *Wol;
    ushort *lip; int *lcp;
    cudaGetSymbolAddress((void**)&E,   g_E);
    cudaGetSymbolAddress((void**)&v,   g_v);
    cudaGetSymbolAddress((void**)&vb,  g_vb);
    cudaGetSymbolAddress((void**)&ob2, g_ob2);
    cudaGetSymbolAddress((void**)&WoS, g_WoS);
    cudaGetSymbolAddress((void**)&stC, g_statC);
    cudaGetSymbolAddress((void**)&stS, g_statS);
    cudaGetSymbolAddress((void**)&nCTh, g_nCT_h);
    cudaGetSymbolAddress((void**)&nCf,  g_nCT_f);
    cudaGetSymbolAddress((void**)&nSTh, g_nST_h); cudaGetSymbolAddress((void**)&nSTl, g_nST_l);
    cudaGetSymbolAddress((void**)&sTh,  g_sT_h);  cudaGetSymbolAddress((void**)&sTl,  g_sT_l);
    cudaGetSymbolAddress((void**)&TTh,  g_TT_h);
    cudaGetSymbolAddress((void**)&TTf,  g_TT_f);
    cudaGetSymbolAddress((void**)&W1h,  g_W1_h);  cudaGetSymbolAddress((void**)&W1l,  g_W1_l);
    cudaGetSymbolAddress((void**)&Woh,  g_Wo_h);  cudaGetSymbolAddress((void**)&Wol,  g_Wo_l);
    cudaGetSymbolAddress((void**)&lip,  g_lidx);
    cudaGetSymbolAddress((void**)&lwp,  g_lw);
    cudaGetSymbolAddress((void**)&lcp,  g_lcnt);

    cudaFuncSetAttribute(mma_gemm<3,0>, cudaFuncAttributeMaxDynamicSharedMemorySize, DSMEM3);
    cudaFuncSetAttribute(mma_gemm<3,2>, cudaFuncAttributeMaxDynamicSharedMemorySize, DSMEM3);
    cudaFuncSetAttribute(mma_gemm<1,3>, cudaFuncAttributeMaxDynamicSharedMemorySize, DSMEM1);
    cudaFuncSetAttribute(sparse_apply_kernel, cudaFuncAttributeMaxDynamicSharedMemorySize, 512 * 33 * 4);

    const long sQC = (long)NHW * NC;   // [B, 4096, 512]
    const long sE  = (long)NHW * NHW;

    // 1) stats
    stats_kernel<<<NB * NC, 256>>>(content, stC);
    stats_kernel<<<NB * NC, 256>>>(style,   stS);

    // 2) transposed operands
    dim3 gt(NHW / 32, NC / 32, NB);
    tsplit_c_kernel<<<gt, 256>>>(content, stC, nCTh, nCf);
    tsplit_s_kernel<<<gt, 256>>>(style,   stS, nSTh, nSTl, sTh, sTl);

    // 3) folded weights: W1 = fw^T gw, Wo = o_w h_w; bias vectors
    dim3 gw64(NC / 64, NC / 64);
    small_gemm_split<1><<<gw64, 256>>>(f_w, g_w, W1h, W1l);
    small_gemm_split<0><<<gw64, 256>>>(o_w, h_w, Woh, Wol);
    vb_kernel<<<NC / 256, 256>>>(f_b, g_w, vb);
    vrow_kernel<<<dim3(NHW / 256, NB), 256>>>(style, stS, vb, v);
    ob2_kernel<<<NC / 256, 256>>>(o_w, h_b, o_b, ob2);

    // 4) WoS[s,c] = sum_j sT[s,j] * Wo[c,j]   (M=4096, N=512, K=512), fp32 out
    dim3 gW(NC / 128, NHW / 256, NB);       // (4, 16, 4)
    mma_gemm<3,0><<<gW, 512, DSMEM3>>>(sTh, sTl, Woh, Wol, WoS, nullptr, nullptr,
                                       NHW, NC, NC, sQC, 0, sQC, nullptr, nullptr, 0);

    // 5) TT[s,i] = sum_j nST[s,j] * W1[i,j]   (M=4096, N=512, K=512), bf16-hi + fp32
    mma_gemm<3,2><<<gW, 512, DSMEM3>>>(nSTh, nSTl, W1h, W1l, TTf, TTh, nullptr,
                                       NHW, NC, NC, sQC, 0, sQC, nullptr, nullptr, 0);

    // 6) E approx[q,s] = sum_i nCT_h[q,i] * TT_h[s,i]  (1-MMA bf16), bf16 out
    dim3 gE(NHW / 128, NHW / 256, NB);      // (32, 16, 4)
    mma_gemm<1,3><<<gE, 512, DSMEM1>>>(nCTh, nullptr, TTh, nullptr, nullptr, E, nullptr,
                                       NHW, NHW, NC, sQC, sQC, sE, nullptr, nullptr, 0);

    // 7) sparse softmax: candidates from approx E (bf16), exact fp32 recompute
    dim3 gs(NHW, NB);
    softmax_sparse_kernel<<<gs, 256>>>(E, v, nCf, TTf, lip, lwp, lcp);

    // 8) sparse apply: out[c,q] = ob2[c] + content[c,q] + sum w * WoS[s,c]
    dim3 ga(NHW / 32, NB);
    sparse_apply_kernel<<<ga, 256, 512 * 33 * 4>>>(WoS, lip, lwp, lcp, ob2, content, out);
}